// round 1
// baseline (speedup 1.0000x reference)
#include <cuda_runtime.h>
#include <cuda_bf16.h>
#include <cstdint>

// ---------------- problem constants (fixed by reference) ----------------
#define NNODES 50000
#define NGENE  40000
#define NGO    (NNODES - NGENE)   // 10000
#define NEDGES 800000
#define DIM    512
#define HID1D  512
#define HID2D  256
#define GOIDD  4096

// ---------------- scratch (device globals: no runtime alloc) ----------------
__device__ int   g_is64;
__device__ int   g_src[NEDGES];
__device__ int   g_dst[NEDGES];
__device__ int   g_indeg[NNODES];
__device__ int   g_rowptr[NNODES + 1];
__device__ int   g_cursor[NNODES];
__device__ float g_dinv[NNODES];
__device__ int   g_csr_src[NEDGES];
__device__ float g_csr_w[NEDGES];

__device__ float g_goid1[(size_t)NGO * 1024];      //  41 MB
__device__ float g_xt[(size_t)NNODES * DIM];       // 102 MB
__device__ float g_hw[(size_t)NNODES * DIM];       // 102 MB (hw1 then hw2)
__device__ float g_r1[(size_t)NNODES * DIM];       // 102 MB (r1 -> h1 in place)
__device__ float g_r2[(size_t)NNODES * HID2D];     //  51 MB (r2 -> h2 in place)

// ---------------- graph preprocessing ----------------

__global__ void k_init_indeg() {
    int i = blockIdx.x * blockDim.x + threadIdx.x;
    if (i < NNODES) g_indeg[i] = 0;
}

// edge_index may be int64 (x64 on) or int32 (default JAX). If int64 (LE),
// the high 32-bit word of every value is 0 (values < 50000).
__global__ void k_detect_idx_dtype(const int* __restrict__ raw) {
    if (threadIdx.x == 0 && blockIdx.x == 0) {
        int is64 = 1;
        for (int k = 0; k < 1024; k++) {
            if (raw[2 * k + 1] != 0) { is64 = 0; break; }
        }
        g_is64 = is64;
    }
}

__global__ void k_convert_edges(const int* __restrict__ raw) {
    int e = blockIdx.x * blockDim.x + threadIdx.x;
    if (e >= NEDGES) return;
    int s, d;
    if (g_is64) {
        const long long* r64 = (const long long*)raw;
        s = (int)r64[e];
        d = (int)r64[NEDGES + e];
    } else {
        s = raw[e];
        d = raw[NEDGES + e];
    }
    g_src[e] = s;
    g_dst[e] = d;
    atomicAdd(&g_indeg[d], 1);
}

__global__ void k_dinv() {
    int i = blockIdx.x * blockDim.x + threadIdx.x;
    if (i < NNODES) g_dinv[i] = rsqrtf(1.0f + (float)g_indeg[i]);
}

// single-block exclusive scan over indeg -> rowptr (+ cursor copy)
__global__ void k_scan() {
    __shared__ int sh[1024];
    __shared__ int carry;
    if (threadIdx.x == 0) carry = 0;
    __syncthreads();
    for (int base = 0; base < NNODES; base += 1024) {
        int i = base + (int)threadIdx.x;
        int v = (i < NNODES) ? g_indeg[i] : 0;
        sh[threadIdx.x] = v;
        __syncthreads();
        for (int off = 1; off < 1024; off <<= 1) {
            int t = (threadIdx.x >= (unsigned)off) ? sh[threadIdx.x - off] : 0;
            __syncthreads();
            sh[threadIdx.x] += t;
            __syncthreads();
        }
        int excl = sh[threadIdx.x] - v + carry;
        if (i < NNODES) { g_rowptr[i] = excl; g_cursor[i] = excl; }
        __syncthreads();
        if (threadIdx.x == 1023) carry += sh[1023];
        __syncthreads();
    }
    if (threadIdx.x == 0) g_rowptr[NNODES] = carry;
}

__global__ void k_fill_csr() {
    int e = blockIdx.x * blockDim.x + threadIdx.x;
    if (e >= NEDGES) return;
    int s = g_src[e], d = g_dst[e];
    int p = atomicAdd(&g_cursor[d], 1);
    g_csr_src[p] = s;
    g_csr_w[p]   = g_dinv[s] * g_dinv[d];
}

// ---------------- SGEMM: C[M,N] = A[M,K] @ B[K,N] (+bias)(+relu) ----------------
// 128x128 tile, BK=16, 256 threads, 8x8 microtile. N%128==0, K%16==0 (true for
// all call sites); only M is guarded.
template <bool BIAS, bool RELU>
__global__ __launch_bounds__(256, 2)
void k_sgemm(const float* __restrict__ A, const float* __restrict__ B,
             const float* __restrict__ bias, float* __restrict__ C,
             int M, int N, int K)
{
    __shared__ float As[16][132];
    __shared__ float Bs[16][128];
    const int tid = threadIdx.x;
    const int bm = blockIdx.y * 128;
    const int bn = blockIdx.x * 128;
    const int tx = tid & 15;
    const int ty = tid >> 4;

    const int arow = tid >> 2;        // 0..63
    const int ac   = (tid & 3) * 4;   // 0,4,8,12
    const int bk   = tid >> 5;        // 0..7
    const int bc   = (tid & 31) * 4;  // 0..124

    float acc[8][8];
#pragma unroll
    for (int i = 0; i < 8; i++)
#pragma unroll
        for (int j = 0; j < 8; j++) acc[i][j] = 0.f;

    for (int k0 = 0; k0 < K; k0 += 16) {
        const int r0 = bm + arow, r1 = bm + arow + 64;
        float4 a0 = make_float4(0.f, 0.f, 0.f, 0.f), a1 = a0;
        if (r0 < M) a0 = *(const float4*)(A + (size_t)r0 * K + k0 + ac);
        if (r1 < M) a1 = *(const float4*)(A + (size_t)r1 * K + k0 + ac);
        As[ac + 0][arow] = a0.x; As[ac + 1][arow] = a0.y;
        As[ac + 2][arow] = a0.z; As[ac + 3][arow] = a0.w;
        As[ac + 0][arow + 64] = a1.x; As[ac + 1][arow + 64] = a1.y;
        As[ac + 2][arow + 64] = a1.z; As[ac + 3][arow + 64] = a1.w;
        *(float4*)&Bs[bk][bc]     = *(const float4*)(B + (size_t)(k0 + bk) * N + bn + bc);
        *(float4*)&Bs[bk + 8][bc] = *(const float4*)(B + (size_t)(k0 + bk + 8) * N + bn + bc);
        __syncthreads();
#pragma unroll
        for (int kk = 0; kk < 16; kk++) {
            float a[8], b[8];
            *(float4*)&a[0] = *(const float4*)&As[kk][ty * 8];
            *(float4*)&a[4] = *(const float4*)&As[kk][ty * 8 + 4];
            *(float4*)&b[0] = *(const float4*)&Bs[kk][tx * 8];
            *(float4*)&b[4] = *(const float4*)&Bs[kk][tx * 8 + 4];
#pragma unroll
            for (int i = 0; i < 8; i++)
#pragma unroll
                for (int j = 0; j < 8; j++)
                    acc[i][j] = fmaf(a[i], b[j], acc[i][j]);
        }
        __syncthreads();
    }

#pragma unroll
    for (int i = 0; i < 8; i++) {
        int row = bm + ty * 8 + i;
        if (row >= M) continue;
#pragma unroll
        for (int j = 0; j < 8; j += 4) {
            int col = bn + tx * 8 + j;
            float4 v = make_float4(acc[i][j], acc[i][j + 1], acc[i][j + 2], acc[i][j + 3]);
            if (BIAS) {
                float4 bb = *(const float4*)(bias + col);
                v.x += bb.x; v.y += bb.y; v.z += bb.z; v.w += bb.w;
            }
            if (RELU) {
                v.x = fmaxf(v.x, 0.f); v.y = fmaxf(v.y, 0.f);
                v.z = fmaxf(v.z, 0.f); v.w = fmaxf(v.w, 0.f);
            }
            *(float4*)(C + (size_t)row * N + col) = v;
        }
    }
}

// ---------------- copy gene_x = x[:40000,:512] into xt ----------------
__global__ void k_copy_gene(const float* __restrict__ x) {
    int idx = blockIdx.x * blockDim.x + threadIdx.x;   // float4 index
    const int F4 = DIM / 4;
    if (idx >= NGENE * F4) return;
    int row = idx / F4, c = idx % F4;
    ((float4*)g_xt)[(size_t)row * F4 + c] =
        ((const float4*)x)[(size_t)row * (GOIDD / 4) + c];
}

// ---------------- GCN aggregate + epilogue (CSR gather, in-place over r) ----
// out[i] = relu( sum_e w_e*hw[src_e] + dinv[i]^2*hw[i] + bias ) + r[i]
template <int F>
__global__ void k_gather_epi(const float* __restrict__ hw, float* __restrict__ rio,
                             const float* __restrict__ bias)
{
    const int F4 = F / 4;
    int i = blockIdx.x;
    int t = threadIdx.x;           // blockDim == F4
    int beg = g_rowptr[i], end = g_rowptr[i + 1];
    const float4* hw4 = (const float4*)hw;
    float4 acc = make_float4(0.f, 0.f, 0.f, 0.f);
    for (int e = beg; e < end; e++) {
        int s = g_csr_src[e];
        float w = g_csr_w[e];
        float4 v = hw4[(size_t)s * F4 + t];
        acc.x += w * v.x; acc.y += w * v.y; acc.z += w * v.z; acc.w += w * v.w;
    }
    float dv = g_dinv[i];
    float sn = dv * dv;
    float4 hv = hw4[(size_t)i * F4 + t];
    float4 bb = ((const float4*)bias)[t];
    float4 r  = ((float4*)rio)[(size_t)i * F4 + t];
    float4 o;
    o.x = fmaxf(acc.x + sn * hv.x + bb.x, 0.f) + r.x;
    o.y = fmaxf(acc.y + sn * hv.y + bb.y, 0.f) + r.y;
    o.z = fmaxf(acc.z + sn * hv.z + bb.z, 0.f) + r.z;
    o.w = fmaxf(acc.w + sn * hv.w + bb.w, 0.f) + r.w;
    ((float4*)rio)[(size_t)i * F4 + t] = o;
}

// ---------------- final fusion: out = [h2[:40000], istj[:40000]] @ W_f + b_f --
__global__ void k_fusion(const float* __restrict__ h2, const float* __restrict__ istj,
                         const float* __restrict__ Wf, const float* __restrict__ bf,
                         float* __restrict__ out)
{
    int gwarp = (blockIdx.x * blockDim.x + threadIdx.x) >> 5;
    int lane = threadIdx.x & 31;
    if (gwarp >= NGENE) return;
    const float* h = h2 + (size_t)gwarp * HID2D;
    float a0 = 0.f, a1 = 0.f;
#pragma unroll
    for (int k = lane; k < HID2D; k += 32) {
        float v = h[k];
        a0 += v * Wf[2 * k];
        a1 += v * Wf[2 * k + 1];
    }
#pragma unroll
    for (int off = 16; off > 0; off >>= 1) {
        a0 += __shfl_down_sync(0xffffffffu, a0, off);
        a1 += __shfl_down_sync(0xffffffffu, a1, off);
    }
    if (lane == 0) {
        float t = istj[gwarp];
        out[2 * gwarp + 0] = a0 + t * Wf[2 * HID2D + 0] + bf[0];
        out[2 * gwarp + 1] = a1 + t * Wf[2 * HID2D + 1] + bf[1];
    }
}

// ---------------- host ----------------
static inline float* sym_f(const void* sym) {
    void* p = nullptr;
    cudaGetSymbolAddress(&p, sym);
    return (float*)p;
}

extern "C" void kernel_launch(void* const* d_in, const int* in_sizes, int n_in,
                              void* d_out, int out_size)
{
    const float* x    = (const float*)d_in[0];
    const int*   eraw = (const int*)  d_in[1];
    const float* istj = (const float*)d_in[2];
    // n_gene may or may not be an input tensor at slot 3
    const int base = (in_sizes[3] < 1000) ? 4 : 3;
    const float* W_go1 = (const float*)d_in[base + 0];
    const float* b_go1 = (const float*)d_in[base + 1];
    const float* W_go2 = (const float*)d_in[base + 2];
    const float* b_go2 = (const float*)d_in[base + 3];
    const float* W_c1  = (const float*)d_in[base + 4];
    const float* b_c1  = (const float*)d_in[base + 5];
    const float* W_c2  = (const float*)d_in[base + 6];
    const float* b_c2  = (const float*)d_in[base + 7];
    const float* W_r1  = (const float*)d_in[base + 8];
    const float* b_r1  = (const float*)d_in[base + 9];
    const float* W_r2  = (const float*)d_in[base + 10];
    const float* b_r2  = (const float*)d_in[base + 11];
    const float* W_f   = (const float*)d_in[base + 12];
    const float* b_f   = (const float*)d_in[base + 13];
    float* out = (float*)d_out;

    float* p_goid1 = sym_f(g_goid1);
    float* p_xt    = sym_f(g_xt);
    float* p_hw    = sym_f(g_hw);
    float* p_r1    = sym_f(g_r1);
    float* p_r2    = sym_f(g_r2);

    // --- graph preprocessing ---
    k_init_indeg<<<(NNODES + 255) / 256, 256>>>();
    k_detect_idx_dtype<<<1, 32>>>(eraw);
    k_convert_edges<<<(NEDGES + 255) / 256, 256>>>(eraw);
    k_dinv<<<(NNODES + 255) / 256, 256>>>();
    k_scan<<<1, 1024>>>();
    k_fill_csr<<<(NEDGES + 255) / 256, 256>>>();

    // --- goid MLP on x[40000:] ---
    {
        dim3 g(1024 / 128, (NGO + 127) / 128);
        k_sgemm<true, true><<<g, 256>>>(x + (size_t)NGENE * GOIDD, W_go1, b_go1,
                                        p_goid1, NGO, 1024, GOIDD);
    }
    {
        dim3 g(DIM / 128, (NGO + 127) / 128);
        k_sgemm<true, true><<<g, 256>>>(p_goid1, W_go2, b_go2,
                                        p_xt + (size_t)NGENE * DIM, NGO, DIM, 1024);
    }
    k_copy_gene<<<(NGENE * (DIM / 4) + 255) / 256, 256>>>(x);

    // --- layer 1: hw1 = xt@W_c1 ; r1 = xt@W_r1+b ; h1 = relu(agg+..)+r1 ---
    {
        dim3 g(HID1D / 128, (NNODES + 127) / 128);
        k_sgemm<false, false><<<g, 256>>>(p_xt, W_c1, nullptr, p_hw, NNODES, HID1D, DIM);
        k_sgemm<true,  false><<<g, 256>>>(p_xt, W_r1, b_r1,    p_r1, NNODES, HID1D, DIM);
    }
    k_gather_epi<HID1D><<<NNODES, HID1D / 4>>>(p_hw, p_r1, b_c1);

    // --- layer 2: hw2 = h1@W_c2 ; r2 = h1@W_r2+b ; h2 = relu(agg+..)+r2 ---
    {
        dim3 g(HID2D / 128, (NNODES + 127) / 128);
        k_sgemm<false, false><<<g, 256>>>(p_r1, W_c2, nullptr, p_hw, NNODES, HID2D, HID1D);
        k_sgemm<true,  false><<<g, 256>>>(p_r1, W_r2, b_r2,    p_r2, NNODES, HID2D, HID1D);
    }
    k_gather_epi<HID2D><<<NNODES, HID2D / 4>>>(p_hw, p_r2, b_c2);

    // --- fusion head ---
    k_fusion<<<(NGENE * 32 + 255) / 256, 256>>>(p_r2, istj, W_f, b_f, out);

    (void)n_in; (void)out_size;
}

// round 3
// speedup vs baseline: 2.1348x; 2.1348x over previous
#include <cuda_runtime.h>
#include <cuda_bf16.h>
#include <cstdint>

// ---------------- problem constants ----------------
#define NNODES 50000
#define NGENE  40000
#define NGO    10000
#define NEDGES 800000
#define DIM    512
#define HID2D  256
#define GOIDD  4096
#define MPAD_GO 10112   // 79*128
#define MPAD_N  50048   // 391*128

// ---------------- helpers ----------------
__device__ __forceinline__ uint32_t smem_u32(const void* p) {
    uint32_t a;
    asm("{ .reg .u64 t; cvta.to.shared.u64 t, %1; cvt.u32.u64 %0, t; }" : "=r"(a) : "l"(p));
    return a;
}
__device__ __forceinline__ void cp16(uint32_t d, const void* s) {
    asm volatile("cp.async.cg.shared.global [%0], [%1], 16;" :: "r"(d), "l"(s) : "memory");
}
#define CP_COMMIT() asm volatile("cp.async.commit_group;" ::: "memory")
#define CP_WAIT(n)  asm volatile("cp.async.wait_group %0;" :: "n"(n) : "memory")

__device__ __forceinline__ void ldsm4(uint32_t* r, uint32_t addr) {
    asm volatile("ldmatrix.sync.aligned.m8n8.x4.shared.b16 {%0,%1,%2,%3}, [%4];"
        : "=r"(r[0]), "=r"(r[1]), "=r"(r[2]), "=r"(r[3]) : "r"(addr));
}
__device__ __forceinline__ void mma16816(float* d, const uint32_t* a, const uint32_t* b) {
    asm volatile(
        "mma.sync.aligned.m16n8k16.row.col.f32.bf16.bf16.f32 "
        "{%0,%1,%2,%3}, {%4,%5,%6,%7}, {%8,%9}, {%0,%1,%2,%3};"
        : "+f"(d[0]), "+f"(d[1]), "+f"(d[2]), "+f"(d[3])
        : "r"(a[0]), "r"(a[1]), "r"(a[2]), "r"(a[3]), "r"(b[0]), "r"(b[1]));
}
__device__ __forceinline__ uint32_t swz(uint32_t base, uint32_t off) {
    return base + (off ^ ((off >> 3) & 0x70));
}

// ---------------- scratch (device globals) ----------------
__device__ int   g_is64;
__device__ int   g_src[NEDGES];
__device__ int   g_dst[NEDGES];
__device__ int   g_indeg[NNODES];
__device__ int   g_rowptr[NNODES + 1];
__device__ int   g_cursor[NNODES];
__device__ float g_dinv[NNODES];
__device__ int   g_csr_src[NEDGES];
__device__ float g_csr_w[NEDGES];

__device__ float g_hw[(size_t)NNODES * DIM];
__device__ float g_r1[(size_t)NNODES * DIM];
__device__ float g_r2[(size_t)NNODES * HID2D];

__device__ __nv_bfloat16 g_xgo_h[(size_t)MPAD_GO * GOIDD];
__device__ __nv_bfloat16 g_xgo_l[(size_t)MPAD_GO * GOIDD];
__device__ __nv_bfloat16 g_go1_h[(size_t)MPAD_GO * 1024];
__device__ __nv_bfloat16 g_go1_l[(size_t)MPAD_GO * 1024];
__device__ __nv_bfloat16 g_xt_h[(size_t)MPAD_N * DIM];
__device__ __nv_bfloat16 g_xt_l[(size_t)MPAD_N * DIM];
__device__ __nv_bfloat16 g_h1_h[(size_t)MPAD_N * DIM];
__device__ __nv_bfloat16 g_h1_l[(size_t)MPAD_N * DIM];

__device__ __nv_bfloat16 g_Wgo1T_h[1024 * 4096];
__device__ __nv_bfloat16 g_Wgo1T_l[1024 * 4096];
__device__ __nv_bfloat16 g_Wgo2T_h[512 * 1024];
__device__ __nv_bfloat16 g_Wgo2T_l[512 * 1024];
__device__ __nv_bfloat16 g_Wc1T_h[512 * 512];
__device__ __nv_bfloat16 g_Wc1T_l[512 * 512];
__device__ __nv_bfloat16 g_Wr1T_h[512 * 512];
__device__ __nv_bfloat16 g_Wr1T_l[512 * 512];
__device__ __nv_bfloat16 g_Wc2T_h[256 * 512];
__device__ __nv_bfloat16 g_Wc2T_l[256 * 512];
__device__ __nv_bfloat16 g_Wr2T_h[256 * 512];
__device__ __nv_bfloat16 g_Wr2T_l[256 * 512];

__device__ __forceinline__ void split2(float v, __nv_bfloat16& h, __nv_bfloat16& l) {
    h = __float2bfloat16(v);
    l = __float2bfloat16(v - __bfloat162float(h));
}

// ---------------- graph preprocessing ----------------
__global__ void k_init_indeg() {
    int i = blockIdx.x * blockDim.x + threadIdx.x;
    if (i < NNODES) g_indeg[i] = 0;
}
__global__ void k_detect_idx_dtype(const int* __restrict__ raw) {
    if (threadIdx.x == 0 && blockIdx.x == 0) {
        int is64 = 1;
        for (int k = 0; k < 1024; k++)
            if (raw[2 * k + 1] != 0) { is64 = 0; break; }
        g_is64 = is64;
    }
}
__global__ void k_convert_edges(const int* __restrict__ raw) {
    int e = blockIdx.x * blockDim.x + threadIdx.x;
    if (e >= NEDGES) return;
    int s, d;
    if (g_is64) {
        const long long* r64 = (const long long*)raw;
        s = (int)r64[e]; d = (int)r64[NEDGES + e];
    } else {
        s = raw[e]; d = raw[NEDGES + e];
    }
    g_src[e] = s; g_dst[e] = d;
    atomicAdd(&g_indeg[d], 1);
}
__global__ void k_dinv() {
    int i = blockIdx.x * blockDim.x + threadIdx.x;
    if (i < NNODES) g_dinv[i] = rsqrtf(1.0f + (float)g_indeg[i]);
}
__global__ void k_scan() {
    __shared__ int sh[1024];
    __shared__ int carry;
    if (threadIdx.x == 0) carry = 0;
    __syncthreads();
    for (int base = 0; base < NNODES; base += 1024) {
        int i = base + (int)threadIdx.x;
        int v = (i < NNODES) ? g_indeg[i] : 0;
        sh[threadIdx.x] = v;
        __syncthreads();
        for (int off = 1; off < 1024; off <<= 1) {
            int t = (threadIdx.x >= (unsigned)off) ? sh[threadIdx.x - off] : 0;
            __syncthreads();
            sh[threadIdx.x] += t;
            __syncthreads();
        }
        int excl = sh[threadIdx.x] - v + carry;
        if (i < NNODES) { g_rowptr[i] = excl; g_cursor[i] = excl; }
        __syncthreads();
        if (threadIdx.x == 1023) carry += sh[1023];
        __syncthreads();
    }
    if (threadIdx.x == 0) g_rowptr[NNODES] = carry;
}
__global__ void k_fill_csr() {
    int e = blockIdx.x * blockDim.x + threadIdx.x;
    if (e >= NEDGES) return;
    int s = g_src[e], d = g_dst[e];
    int p = atomicAdd(&g_cursor[d], 1);
    g_csr_src[p] = s;
    g_csr_w[p]   = g_dinv[s] * g_dinv[d];
}

// ---------------- conversion / split kernels ----------------
__global__ void k_split_xgo(const float* __restrict__ x) {
    size_t i = (size_t)blockIdx.x * blockDim.x + threadIdx.x;  // float2 unit
    const size_t total = (size_t)MPAD_GO * GOIDD / 2;
    if (i >= total) return;
    size_t row = i / (GOIDD / 2), c2 = i % (GOIDD / 2);
    float2 v = make_float2(0.f, 0.f);
    if (row < NGO) v = ((const float2*)x)[((size_t)(NGENE + row) * GOIDD) / 2 + c2];
    __nv_bfloat16 h0, l0, h1, l1;
    split2(v.x, h0, l0); split2(v.y, h1, l1);
    __nv_bfloat162 hp; hp.x = h0; hp.y = h1;
    __nv_bfloat162 lp; lp.x = l0; lp.y = l1;
    ((__nv_bfloat162*)g_xgo_h)[i] = hp;
    ((__nv_bfloat162*)g_xgo_l)[i] = lp;
}

__global__ void k_split_w(const float* __restrict__ W, __nv_bfloat16* __restrict__ dh,
                          __nv_bfloat16* __restrict__ dl, int K, int N) {
    size_t i = (size_t)blockIdx.x * blockDim.x + threadIdx.x;
    if (i >= (size_t)K * N) return;
    int k = (int)(i / N), n = (int)(i % N);
    __nv_bfloat16 h, l;
    split2(W[i], h, l);
    dh[(size_t)n * K + k] = h;
    dl[(size_t)n * K + k] = l;
}

__global__ void k_copy_gene_split(const float* __restrict__ x) {
    size_t i = (size_t)blockIdx.x * blockDim.x + threadIdx.x;  // float2 unit
    const size_t total = (size_t)NGENE * DIM / 2;
    if (i >= total) return;
    size_t row = i / (DIM / 2), c2 = i % (DIM / 2);
    float2 v = ((const float2*)x)[((size_t)row * GOIDD) / 2 + c2];
    __nv_bfloat16 h0, l0, h1, l1;
    split2(v.x, h0, l0); split2(v.y, h1, l1);
    __nv_bfloat162 hp; hp.x = h0; hp.y = h1;
    __nv_bfloat162 lp; lp.x = l0; lp.y = l1;
    ((__nv_bfloat162*)g_xt_h)[(size_t)row * (DIM / 2) + c2] = hp;
    ((__nv_bfloat162*)g_xt_l)[(size_t)row * (DIM / 2) + c2] = lp;
}

__global__ void k_zero_bf16(__nv_bfloat16* p, int n2) {
    int i = blockIdx.x * blockDim.x + threadIdx.x;
    if (i < n2) ((uint32_t*)p)[i] = 0u;
}

// ---------------- HMMA bf16 split GEMM ----------------
// C[M,N] = (Ah+Al)[M,K] @ (Bh+Bl)^T  (B stored [N,K] K-major), fp32 accum via
// mma.sync m16n8k16: C = AhBh + AhBl + AlBh.  CTA tile 128x128, K-chunk 64,
// 256 threads = 8 warps (4 m x 2 n), warp tile 32x64.
// A row-padded to gridDim.y*128; N%128==0; K%64==0. Stores guarded by M.
#define GEMM_SMEM (2 * 4 * 16384)

template <bool BIAS, bool RELU, bool WF32, bool WBF16>
__global__ __launch_bounds__(256, 1)
void k_hgemm(const __nv_bfloat16* __restrict__ Ah, const __nv_bfloat16* __restrict__ Al,
             const __nv_bfloat16* __restrict__ Bh, const __nv_bfloat16* __restrict__ Bl,
             const float* __restrict__ bias,
             float* __restrict__ Cf, __nv_bfloat16* __restrict__ Ch, __nv_bfloat16* __restrict__ Cl,
             int M, int N, int K)
{
    extern __shared__ char smem[];
    const uint32_t sb = smem_u32(smem);
    const int tid  = threadIdx.x;
    const int wid  = tid >> 5;
    const int lane = tid & 31;
    const int wm   = wid >> 1;       // 0..3 (m block of 32)
    const int wn   = wid & 1;        // 0..1 (n block of 64)
    const int bm = blockIdx.y * 128, bn = blockIdx.x * 128;

    // cp.async source row pointers: thread t handles row t>>1, half (t&1)
    const int lrow  = tid >> 1;
    const int lhalf = (tid & 1) * 64;
    const char* srcA_h = (const char*)(Ah + (size_t)(bm + lrow) * K) + lhalf;
    const char* srcA_l = (const char*)(Al + (size_t)(bm + lrow) * K) + lhalf;
    const char* srcB_h = (const char*)(Bh + (size_t)(bn + lrow) * K) + lhalf;
    const char* srcB_l = (const char*)(Bl + (size_t)(bn + lrow) * K) + lhalf;

    const int NC = K / 64;

    auto load_chunk = [&](int s, int c) {
        const uint32_t kb = (uint32_t)c * 128;
        const char* srcs[4] = { srcA_h + kb, srcA_l + kb, srcB_h + kb, srcB_l + kb };
        const uint32_t lbase = (uint32_t)lrow * 128 + (uint32_t)lhalf;
#pragma unroll
        for (int m = 0; m < 4; m++) {
            uint32_t dbase = sb + (uint32_t)(s * 4 + m) * 16384;
#pragma unroll
            for (int i = 0; i < 4; i++) {
                uint32_t off = lbase + i * 16;
                cp16(swz(dbase, off), srcs[m] + i * 16);
            }
        }
        CP_COMMIT();
    };

    float acc[64];
#pragma unroll
    for (int i = 0; i < 64; i++) acc[i] = 0.f;

    // fragment lane addressing (within a tile, before swizzle)
    const uint32_t a_row = (uint32_t)(wm * 32) + (lane & 15);
    const uint32_t a_ksel = (lane >> 4) << 4;                 // +0 / +16 bytes
    const uint32_t b_row = (uint32_t)(wn * 64) + (lane & 7) + ((lane >> 4) << 3);
    const uint32_t b_ksel = (lane & 8) ? 16u : 0u;

    load_chunk(0, 0);

    for (int c = 0; c < NC; c++) {
        const int b = c & 1;
        if (c + 1 < NC) { load_chunk(1 - b, c + 1); CP_WAIT(1); }
        else            { CP_WAIT(0); }
        __syncthreads();

        const uint32_t tAh = sb + (uint32_t)(b * 4 + 0) * 16384;
        const uint32_t tAl = sb + (uint32_t)(b * 4 + 1) * 16384;
        const uint32_t tBh = sb + (uint32_t)(b * 4 + 2) * 16384;
        const uint32_t tBl = sb + (uint32_t)(b * 4 + 3) * 16384;

#pragma unroll
        for (int ks = 0; ks < 4; ks++) {
            const uint32_t kb = (uint32_t)ks * 32;
            uint32_t ah[8], al[8], bh[16], bl[16];
#pragma unroll
            for (int mt = 0; mt < 2; mt++) {
                uint32_t offA = (a_row + mt * 16) * 128 + kb + a_ksel;
                ldsm4(&ah[mt * 4], swz(tAh, offA));
                ldsm4(&al[mt * 4], swz(tAl, offA));
            }
#pragma unroll
            for (int p = 0; p < 4; p++) {
                uint32_t offB = (b_row + p * 16) * 128 + kb + b_ksel;
                ldsm4(&bh[p * 4], swz(tBh, offB));
                ldsm4(&bl[p * 4], swz(tBl, offB));
            }
#pragma unroll
            for (int mt = 0; mt < 2; mt++) {
#pragma unroll
                for (int nt = 0; nt < 8; nt++) {
                    float* d = &acc[(mt * 8 + nt) * 4];
                    mma16816(d, &ah[mt * 4], &bh[nt * 2]);
                    mma16816(d, &ah[mt * 4], &bl[nt * 2]);
                    mma16816(d, &al[mt * 4], &bh[nt * 2]);
                }
            }
        }
        __syncthreads();
    }

    // ---- epilogue ----
#pragma unroll
    for (int mt = 0; mt < 2; mt++) {
#pragma unroll
        for (int nt = 0; nt < 8; nt++) {
            const float* d = &acc[(mt * 8 + nt) * 4];
            const int r0 = bm + wm * 32 + mt * 16 + (lane >> 2);
            const int r1 = r0 + 8;
            const int col = bn + wn * 64 + nt * 8 + 2 * (lane & 3);
            float2 v0 = make_float2(d[0], d[1]);
            float2 v1 = make_float2(d[2], d[3]);
            if (BIAS) {
                float b0 = bias[col], b1 = bias[col + 1];
                v0.x += b0; v0.y += b1; v1.x += b0; v1.y += b1;
            }
            if (RELU) {
                v0.x = fmaxf(v0.x, 0.f); v0.y = fmaxf(v0.y, 0.f);
                v1.x = fmaxf(v1.x, 0.f); v1.y = fmaxf(v1.y, 0.f);
            }
            if (WF32) {
                if (r0 < M) *(float2*)(Cf + (size_t)r0 * N + col) = v0;
                if (r1 < M) *(float2*)(Cf + (size_t)r1 * N + col) = v1;
            }
            if (WBF16) {
                __nv_bfloat16 h0, l0, h1, l1;
                split2(v0.x, h0, l0); split2(v0.y, h1, l1);
                __nv_bfloat162 hp; hp.x = h0; hp.y = h1;
                __nv_bfloat162 lp; lp.x = l0; lp.y = l1;
                if (r0 < M) {
                    *(__nv_bfloat162*)(Ch + (size_t)r0 * N + col) = hp;
                    *(__nv_bfloat162*)(Cl + (size_t)r0 * N + col) = lp;
                }
                split2(v1.x, h0, l0); split2(v1.y, h1, l1);
                hp.x = h0; hp.y = h1; lp.x = l0; lp.y = l1;
                if (r1 < M) {
                    *(__nv_bfloat162*)(Ch + (size_t)r1 * N + col) = hp;
                    *(__nv_bfloat162*)(Cl + (size_t)r1 * N + col) = lp;
                }
            }
        }
    }
}

// ---------------- GCN aggregate + epilogue (CSR gather) ----------------
template <int F, bool SPLIT>
__global__ void k_gather_epi(const float* __restrict__ hw, float* __restrict__ rio,
                             const float* __restrict__ bias,
                             __nv_bfloat16* __restrict__ oh, __nv_bfloat16* __restrict__ ol)
{
    const int F4 = F / 4;
    int i = blockIdx.x;
    int t = threadIdx.x;
    int beg = g_rowptr[i], end = g_rowptr[i + 1];
    const float4* hw4 = (const float4*)hw;
    float4 acc = make_float4(0.f, 0.f, 0.f, 0.f);
    for (int e = beg; e < end; e++) {
        int s = g_csr_src[e];
        float w = g_csr_w[e];
        float4 v = hw4[(size_t)s * F4 + t];
        acc.x += w * v.x; acc.y += w * v.y; acc.z += w * v.z; acc.w += w * v.w;
    }
    float dv = g_dinv[i];
    float sn = dv * dv;
    float4 hv = hw4[(size_t)i * F4 + t];
    float4 bb = ((const float4*)bias)[t];
    float4 r  = ((const float4*)rio)[(size_t)i * F4 + t];
    float4 o;
    o.x = fmaxf(acc.x + sn * hv.x + bb.x, 0.f) + r.x;
    o.y = fmaxf(acc.y + sn * hv.y + bb.y, 0.f) + r.y;
    o.z = fmaxf(acc.z + sn * hv.z + bb.z, 0.f) + r.z;
    o.w = fmaxf(acc.w + sn * hv.w + bb.w, 0.f) + r.w;
    if (SPLIT) {
        __nv_bfloat16 h0, l0, h1, l1, h2, l2, h3, l3;
        split2(o.x, h0, l0); split2(o.y, h1, l1);
        split2(o.z, h2, l2); split2(o.w, h3, l3);
        __nv_bfloat162 hp0; hp0.x = h0; hp0.y = h1;
        __nv_bfloat162 hp1; hp1.x = h2; hp1.y = h3;
        __nv_bfloat162 lp0; lp0.x = l0; lp0.y = l1;
        __nv_bfloat162 lp1; lp1.x = l2; lp1.y = l3;
        __nv_bfloat162* ph = (__nv_bfloat162*)(oh + (size_t)i * F + t * 4);
        __nv_bfloat162* pl = (__nv_bfloat162*)(ol + (size_t)i * F + t * 4);
        ph[0] = hp0; ph[1] = hp1;
        pl[0] = lp0; pl[1] = lp1;
    } else {
        ((float4*)rio)[(size_t)i * F4 + t] = o;
    }
}

// ---------------- final fusion ----------------
__global__ void k_fusion(const float* __restrict__ h2, const float* __restrict__ istj,
                         const float* __restrict__ Wf, const float* __restrict__ bf,
                         float* __restrict__ out)
{
    int gwarp = (blockIdx.x * blockDim.x + threadIdx.x) >> 5;
    int lane = threadIdx.x & 31;
    if (gwarp >= NGENE) return;
    const float* h = h2 + (size_t)gwarp * HID2D;
    float a0 = 0.f, a1 = 0.f;
#pragma unroll
    for (int k = lane; k < HID2D; k += 32) {
        float v = h[k];
        a0 += v * Wf[2 * k];
        a1 += v * Wf[2 * k + 1];
    }
#pragma unroll
    for (int off = 16; off > 0; off >>= 1) {
        a0 += __shfl_down_sync(0xffffffffu, a0, off);
        a1 += __shfl_down_sync(0xffffffffu, a1, off);
    }
    if (lane == 0) {
        float t = istj[gwarp];
        out[2 * gwarp + 0] = a0 + t * Wf[2 * HID2D + 0] + bf[0];
        out[2 * gwarp + 1] = a1 + t * Wf[2 * HID2D + 1] + bf[1];
    }
}

// ---------------- host ----------------
template <typename T>
static inline T* sym(const void* s) {
    void* p = nullptr;
    cudaGetSymbolAddress(&p, s);
    return (T*)p;
}

extern "C" void kernel_launch(void* const* d_in, const int* in_sizes, int n_in,
                              void* d_out, int out_size)
{
    const float* x    = (const float*)d_in[0];
    const int*   eraw = (const int*)  d_in[1];
    const float* istj = (const float*)d_in[2];
    const int base = (in_sizes[3] < 1000) ? 4 : 3;
    const float* W_go1 = (const float*)d_in[base + 0];
    const float* b_go1 = (const float*)d_in[base + 1];
    const float* W_go2 = (const float*)d_in[base + 2];
    const float* b_go2 = (const float*)d_in[base + 3];
    const float* W_c1  = (const float*)d_in[base + 4];
    const float* b_c1  = (const float*)d_in[base + 5];
    const float* W_c2  = (const float*)d_in[base + 6];
    const float* b_c2  = (const float*)d_in[base + 7];
    const float* W_r1  = (const float*)d_in[base + 8];
    const float* b_r1  = (const float*)d_in[base + 9];
    const float* W_r2  = (const float*)d_in[base + 10];
    const float* b_r2  = (const float*)d_in[base + 11];
    const float* W_f   = (const float*)d_in[base + 12];
    const float* b_f   = (const float*)d_in[base + 13];
    float* out = (float*)d_out;

    cudaFuncSetAttribute((const void*)k_hgemm<true,  true,  false, true >, cudaFuncAttributeMaxDynamicSharedMemorySize, GEMM_SMEM);
    cudaFuncSetAttribute((const void*)k_hgemm<false, false, true,  false>, cudaFuncAttributeMaxDynamicSharedMemorySize, GEMM_SMEM);
    cudaFuncSetAttribute((const void*)k_hgemm<true,  false, true,  false>, cudaFuncAttributeMaxDynamicSharedMemorySize, GEMM_SMEM);

    float* p_hw = sym<float>(g_hw);
    float* p_r1 = sym<float>(g_r1);
    float* p_r2 = sym<float>(g_r2);
    __nv_bfloat16* xgo_h = sym<__nv_bfloat16>(g_xgo_h); __nv_bfloat16* xgo_l = sym<__nv_bfloat16>(g_xgo_l);
    __nv_bfloat16* go1_h = sym<__nv_bfloat16>(g_go1_h); __nv_bfloat16* go1_l = sym<__nv_bfloat16>(g_go1_l);
    __nv_bfloat16* xt_h  = sym<__nv_bfloat16>(g_xt_h);  __nv_bfloat16* xt_l  = sym<__nv_bfloat16>(g_xt_l);
    __nv_bfloat16* h1_h  = sym<__nv_bfloat16>(g_h1_h);  __nv_bfloat16* h1_l  = sym<__nv_bfloat16>(g_h1_l);
    __nv_bfloat16* wgo1h = sym<__nv_bfloat16>(g_Wgo1T_h); __nv_bfloat16* wgo1l = sym<__nv_bfloat16>(g_Wgo1T_l);
    __nv_bfloat16* wgo2h = sym<__nv_bfloat16>(g_Wgo2T_h); __nv_bfloat16* wgo2l = sym<__nv_bfloat16>(g_Wgo2T_l);
    __nv_bfloat16* wc1h  = sym<__nv_bfloat16>(g_Wc1T_h);  __nv_bfloat16* wc1l  = sym<__nv_bfloat16>(g_Wc1T_l);
    __nv_bfloat16* wr1h  = sym<__nv_bfloat16>(g_Wr1T_h);  __nv_bfloat16* wr1l  = sym<__nv_bfloat16>(g_Wr1T_l);
    __nv_bfloat16* wc2h  = sym<__nv_bfloat16>(g_Wc2T_h);  __nv_bfloat16* wc2l  = sym<__nv_bfloat16>(g_Wc2T_l);
    __nv_bfloat16* wr2h  = sym<__nv_bfloat16>(g_Wr2T_h);  __nv_bfloat16* wr2l  = sym<__nv_bfloat16>(g_Wr2T_l);

    // --- graph preprocessing ---
    k_init_indeg<<<(NNODES + 255) / 256, 256>>>();
    k_detect_idx_dtype<<<1, 32>>>(eraw);
    k_convert_edges<<<(NEDGES + 255) / 256, 256>>>(eraw);
    k_dinv<<<(NNODES + 255) / 256, 256>>>();
    k_scan<<<1, 1024>>>();
    k_fill_csr<<<(NEDGES + 255) / 256, 256>>>();

    // --- splits / conversions ---
    {
        size_t n2 = (size_t)MPAD_GO * GOIDD / 2;
        k_split_xgo<<<(unsigned)((n2 + 255) / 256), 256>>>(x);
    }
    k_split_w<<<(4096 * 1024 + 255) / 256, 256>>>(W_go1, wgo1h, wgo1l, 4096, 1024);
    k_split_w<<<(1024 * 512  + 255) / 256, 256>>>(W_go2, wgo2h, wgo2l, 1024, 512);
    k_split_w<<<(512  * 512  + 255) / 256, 256>>>(W_c1,  wc1h,  wc1l,  512,  512);
    k_split_w<<<(512  * 512  + 255) / 256, 256>>>(W_r1,  wr1h,  wr1l,  512,  512);
    k_split_w<<<(512  * 256  + 255) / 256, 256>>>(W_c2,  wc2h,  wc2l,  512,  256);
    k_split_w<<<(512  * 256  + 255) / 256, 256>>>(W_r2,  wr2h,  wr2l,  512,  256);
    k_copy_gene_split<<<(unsigned)(((size_t)NGENE * DIM / 2 + 255) / 256), 256>>>(x);
    k_zero_bf16<<<(112 * 1024 / 2 + 255) / 256, 256>>>(go1_h + (size_t)NGO * 1024, 112 * 1024 / 2);
    k_zero_bf16<<<(112 * 1024 / 2 + 255) / 256, 256>>>(go1_l + (size_t)NGO * 1024, 112 * 1024 / 2);
    k_zero_bf16<<<(48 * 512 / 2 + 255) / 256, 256>>>(xt_h + (size_t)NNODES * DIM, 48 * 512 / 2);
    k_zero_bf16<<<(48 * 512 / 2 + 255) / 256, 256>>>(xt_l + (size_t)NNODES * DIM, 48 * 512 / 2);
    k_zero_bf16<<<(48 * 512 / 2 + 255) / 256, 256>>>(h1_h + (size_t)NNODES * DIM, 48 * 512 / 2);
    k_zero_bf16<<<(48 * 512 / 2 + 255) / 256, 256>>>(h1_l + (size_t)NNODES * DIM, 48 * 512 / 2);

    // --- goid MLP ---
    {
        dim3 g(1024 / 128, MPAD_GO / 128);
        k_hgemm<true, true, false, true><<<g, 256, GEMM_SMEM>>>(
            xgo_h, xgo_l, wgo1h, wgo1l, b_go1,
            nullptr, go1_h, go1_l, NGO, 1024, 4096);
    }
    {
        dim3 g(512 / 128, MPAD_GO / 128);
        k_hgemm<true, true, false, true><<<g, 256, GEMM_SMEM>>>(
            go1_h, go1_l, wgo2h, wgo2l, b_go2,
            nullptr, xt_h + (size_t)NGENE * DIM, xt_l + (size_t)NGENE * DIM, NGO, 512, 1024);
    }

    // --- layer 1 ---
    {
        dim3 g(512 / 128, MPAD_N / 128);
        k_hgemm<false, false, true, false><<<g, 256, GEMM_SMEM>>>(
            xt_h, xt_l, wc1h, wc1l, nullptr, p_hw, nullptr, nullptr, NNODES, 512, 512);
        k_hgemm<true, false, true, false><<<g, 256, GEMM_SMEM>>>(
            xt_h, xt_l, wr1h, wr1l, b_r1, p_r1, nullptr, nullptr, NNODES, 512, 512);
    }
    k_gather_epi<DIM, true><<<NNODES, DIM / 4>>>(p_hw, p_r1, b_c1, h1_h, h1_l);

    // --- layer 2 ---
    {
        dim3 g(256 / 128, MPAD_N / 128);
        k_hgemm<false, false, true, false><<<g, 256, GEMM_SMEM>>>(
            h1_h, h1_l, wc2h, wc2l, nullptr, p_hw, nullptr, nullptr, NNODES, 256, 512);
        k_hgemm<true, false, true, false><<<g, 256, GEMM_SMEM>>>(
            h1_h, h1_l, wr2h, wr2l, b_r2, p_r2, nullptr, nullptr, NNODES, 256, 512);
    }
    k_gather_epi<HID2D, false><<<NNODES, HID2D / 4>>>(p_hw, p_r2, b_c2, nullptr, nullptr);

    // --- fusion head ---
    k_fusion<<<(NGENE * 32 + 255) / 256, 256>>>(p_r2, istj, W_f, b_f, out);

    (void)n_in; (void)out_size;
}

// round 4
// speedup vs baseline: 2.7908x; 1.3073x over previous
#include <cuda_runtime.h>
#include <cuda_fp16.h>
#include <cstdint>

// ---------------- problem constants ----------------
#define NNODES 50000
#define NGENE  40000
#define NGO    10000
#define NEDGES 800000
#define DIM    512
#define HID2D  256
#define GOIDD  4096
#define MPAD_GO 10112   // 79*128
#define MPAD_N  50048   // 391*128

// ---------------- helpers ----------------
__device__ __forceinline__ uint32_t smem_u32(const void* p) {
    uint32_t a;
    asm("{ .reg .u64 t; cvta.to.shared.u64 t, %1; cvt.u32.u64 %0, t; }" : "=r"(a) : "l"(p));
    return a;
}
__device__ __forceinline__ void cp16(uint32_t d, const void* s) {
    asm volatile("cp.async.cg.shared.global [%0], [%1], 16;" :: "r"(d), "l"(s) : "memory");
}
#define CP_COMMIT() asm volatile("cp.async.commit_group;" ::: "memory")
#define CP_WAIT(n)  asm volatile("cp.async.wait_group %0;" :: "n"(n) : "memory")

__device__ __forceinline__ void ldsm4(uint32_t* r, uint32_t addr) {
    asm volatile("ldmatrix.sync.aligned.m8n8.x4.shared.b16 {%0,%1,%2,%3}, [%4];"
        : "=r"(r[0]), "=r"(r[1]), "=r"(r[2]), "=r"(r[3]) : "r"(addr));
}
__device__ __forceinline__ void mma16816(float* d, const uint32_t* a, const uint32_t* b) {
    asm volatile(
        "mma.sync.aligned.m16n8k16.row.col.f32.f16.f16.f32 "
        "{%0,%1,%2,%3}, {%4,%5,%6,%7}, {%8,%9}, {%0,%1,%2,%3};"
        : "+f"(d[0]), "+f"(d[1]), "+f"(d[2]), "+f"(d[3])
        : "r"(a[0]), "r"(a[1]), "r"(a[2]), "r"(a[3]), "r"(b[0]), "r"(b[1]));
}
__device__ __forceinline__ uint32_t swz(uint32_t base, uint32_t off) {
    return base + (off ^ ((off >> 3) & 0x70));
}

// ---------------- scratch (device globals) ----------------
__device__ int   g_is64;
__device__ int   g_src[NEDGES];
__device__ int   g_dst[NEDGES];
__device__ int   g_indeg[NNODES];
__device__ int   g_rowptr[NNODES + 1];
__device__ int   g_cursor[NNODES];
__device__ float g_dinv[NNODES];
__device__ __align__(128) int   g_csr_src[NEDGES];
__device__ __align__(128) float g_csr_w[NEDGES];

__device__ __align__(128) float g_hw[(size_t)NNODES * DIM];
__device__ __align__(128) float g_r1[(size_t)NNODES * DIM];
__device__ __align__(128) float g_r2[(size_t)NNODES * HID2D];

// fp16 activations (single precision copy; rows padded to 128 multiples)
__device__ __align__(128) __half g_xgo[(size_t)MPAD_GO * GOIDD];
__device__ __align__(128) __half g_go1[(size_t)MPAD_GO * 1024];
__device__ __align__(128) __half g_xt [(size_t)MPAD_N * DIM];
__device__ __align__(128) __half g_h1 [(size_t)MPAD_N * DIM];

// fp16 hi/lo split transposed weights ([N,K] K-major)
__device__ __align__(128) __half g_Wgo1T_h[1024 * 4096];
__device__ __align__(128) __half g_Wgo1T_l[1024 * 4096];
__device__ __align__(128) __half g_Wgo2T_h[512 * 1024];
__device__ __align__(128) __half g_Wgo2T_l[512 * 1024];
__device__ __align__(128) __half g_W1T_h[1024 * 512];   // [Wc1T ; Wr1T]
__device__ __align__(128) __half g_W1T_l[1024 * 512];
__device__ __align__(128) __half g_W2T_h[512 * 512];    // [Wc2T ; Wr2T]
__device__ __align__(128) __half g_W2T_l[512 * 512];

// ---------------- graph preprocessing ----------------
__global__ void k_init_indeg() {
    int i = blockIdx.x * blockDim.x + threadIdx.x;
    if (i < NNODES) g_indeg[i] = 0;
}
__global__ void k_detect_idx_dtype(const int* __restrict__ raw) {
    if (threadIdx.x == 0 && blockIdx.x == 0) {
        int is64 = 1;
        for (int k = 0; k < 1024; k++)
            if (raw[2 * k + 1] != 0) { is64 = 0; break; }
        g_is64 = is64;
    }
}
__global__ void k_convert_edges(const int* __restrict__ raw) {
    int e = blockIdx.x * blockDim.x + threadIdx.x;
    if (e >= NEDGES) return;
    int s, d;
    if (g_is64) {
        const long long* r64 = (const long long*)raw;
        s = (int)r64[e]; d = (int)r64[NEDGES + e];
    } else {
        s = raw[e]; d = raw[NEDGES + e];
    }
    g_src[e] = s; g_dst[e] = d;
    atomicAdd(&g_indeg[d], 1);
}
__global__ void k_dinv() {
    int i = blockIdx.x * blockDim.x + threadIdx.x;
    if (i < NNODES) g_dinv[i] = rsqrtf(1.0f + (float)g_indeg[i]);
}
__global__ void k_scan() {
    __shared__ int sh[1024];
    __shared__ int carry;
    if (threadIdx.x == 0) carry = 0;
    __syncthreads();
    for (int base = 0; base < NNODES; base += 1024) {
        int i = base + (int)threadIdx.x;
        int v = (i < NNODES) ? g_indeg[i] : 0;
        sh[threadIdx.x] = v;
        __syncthreads();
        for (int off = 1; off < 1024; off <<= 1) {
            int t = (threadIdx.x >= (unsigned)off) ? sh[threadIdx.x - off] : 0;
            __syncthreads();
            sh[threadIdx.x] += t;
            __syncthreads();
        }
        int excl = sh[threadIdx.x] - v + carry;
        if (i < NNODES) { g_rowptr[i] = excl; g_cursor[i] = excl; }
        __syncthreads();
        if (threadIdx.x == 1023) carry += sh[1023];
        __syncthreads();
    }
    if (threadIdx.x == 0) g_rowptr[NNODES] = carry;
}
__global__ void k_fill_csr() {
    int e = blockIdx.x * blockDim.x + threadIdx.x;
    if (e >= NEDGES) return;
    int s = g_src[e], d = g_dst[e];
    int p = atomicAdd(&g_cursor[d], 1);
    g_csr_src[p] = s;
    g_csr_w[p]   = g_dinv[s] * g_dinv[d];
}

// ---------------- conversion kernels ----------------
// x[40000:, :4096] -> fp16 (zero pad rows to MPAD_GO)
__global__ void k_cvt_xgo(const float* __restrict__ x) {
    size_t i = (size_t)blockIdx.x * blockDim.x + threadIdx.x;  // half2 unit
    const size_t total = (size_t)MPAD_GO * GOIDD / 2;
    if (i >= total) return;
    size_t row = i / (GOIDD / 2), c2 = i % (GOIDD / 2);
    float2 v = make_float2(0.f, 0.f);
    if (row < NGO) v = ((const float2*)x)[((size_t)(NGENE + row) * GOIDD) / 2 + c2];
    ((__half2*)g_xgo)[i] = __floats2half2_rn(v.x, v.y);
}
// x[:40000, :512] -> g_xt fp16
__global__ void k_cvt_gene(const float* __restrict__ x) {
    size_t i = (size_t)blockIdx.x * blockDim.x + threadIdx.x;  // half2 unit
    const size_t total = (size_t)NGENE * DIM / 2;
    if (i >= total) return;
    size_t row = i / (DIM / 2), c2 = i % (DIM / 2);
    float2 v = ((const float2*)x)[((size_t)row * GOIDD) / 2 + c2];
    ((__half2*)g_xt)[(size_t)row * (DIM / 2) + c2] = __floats2half2_rn(v.x, v.y);
}
// W[K,N] fp32 -> [N,K] fp16 hi + lo
__global__ void k_split_w16(const float* __restrict__ W, __half* __restrict__ dh,
                            __half* __restrict__ dl, int K, int N) {
    size_t i = (size_t)blockIdx.x * blockDim.x + threadIdx.x;
    if (i >= (size_t)K * N) return;
    int k = (int)(i / N), n = (int)(i % N);
    float v = W[i];
    __half h = __float2half_rn(v);
    __half l = __float2half_rn(v - __half2float(h));
    dh[(size_t)n * K + k] = h;
    dl[(size_t)n * K + k] = l;
}
__global__ void k_zero16(__half* p, int n2) {
    int i = blockIdx.x * blockDim.x + threadIdx.x;
    if (i < n2) ((uint32_t*)p)[i] = 0u;
}

// ---------------- fp16 2-product HMMA GEMM ----------------
// C[M,N] = A[M,K](fp16) @ (Bh+Bl)^T (fp16 split weights, stored [N,K] K-major)
// CTA tile 128x128, K-chunk 64, 3-stage cp.async pipeline, 8 warps (4m x 2n).
// DUAL: cols [0,N/2) -> C1 (no bias/relu), cols [N/2,N) -> C2 (+bias). Strides N/2.
// else: single output (+bias/relu), fp32 (C1) or fp16 (Ch).
#define GEMM_SMEM (3 * 3 * 16384)   // 144 KB

template <bool DUAL, bool BIAS, bool RELU, bool WH16>
__global__ __launch_bounds__(256, 1)
void k_hgemm(const __half* __restrict__ A,
             const __half* __restrict__ Bh, const __half* __restrict__ Bl,
             const float* __restrict__ bias,
             float* __restrict__ C1, float* __restrict__ C2, __half* __restrict__ Ch,
             int M, int N, int K)
{
    extern __shared__ char smem[];
    const uint32_t sb = smem_u32(smem);
    const int tid  = threadIdx.x;
    const int wid  = tid >> 5;
    const int lane = tid & 31;
    const int wm   = wid >> 1;       // 0..3
    const int wn   = wid & 1;        // 0..1
    const int bm = blockIdx.y * 128, bn = blockIdx.x * 128;

    const int lrow  = tid >> 1;          // 0..127
    const int lhalf = (tid & 1) * 64;    // byte offset within 128B row
    const char* srcA  = (const char*)(A  + (size_t)(bm + lrow) * K) + lhalf;
    const char* srcBh = (const char*)(Bh + (size_t)(bn + lrow) * K) + lhalf;
    const char* srcBl = (const char*)(Bl + (size_t)(bn + lrow) * K) + lhalf;

    const int NC = K / 64;

    auto load_chunk = [&](int s, int c) {
        const uint32_t kb = (uint32_t)c * 128;
        const uint32_t stg = sb + (uint32_t)s * 49152;
        const uint32_t lbase = (uint32_t)lrow * 128 + (uint32_t)lhalf;
        const char* ps[3] = { srcA + kb, srcBh + kb, srcBl + kb };
#pragma unroll
        for (int m = 0; m < 3; m++) {
            uint32_t dbase = stg + (uint32_t)m * 16384;
#pragma unroll
            for (int i = 0; i < 4; i++) {
                uint32_t off = lbase + i * 16;
                cp16(swz(dbase, off), ps[m] + i * 16);
            }
        }
        CP_COMMIT();
    };

    float acc[64];
#pragma unroll
    for (int i = 0; i < 64; i++) acc[i] = 0.f;

    const uint32_t a_row  = (uint32_t)(wm * 32) + (lane & 15);
    const uint32_t a_ksel = (lane >> 4) << 4;
    const uint32_t b_row  = (uint32_t)(wn * 64) + (lane & 7) + ((lane >> 4) << 3);
    const uint32_t b_ksel = (lane & 8) ? 16u : 0u;

    load_chunk(0, 0);
    if (NC > 1) load_chunk(1, 1);

    for (int c = 0; c < NC; c++) {
        if (c + 1 < NC) { CP_WAIT(1); } else { CP_WAIT(0); }
        __syncthreads();
        if (c + 2 < NC) load_chunk((c + 2) % 3, c + 2);

        const uint32_t stg = sb + (uint32_t)(c % 3) * 49152;
        const uint32_t tA  = stg;
        const uint32_t tBh = stg + 16384;
        const uint32_t tBl = stg + 32768;

#pragma unroll
        for (int ks = 0; ks < 4; ks++) {
            const uint32_t kb = (uint32_t)ks * 32;
            uint32_t a[8], bh[16], bl[16];
#pragma unroll
            for (int mt = 0; mt < 2; mt++) {
                uint32_t offA = (a_row + mt * 16) * 128 + kb + a_ksel;
                ldsm4(&a[mt * 4], swz(tA, offA));
            }
#pragma unroll
            for (int p = 0; p < 4; p++) {
                uint32_t offB = (b_row + p * 16) * 128 + kb + b_ksel;
                ldsm4(&bh[p * 4], swz(tBh, offB));
                ldsm4(&bl[p * 4], swz(tBl, offB));
            }
#pragma unroll
            for (int mt = 0; mt < 2; mt++) {
#pragma unroll
                for (int nt = 0; nt < 8; nt++) {
                    float* d = &acc[(mt * 8 + nt) * 4];
                    mma16816(d, &a[mt * 4], &bh[nt * 2]);
                    mma16816(d, &a[mt * 4], &bl[nt * 2]);
                }
            }
        }
    }

    // ---- epilogue ----
    const int half  = N >> 1;
    const bool sec  = DUAL && (bn >= half);
    float* Cd       = DUAL ? (sec ? C2 : C1) : C1;
    const int cbase = sec ? half : 0;
    const int cstr  = DUAL ? half : N;

#pragma unroll
    for (int mt = 0; mt < 2; mt++) {
#pragma unroll
        for (int nt = 0; nt < 8; nt++) {
            const float* d = &acc[(mt * 8 + nt) * 4];
            const int r0 = bm + wm * 32 + mt * 16 + (lane >> 2);
            const int r1 = r0 + 8;
            const int col = bn + wn * 64 + nt * 8 + 2 * (lane & 3);
            float2 v0 = make_float2(d[0], d[1]);
            float2 v1 = make_float2(d[2], d[3]);
            if (DUAL) {
                if (BIAS && sec) {
                    float b0 = bias[col - cbase], b1 = bias[col - cbase + 1];
                    v0.x += b0; v0.y += b1; v1.x += b0; v1.y += b1;
                }
                const int cc = col - cbase;
                if (r0 < M) *(float2*)(Cd + (size_t)r0 * cstr + cc) = v0;
                if (r1 < M) *(float2*)(Cd + (size_t)r1 * cstr + cc) = v1;
            } else {
                if (BIAS) {
                    float b0 = bias[col], b1 = bias[col + 1];
                    v0.x += b0; v0.y += b1; v1.x += b0; v1.y += b1;
                }
                if (RELU) {
                    v0.x = fmaxf(v0.x, 0.f); v0.y = fmaxf(v0.y, 0.f);
                    v1.x = fmaxf(v1.x, 0.f); v1.y = fmaxf(v1.y, 0.f);
                }
                if (WH16) {
                    if (r0 < M) *(__half2*)(Ch + (size_t)r0 * N + col) = __floats2half2_rn(v0.x, v0.y);
                    if (r1 < M) *(__half2*)(Ch + (size_t)r1 * N + col) = __floats2half2_rn(v1.x, v1.y);
                } else {
                    if (r0 < M) *(float2*)(C1 + (size_t)r0 * N + col) = v0;
                    if (r1 < M) *(float2*)(C1 + (size_t)r1 * N + col) = v1;
                }
            }
        }
    }
}

// ---------------- GCN aggregate + epilogue (CSR gather) ----------------
// o[i] = relu( sum_e w_e*hw[src_e] + dinv[i]^2*hw[i] + bias ) + r[i]
// H16OUT: write fp16 (oh); else overwrite rio fp32.
template <int F, bool H16OUT>
__global__ void k_gather_epi(const float* __restrict__ hw, float* __restrict__ rio,
                             const float* __restrict__ bias, __half* __restrict__ oh)
{
    const int F4 = F / 4;
    int i = blockIdx.x;
    int t = threadIdx.x;
    int beg = g_rowptr[i], end = g_rowptr[i + 1];
    const float4* hw4 = (const float4*)hw;
    float4 acc = make_float4(0.f, 0.f, 0.f, 0.f);
    if (beg < end) {
        int s = g_csr_src[beg];
        float w = g_csr_w[beg];
        for (int e = beg; e < end; e++) {
            int s2 = 0; float w2 = 0.f;
            if (e + 1 < end) { s2 = g_csr_src[e + 1]; w2 = g_csr_w[e + 1]; }
            float4 v = hw4[(size_t)s * F4 + t];
            acc.x += w * v.x; acc.y += w * v.y; acc.z += w * v.z; acc.w += w * v.w;
            s = s2; w = w2;
        }
    }
    float dv = g_dinv[i];
    float sn = dv * dv;
    float4 hv = hw4[(size_t)i * F4 + t];
    float4 bb = ((const float4*)bias)[t];
    float4 r  = ((const float4*)rio)[(size_t)i * F4 + t];
    float4 o;
    o.x = fmaxf(acc.x + sn * hv.x + bb.x, 0.f) + r.x;
    o.y = fmaxf(acc.y + sn * hv.y + bb.y, 0.f) + r.y;
    o.z = fmaxf(acc.z + sn * hv.z + bb.z, 0.f) + r.z;
    o.w = fmaxf(acc.w + sn * hv.w + bb.w, 0.f) + r.w;
    if (H16OUT) {
        __half2* ph = (__half2*)(oh + (size_t)i * F + t * 4);
        ph[0] = __floats2half2_rn(o.x, o.y);
        ph[1] = __floats2half2_rn(o.z, o.w);
    } else {
        ((float4*)rio)[(size_t)i * F4 + t] = o;
    }
}

// ---------------- final fusion ----------------
__global__ void k_fusion(const float* __restrict__ h2, const float* __restrict__ istj,
                         const float* __restrict__ Wf, const float* __restrict__ bf,
                         float* __restrict__ out)
{
    int gwarp = (blockIdx.x * blockDim.x + threadIdx.x) >> 5;
    int lane = threadIdx.x & 31;
    if (gwarp >= NGENE) return;
    const float* h = h2 + (size_t)gwarp * HID2D;
    float a0 = 0.f, a1 = 0.f;
#pragma unroll
    for (int k = lane; k < HID2D; k += 32) {
        float v = h[k];
        a0 += v * Wf[2 * k];
        a1 += v * Wf[2 * k + 1];
    }
#pragma unroll
    for (int off = 16; off > 0; off >>= 1) {
        a0 += __shfl_down_sync(0xffffffffu, a0, off);
        a1 += __shfl_down_sync(0xffffffffu, a1, off);
    }
    if (lane == 0) {
        float t = istj[gwarp];
        out[2 * gwarp + 0] = a0 + t * Wf[2 * HID2D + 0] + bf[0];
        out[2 * gwarp + 1] = a1 + t * Wf[2 * HID2D + 1] + bf[1];
    }
}

// ---------------- host ----------------
template <typename T>
static inline T* sym(const void* s) {
    void* p = nullptr;
    cudaGetSymbolAddress(&p, s);
    return (T*)p;
}

extern "C" void kernel_launch(void* const* d_in, const int* in_sizes, int n_in,
                              void* d_out, int out_size)
{
    const float* x    = (const float*)d_in[0];
    const int*   eraw = (const int*)  d_in[1];
    const float* istj = (const float*)d_in[2];
    const int base = (in_sizes[3] < 1000) ? 4 : 3;
    const float* W_go1 = (const float*)d_in[base + 0];
    const float* b_go1 = (const float*)d_in[base + 1];
    const float* W_go2 = (const float*)d_in[base + 2];
    const float* b_go2 = (const float*)d_in[base + 3];
    const float* W_c1  = (const float*)d_in[base + 4];
    const float* b_c1  = (const float*)d_in[base + 5];
    const float* W_c2  = (const float*)d_in[base + 6];
    const float* b_c2  = (const float*)d_in[base + 7];
    const float* W_r1  = (const float*)d_in[base + 8];
    const float* b_r1  = (const float*)d_in[base + 9];
    const float* W_r2  = (const float*)d_in[base + 10];
    const float* b_r2  = (const float*)d_in[base + 11];
    const float* W_f   = (const float*)d_in[base + 12];
    const float* b_f   = (const float*)d_in[base + 13];
    float* out = (float*)d_out;

    cudaFuncSetAttribute((const void*)k_hgemm<false, true,  true,  true >,
                         cudaFuncAttributeMaxDynamicSharedMemorySize, GEMM_SMEM);
    cudaFuncSetAttribute((const void*)k_hgemm<true,  true,  false, false>,
                         cudaFuncAttributeMaxDynamicSharedMemorySize, GEMM_SMEM);

    float* p_hw = sym<float>(g_hw);
    float* p_r1 = sym<float>(g_r1);
    float* p_r2 = sym<float>(g_r2);
    __half* xgo  = sym<__half>(g_xgo);
    __half* go1  = sym<__half>(g_go1);
    __half* xt   = sym<__half>(g_xt);
    __half* h1   = sym<__half>(g_h1);
    __half* wgo1h = sym<__half>(g_Wgo1T_h); __half* wgo1l = sym<__half>(g_Wgo1T_l);
    __half* wgo2h = sym<__half>(g_Wgo2T_h); __half* wgo2l = sym<__half>(g_Wgo2T_l);
    __half* w1h   = sym<__half>(g_W1T_h);   __half* w1l   = sym<__half>(g_W1T_l);
    __half* w2h   = sym<__half>(g_W2T_h);   __half* w2l   = sym<__half>(g_W2T_l);

    // --- graph preprocessing ---
    k_init_indeg<<<(NNODES + 255) / 256, 256>>>();
    k_detect_idx_dtype<<<1, 32>>>(eraw);
    k_convert_edges<<<(NEDGES + 255) / 256, 256>>>(eraw);
    k_dinv<<<(NNODES + 255) / 256, 256>>>();
    k_scan<<<1, 1024>>>();
    k_fill_csr<<<(NEDGES + 255) / 256, 256>>>();

    // --- conversions ---
    {
        size_t n2 = (size_t)MPAD_GO * GOIDD / 2;
        k_cvt_xgo<<<(unsigned)((n2 + 255) / 256), 256>>>(x);
    }
    k_cvt_gene<<<(unsigned)(((size_t)NGENE * DIM / 2 + 255) / 256), 256>>>(x);
    k_split_w16<<<(4096 * 1024 + 255) / 256, 256>>>(W_go1, wgo1h, wgo1l, 4096, 1024);
    k_split_w16<<<(1024 * 512  + 255) / 256, 256>>>(W_go2, wgo2h, wgo2l, 1024, 512);
    k_split_w16<<<(512 * 512 + 255) / 256, 256>>>(W_c1, w1h,             w1l,             512, 512);
    k_split_w16<<<(512 * 512 + 255) / 256, 256>>>(W_r1, w1h + 512 * 512, w1l + 512 * 512, 512, 512);
    k_split_w16<<<(512 * 256 + 255) / 256, 256>>>(W_c2, w2h,             w2l,             512, 256);
    k_split_w16<<<(512 * 256 + 255) / 256, 256>>>(W_r2, w2h + 256 * 512, w2l + 256 * 512, 512, 256);
    // zero padded A rows
    k_zero16<<<(112 * 1024 / 2 + 255) / 256, 256>>>(go1 + (size_t)NGO * 1024, 112 * 1024 / 2);
    k_zero16<<<(48 * 512 / 2 + 255) / 256, 256>>>(xt + (size_t)NNODES * DIM, 48 * 512 / 2);
    k_zero16<<<(48 * 512 / 2 + 255) / 256, 256>>>(h1 + (size_t)NNODES * DIM, 48 * 512 / 2);

    // --- goid MLP ---
    {
        dim3 g(1024 / 128, MPAD_GO / 128);
        k_hgemm<false, true, true, true><<<g, 256, GEMM_SMEM>>>(
            xgo, wgo1h, wgo1l, b_go1, nullptr, nullptr, go1, NGO, 1024, 4096);
    }
    {
        dim3 g(512 / 128, MPAD_GO / 128);
        k_hgemm<false, true, true, true><<<g, 256, GEMM_SMEM>>>(
            go1, wgo2h, wgo2l, b_go2, nullptr, nullptr,
            xt + (size_t)NGENE * DIM, NGO, 512, 1024);
    }

    // --- layer 1: dual GEMM (hw | r1), then gather -> h1 fp16 ---
    {
        dim3 g(1024 / 128, MPAD_N / 128);
        k_hgemm<true, true, false, false><<<g, 256, GEMM_SMEM>>>(
            xt, w1h, w1l, b_r1, p_hw, p_r1, nullptr, NNODES, 1024, 512);
    }
    k_gather_epi<DIM, true><<<NNODES, DIM / 4>>>(p_hw, p_r1, b_c1, h1);

    // --- layer 2: dual GEMM (hw | r2), then gather -> h2 fp32 (in r2) ---
    {
        dim3 g(512 / 128, MPAD_N / 128);
        k_hgemm<true, true, false, false><<<g, 256, GEMM_SMEM>>>(
            h1, w2h, w2l, b_r2, p_hw, p_r2, nullptr, NNODES, 512, 512);
    }
    k_gather_epi<HID2D, false><<<NNODES, HID2D / 4>>>(p_hw, p_r2, b_c2, nullptr);

    // --- fusion head ---
    k_fusion<<<(NGENE * 32 + 255) / 256, 256>>>(p_r2, istj, W_f, b_f, out);

    (void)n_in; (void)out_size;
}

// round 5
// speedup vs baseline: 3.1437x; 1.1264x over previous
#include <cuda_runtime.h>
#include <cuda_fp16.h>
#include <cstdint>

// ---------------- problem constants ----------------
#define NNODES 50000
#define NGENE  40000
#define NGO    10000
#define NEDGES 800000
#define DIM    512
#define HID2D  256
#define GOIDD  4096
#define MPAD_GO 10112   // 79*128
#define MPAD_N  50048   // 391*128

// ---------------- helpers ----------------
__device__ __forceinline__ uint32_t smem_u32(const void* p) {
    uint32_t a;
    asm("{ .reg .u64 t; cvta.to.shared.u64 t, %1; cvt.u32.u64 %0, t; }" : "=r"(a) : "l"(p));
    return a;
}
__device__ __forceinline__ void cp16(uint32_t d, const void* s) {
    asm volatile("cp.async.cg.shared.global [%0], [%1], 16;" :: "r"(d), "l"(s) : "memory");
}
#define CP_COMMIT() asm volatile("cp.async.commit_group;" ::: "memory")
#define CP_WAIT(n)  asm volatile("cp.async.wait_group %0;" :: "n"(n) : "memory")

__device__ __forceinline__ void ldsm4(uint32_t* r, uint32_t addr) {
    asm volatile("ldmatrix.sync.aligned.m8n8.x4.shared.b16 {%0,%1,%2,%3}, [%4];"
        : "=r"(r[0]), "=r"(r[1]), "=r"(r[2]), "=r"(r[3]) : "r"(addr));
}
__device__ __forceinline__ void mma16816(float* d, const uint32_t* a, const uint32_t* b) {
    asm volatile(
        "mma.sync.aligned.m16n8k16.row.col.f32.f16.f16.f32 "
        "{%0,%1,%2,%3}, {%4,%5,%6,%7}, {%8,%9}, {%0,%1,%2,%3};"
        : "+f"(d[0]), "+f"(d[1]), "+f"(d[2]), "+f"(d[3])
        : "r"(a[0]), "r"(a[1]), "r"(a[2]), "r"(a[3]), "r"(b[0]), "r"(b[1]));
}
__device__ __forceinline__ uint32_t swz(uint32_t base, uint32_t off) {
    return base + (off ^ ((off >> 3) & 0x70));
}

// ---------------- scratch (device globals) ----------------
__device__ int   g_is64;
__device__ int   g_src[NEDGES];
__device__ int   g_dst[NEDGES];
__device__ int   g_indeg[NNODES];
__device__ int   g_rowptr[NNODES + 1];
__device__ int   g_cursor[NNODES];
__device__ float g_dinv[NNODES];
__device__ __align__(128) int   g_csr_src[NEDGES];
__device__ __align__(128) float g_csr_w[NEDGES];

__device__ __align__(128) float g_hw[(size_t)NNODES * DIM];
__device__ __align__(128) float g_r1[(size_t)NNODES * DIM];
__device__ __align__(128) float g_r2[(size_t)NNODES * HID2D];

// fp16 activations (rows padded to 128 multiples)
__device__ __align__(128) __half g_xgo[(size_t)MPAD_GO * GOIDD];
__device__ __align__(128) __half g_go1[(size_t)MPAD_GO * 1024];
__device__ __align__(128) __half g_xt [(size_t)MPAD_N * DIM];
__device__ __align__(128) __half g_h1 [(size_t)MPAD_N * DIM];

// fp16 hi/lo split transposed weights ([N,K] K-major)
__device__ __align__(128) __half g_Wgo1T_h[1024 * 4096];
__device__ __align__(128) __half g_Wgo1T_l[1024 * 4096];
__device__ __align__(128) __half g_Wgo2T_h[512 * 1024];
__device__ __align__(128) __half g_Wgo2T_l[512 * 1024];
__device__ __align__(128) __half g_W1T_h[1024 * 512];   // [Wc1T ; Wr1T]
__device__ __align__(128) __half g_W1T_l[1024 * 512];
__device__ __align__(128) __half g_W2T_h[512 * 512];    // [Wc2T ; Wr2T]
__device__ __align__(128) __half g_W2T_l[512 * 512];

// ---------------- graph preprocessing ----------------
__global__ void k_init_indeg() {
    int i = blockIdx.x * blockDim.x + threadIdx.x;
    if (i < NNODES) g_indeg[i] = 0;
}
// parallel dtype detect: 1024 threads sample the 2nd 32-bit word of each of
// the first 1024 int64 candidates; any nonzero -> int32 layout.
__global__ void k_detect_idx_dtype(const int* __restrict__ raw) {
    __shared__ int flag;
    if (threadIdx.x == 0) flag = 1;
    __syncthreads();
    if (raw[2 * threadIdx.x + 1] != 0) flag = 0;
    __syncthreads();
    if (threadIdx.x == 0) g_is64 = flag;
}
__global__ void k_convert_edges(const int* __restrict__ raw) {
    int e = blockIdx.x * blockDim.x + threadIdx.x;
    if (e >= NEDGES) return;
    int s, d;
    if (g_is64) {
        const long long* r64 = (const long long*)raw;
        s = (int)r64[e]; d = (int)r64[NEDGES + e];
    } else {
        s = raw[e]; d = raw[NEDGES + e];
    }
    g_src[e] = s; g_dst[e] = d;
    atomicAdd(&g_indeg[d], 1);
}
__global__ void k_dinv() {
    int i = blockIdx.x * blockDim.x + threadIdx.x;
    if (i < NNODES) g_dinv[i] = rsqrtf(1.0f + (float)g_indeg[i]);
}
__global__ void k_scan() {
    __shared__ int sh[1024];
    __shared__ int carry;
    if (threadIdx.x == 0) carry = 0;
    __syncthreads();
    for (int base = 0; base < NNODES; base += 1024) {
        int i = base + (int)threadIdx.x;
        int v = (i < NNODES) ? g_indeg[i] : 0;
        sh[threadIdx.x] = v;
        __syncthreads();
        for (int off = 1; off < 1024; off <<= 1) {
            int t = (threadIdx.x >= (unsigned)off) ? sh[threadIdx.x - off] : 0;
            __syncthreads();
            sh[threadIdx.x] += t;
            __syncthreads();
        }
        int excl = sh[threadIdx.x] - v + carry;
        if (i < NNODES) { g_rowptr[i] = excl; g_cursor[i] = excl; }
        __syncthreads();
        if (threadIdx.x == 1023) carry += sh[1023];
        __syncthreads();
    }
    if (threadIdx.x == 0) g_rowptr[NNODES] = carry;
}
__global__ void k_fill_csr() {
    int e = blockIdx.x * blockDim.x + threadIdx.x;
    if (e >= NEDGES) return;
    int s = g_src[e], d = g_dst[e];
    int p = atomicAdd(&g_cursor[d], 1);
    g_csr_src[p] = s;
    g_csr_w[p]   = g_dinv[s] * g_dinv[d];
}

// ---------------- conversion kernels ----------------
__global__ void k_cvt_xgo(const float* __restrict__ x) {
    size_t i = (size_t)blockIdx.x * blockDim.x + threadIdx.x;  // half2 unit
    const size_t total = (size_t)MPAD_GO * GOIDD / 2;
    if (i >= total) return;
    size_t row = i / (GOIDD / 2), c2 = i % (GOIDD / 2);
    float2 v = make_float2(0.f, 0.f);
    if (row < NGO) v = ((const float2*)x)[((size_t)(NGENE + row) * GOIDD) / 2 + c2];
    ((__half2*)g_xgo)[i] = __floats2half2_rn(v.x, v.y);
}
__global__ void k_cvt_gene(const float* __restrict__ x) {
    size_t i = (size_t)blockIdx.x * blockDim.x + threadIdx.x;  // half2 unit
    const size_t total = (size_t)NGENE * DIM / 2;
    if (i >= total) return;
    size_t row = i / (DIM / 2), c2 = i % (DIM / 2);
    float2 v = ((const float2*)x)[((size_t)row * GOIDD) / 2 + c2];
    ((__half2*)g_xt)[(size_t)row * (DIM / 2) + c2] = __floats2half2_rn(v.x, v.y);
}
// W[K,N] fp32 -> [N,K] fp16 hi + lo, 32x32 smem-tiled transpose (coalesced).
// grid: (N/32, K/32), block (32, 8). K,N multiples of 32 at all call sites.
__global__ void k_split_w16T(const float* __restrict__ W, __half* __restrict__ dh,
                             __half* __restrict__ dl, int K, int N) {
    __shared__ float tile[32][33];
    const int nb = blockIdx.x * 32, kb = blockIdx.y * 32;
    const int tx = threadIdx.x, ty = threadIdx.y;
#pragma unroll
    for (int r = 0; r < 32; r += 8)
        tile[ty + r][tx] = W[(size_t)(kb + ty + r) * N + nb + tx];
    __syncthreads();
#pragma unroll
    for (int r = 0; r < 32; r += 8) {
        float v = tile[tx][ty + r];              // k = kb+tx, n = nb+ty+r
        __half h = __float2half_rn(v);
        __half l = __float2half_rn(v - __half2float(h));
        dh[(size_t)(nb + ty + r) * K + kb + tx] = h;
        dl[(size_t)(nb + ty + r) * K + kb + tx] = l;
    }
}
__global__ void k_zero16(__half* p, int n2) {
    int i = blockIdx.x * blockDim.x + threadIdx.x;
    if (i < n2) ((uint32_t*)p)[i] = 0u;
}

// ---------------- fp16 2-product HMMA GEMM ----------------
// C[M,N] = A[M,K](fp16) @ (Bh+Bl)^T (fp16 split weights, stored [N,K] K-major)
// CTA tile 128x128, K-chunk 64, 2-stage cp.async pipeline, 2 CTAs/SM,
// 8 warps (4m x 2n).
// DUAL: cols [0,N/2) -> C1 (no bias/relu), cols [N/2,N) -> C2 (+bias).
#define GEMM_SMEM (2 * 3 * 16384)   // 96 KB

template <bool DUAL, bool BIAS, bool RELU, bool WH16>
__global__ __launch_bounds__(256, 2)
void k_hgemm(const __half* __restrict__ A,
             const __half* __restrict__ Bh, const __half* __restrict__ Bl,
             const float* __restrict__ bias,
             float* __restrict__ C1, float* __restrict__ C2, __half* __restrict__ Ch,
             int M, int N, int K)
{
    extern __shared__ char smem[];
    const uint32_t sb = smem_u32(smem);
    const int tid  = threadIdx.x;
    const int wid  = tid >> 5;
    const int lane = tid & 31;
    const int wm   = wid >> 1;       // 0..3
    const int wn   = wid & 1;        // 0..1
    const int bm = blockIdx.y * 128, bn = blockIdx.x * 128;

    const int lrow  = tid >> 1;          // 0..127
    const int lhalf = (tid & 1) * 64;    // byte offset within 128B row
    const char* srcA  = (const char*)(A  + (size_t)(bm + lrow) * K) + lhalf;
    const char* srcBh = (const char*)(Bh + (size_t)(bn + lrow) * K) + lhalf;
    const char* srcBl = (const char*)(Bl + (size_t)(bn + lrow) * K) + lhalf;

    const int NC = K / 64;

    auto load_chunk = [&](int s, int c) {
        const uint32_t kb = (uint32_t)c * 128;
        const uint32_t stg = sb + (uint32_t)s * 49152;
        const uint32_t lbase = (uint32_t)lrow * 128 + (uint32_t)lhalf;
        const char* ps[3] = { srcA + kb, srcBh + kb, srcBl + kb };
#pragma unroll
        for (int m = 0; m < 3; m++) {
            uint32_t dbase = stg + (uint32_t)m * 16384;
#pragma unroll
            for (int i = 0; i < 4; i++) {
                uint32_t off = lbase + i * 16;
                cp16(swz(dbase, off), ps[m] + i * 16);
            }
        }
        CP_COMMIT();
    };

    float acc[64];
#pragma unroll
    for (int i = 0; i < 64; i++) acc[i] = 0.f;

    const uint32_t a_row  = (uint32_t)(wm * 32) + (lane & 15);
    const uint32_t a_ksel = (lane >> 4) << 4;
    const uint32_t b_row  = (uint32_t)(wn * 64) + (lane & 7) + ((lane >> 4) << 3);
    const uint32_t b_ksel = (lane & 8) ? 16u : 0u;

    load_chunk(0, 0);

    for (int c = 0; c < NC; c++) {
        if (c + 1 < NC) { load_chunk((c + 1) & 1, c + 1); CP_WAIT(1); }
        else            { CP_WAIT(0); }
        __syncthreads();

        const uint32_t stg = sb + (uint32_t)(c & 1) * 49152;
        const uint32_t tA  = stg;
        const uint32_t tBh = stg + 16384;
        const uint32_t tBl = stg + 32768;

#pragma unroll
        for (int ks = 0; ks < 4; ks++) {
            const uint32_t kb = (uint32_t)ks * 32;
            uint32_t a[8];
            ldsm4(&a[0], swz(tA, (a_row)      * 128 + kb + a_ksel));
            ldsm4(&a[4], swz(tA, (a_row + 16) * 128 + kb + a_ksel));
#pragma unroll
            for (int p = 0; p < 4; p++) {
                uint32_t bh4[4], bl4[4];
                const uint32_t offB = (b_row + p * 16) * 128 + kb + b_ksel;
                ldsm4(bh4, swz(tBh, offB));
                ldsm4(bl4, swz(tBl, offB));
#pragma unroll
                for (int mt = 0; mt < 2; mt++) {
                    float* d0 = &acc[(mt * 8 + 2 * p) * 4];
                    float* d1 = &acc[(mt * 8 + 2 * p + 1) * 4];
                    mma16816(d0, &a[mt * 4], &bh4[0]);
                    mma16816(d0, &a[mt * 4], &bl4[0]);
                    mma16816(d1, &a[mt * 4], &bh4[2]);
                    mma16816(d1, &a[mt * 4], &bl4[2]);
                }
            }
        }
        __syncthreads();
    }

    // ---- epilogue ----
    const int half  = N >> 1;
    const bool sec  = DUAL && (bn >= half);
    float* Cd       = DUAL ? (sec ? C2 : C1) : C1;
    const int cbase = sec ? half : 0;
    const int cstr  = DUAL ? half : N;

#pragma unroll
    for (int mt = 0; mt < 2; mt++) {
#pragma unroll
        for (int nt = 0; nt < 8; nt++) {
            const float* d = &acc[(mt * 8 + nt) * 4];
            const int r0 = bm + wm * 32 + mt * 16 + (lane >> 2);
            const int r1 = r0 + 8;
            const int col = bn + wn * 64 + nt * 8 + 2 * (lane & 3);
            float2 v0 = make_float2(d[0], d[1]);
            float2 v1 = make_float2(d[2], d[3]);
            if (DUAL) {
                if (BIAS && sec) {
                    float b0 = bias[col - cbase], b1 = bias[col - cbase + 1];
                    v0.x += b0; v0.y += b1; v1.x += b0; v1.y += b1;
                }
                const int cc = col - cbase;
                if (r0 < M) *(float2*)(Cd + (size_t)r0 * cstr + cc) = v0;
                if (r1 < M) *(float2*)(Cd + (size_t)r1 * cstr + cc) = v1;
            } else {
                if (BIAS) {
                    float b0 = bias[col], b1 = bias[col + 1];
                    v0.x += b0; v0.y += b1; v1.x += b0; v1.y += b1;
                }
                if (RELU) {
                    v0.x = fmaxf(v0.x, 0.f); v0.y = fmaxf(v0.y, 0.f);
                    v1.x = fmaxf(v1.x, 0.f); v1.y = fmaxf(v1.y, 0.f);
                }
                if (WH16) {
                    if (r0 < M) *(__half2*)(Ch + (size_t)r0 * N + col) = __floats2half2_rn(v0.x, v0.y);
                    if (r1 < M) *(__half2*)(Ch + (size_t)r1 * N + col) = __floats2half2_rn(v1.x, v1.y);
                } else {
                    if (r0 < M) *(float2*)(C1 + (size_t)r0 * N + col) = v0;
                    if (r1 < M) *(float2*)(C1 + (size_t)r1 * N + col) = v1;
                }
            }
        }
    }
}

// ---------------- GCN aggregate + epilogue (CSR gather) ----------------
template <int F, bool H16OUT>
__global__ void k_gather_epi(const float* __restrict__ hw, float* __restrict__ rio,
                             const float* __restrict__ bias, __half* __restrict__ oh)
{
    const int F4 = F / 4;
    int i = blockIdx.x;
    int t = threadIdx.x;
    int beg = g_rowptr[i], end = g_rowptr[i + 1];
    const float4* hw4 = (const float4*)hw;
    float4 acc = make_float4(0.f, 0.f, 0.f, 0.f);
    if (beg < end) {
        int s = g_csr_src[beg];
        float w = g_csr_w[beg];
        for (int e = beg; e < end; e++) {
            int s2 = 0; float w2 = 0.f;
            if (e + 1 < end) { s2 = g_csr_src[e + 1]; w2 = g_csr_w[e + 1]; }
            float4 v = hw4[(size_t)s * F4 + t];
            acc.x += w * v.x; acc.y += w * v.y; acc.z += w * v.z; acc.w += w * v.w;
            s = s2; w = w2;
        }
    }
    float dv = g_dinv[i];
    float sn = dv * dv;
    float4 hv = hw4[(size_t)i * F4 + t];
    float4 bb = ((const float4*)bias)[t];
    float4 r  = ((const float4*)rio)[(size_t)i * F4 + t];
    float4 o;
    o.x = fmaxf(acc.x + sn * hv.x + bb.x, 0.f) + r.x;
    o.y = fmaxf(acc.y + sn * hv.y + bb.y, 0.f) + r.y;
    o.z = fmaxf(acc.z + sn * hv.z + bb.z, 0.f) + r.z;
    o.w = fmaxf(acc.w + sn * hv.w + bb.w, 0.f) + r.w;
    if (H16OUT) {
        __half2* ph = (__half2*)(oh + (size_t)i * F + t * 4);
        ph[0] = __floats2half2_rn(o.x, o.y);
        ph[1] = __floats2half2_rn(o.z, o.w);
    } else {
        ((float4*)rio)[(size_t)i * F4 + t] = o;
    }
}

// ---------------- final fusion ----------------
__global__ void k_fusion(const float* __restrict__ h2, const float* __restrict__ istj,
                         const float* __restrict__ Wf, const float* __restrict__ bf,
                         float* __restrict__ out)
{
    int gwarp = (blockIdx.x * blockDim.x + threadIdx.x) >> 5;
    int lane = threadIdx.x & 31;
    if (gwarp >= NGENE) return;
    const float* h = h2 + (size_t)gwarp * HID2D;
    float a0 = 0.f, a1 = 0.f;
#pragma unroll
    for (int k = lane; k < HID2D; k += 32) {
        float v = h[k];
        a0 += v * Wf[2 * k];
        a1 += v * Wf[2 * k + 1];
    }
#pragma unroll
    for (int off = 16; off > 0; off >>= 1) {
        a0 += __shfl_down_sync(0xffffffffu, a0, off);
        a1 += __shfl_down_sync(0xffffffffu, a1, off);
    }
    if (lane == 0) {
        float t = istj[gwarp];
        out[2 * gwarp + 0] = a0 + t * Wf[2 * HID2D + 0] + bf[0];
        out[2 * gwarp + 1] = a1 + t * Wf[2 * HID2D + 1] + bf[1];
    }
}

// ---------------- host ----------------
template <typename T>
static inline T* sym(const void* s) {
    void* p = nullptr;
    cudaGetSymbolAddress(&p, s);
    return (T*)p;
}

extern "C" void kernel_launch(void* const* d_in, const int* in_sizes, int n_in,
                              void* d_out, int out_size)
{
    const float* x    = (const float*)d_in[0];
    const int*   eraw = (const int*)  d_in[1];
    const float* istj = (const float*)d_in[2];
    const int base = (in_sizes[3] < 1000) ? 4 : 3;
    const float* W_go1 = (const float*)d_in[base + 0];
    const float* b_go1 = (const float*)d_in[base + 1];
    const float* W_go2 = (const float*)d_in[base + 2];
    const float* b_go2 = (const float*)d_in[base + 3];
    const float* W_c1  = (const float*)d_in[base + 4];
    const float* b_c1  = (const float*)d_in[base + 5];
    const float* W_c2  = (const float*)d_in[base + 6];
    const float* b_c2  = (const float*)d_in[base + 7];
    const float* W_r1  = (const float*)d_in[base + 8];
    const float* b_r1  = (const float*)d_in[base + 9];
    const float* W_r2  = (const float*)d_in[base + 10];
    const float* b_r2  = (const float*)d_in[base + 11];
    const float* W_f   = (const float*)d_in[base + 12];
    const float* b_f   = (const float*)d_in[base + 13];
    float* out = (float*)d_out;

    cudaFuncSetAttribute((const void*)k_hgemm<false, true,  true,  true >,
                         cudaFuncAttributeMaxDynamicSharedMemorySize, GEMM_SMEM);
    cudaFuncSetAttribute((const void*)k_hgemm<true,  true,  false, false>,
                         cudaFuncAttributeMaxDynamicSharedMemorySize, GEMM_SMEM);

    float* p_hw = sym<float>(g_hw);
    float* p_r1 = sym<float>(g_r1);
    float* p_r2 = sym<float>(g_r2);
    __half* xgo  = sym<__half>(g_xgo);
    __half* go1  = sym<__half>(g_go1);
    __half* xt   = sym<__half>(g_xt);
    __half* h1   = sym<__half>(g_h1);
    __half* wgo1h = sym<__half>(g_Wgo1T_h); __half* wgo1l = sym<__half>(g_Wgo1T_l);
    __half* wgo2h = sym<__half>(g_Wgo2T_h); __half* wgo2l = sym<__half>(g_Wgo2T_l);
    __half* w1h   = sym<__half>(g_W1T_h);   __half* w1l   = sym<__half>(g_W1T_l);
    __half* w2h   = sym<__half>(g_W2T_h);   __half* w2l   = sym<__half>(g_W2T_l);

    // --- graph preprocessing ---
    k_init_indeg<<<(NNODES + 255) / 256, 256>>>();
    k_detect_idx_dtype<<<1, 1024>>>(eraw);
    k_convert_edges<<<(NEDGES + 255) / 256, 256>>>(eraw);
    k_dinv<<<(NNODES + 255) / 256, 256>>>();
    k_scan<<<1, 1024>>>();
    k_fill_csr<<<(NEDGES + 255) / 256, 256>>>();

    // --- conversions ---
    {
        size_t n2 = (size_t)MPAD_GO * GOIDD / 2;
        k_cvt_xgo<<<(unsigned)((n2 + 255) / 256), 256>>>(x);
    }
    k_cvt_gene<<<(unsigned)(((size_t)NGENE * DIM / 2 + 255) / 256), 256>>>(x);
    {
        dim3 b(32, 8);
        k_split_w16T<<<dim3(1024 / 32, 4096 / 32), b>>>(W_go1, wgo1h, wgo1l, 4096, 1024);
        k_split_w16T<<<dim3(512 / 32, 1024 / 32),  b>>>(W_go2, wgo2h, wgo2l, 1024, 512);
        k_split_w16T<<<dim3(512 / 32, 512 / 32),   b>>>(W_c1, w1h,             w1l,             512, 512);
        k_split_w16T<<<dim3(512 / 32, 512 / 32),   b>>>(W_r1, w1h + 512 * 512, w1l + 512 * 512, 512, 512);
        k_split_w16T<<<dim3(256 / 32, 512 / 32),   b>>>(W_c2, w2h,             w2l,             512, 256);
        k_split_w16T<<<dim3(256 / 32, 512 / 32),   b>>>(W_r2, w2h + 256 * 512, w2l + 256 * 512, 512, 256);
    }
    // zero padded A rows
    k_zero16<<<(112 * 1024 / 2 + 255) / 256, 256>>>(go1 + (size_t)NGO * 1024, 112 * 1024 / 2);
    k_zero16<<<(48 * 512 / 2 + 255) / 256, 256>>>(xt + (size_t)NNODES * DIM, 48 * 512 / 2);
    k_zero16<<<(48 * 512 / 2 + 255) / 256, 256>>>(h1 + (size_t)NNODES * DIM, 48 * 512 / 2);

    // --- goid MLP ---
    {
        dim3 g(1024 / 128, MPAD_GO / 128);
        k_hgemm<false, true, true, true><<<g, 256, GEMM_SMEM>>>(
            xgo, wgo1h, wgo1l, b_go1, nullptr, nullptr, go1, NGO, 1024, 4096);
    }
    {
        dim3 g(512 / 128, MPAD_GO / 128);
        k_hgemm<false, true, true, true><<<g, 256, GEMM_SMEM>>>(
            go1, wgo2h, wgo2l, b_go2, nullptr, nullptr,
            xt + (size_t)NGENE * DIM, NGO, 512, 1024);
    }

    // --- layer 1: dual GEMM (hw | r1), then gather -> h1 fp16 ---
    {
        dim3 g(1024 / 128, MPAD_N / 128);
        k_hgemm<true, true, false, false><<<g, 256, GEMM_SMEM>>>(
            xt, w1h, w1l, b_r1, p_hw, p_r1, nullptr, NNODES, 1024, 512);
    }
    k_gather_epi<DIM, true><<<NNODES, DIM / 4>>>(p_hw, p_r1, b_c1, h1);

    // --- layer 2: dual GEMM (hw | r2), then gather -> h2 fp32 (in r2) ---
    {
        dim3 g(512 / 128, MPAD_N / 128);
        k_hgemm<true, true, false, false><<<g, 256, GEMM_SMEM>>>(
            h1, w2h, w2l, b_r2, p_hw, p_r2, nullptr, NNODES, 512, 512);
    }
    k_gather_epi<HID2D, false><<<NNODES, HID2D / 4>>>(p_hw, p_r2, b_c2, nullptr);

    // --- fusion head ---
    k_fusion<<<(NGENE * 32 + 255) / 256, 256>>>(p_r2, istj, W_f, b_f, out);

    (void)n_in; (void)out_size;
}

// round 7
// speedup vs baseline: 4.1114x; 1.3078x over previous
#include <cuda_runtime.h>
#include <cuda_fp16.h>
#include <cstdint>

// ---------------- problem constants ----------------
#define NNODES 50000
#define NGENE  40000
#define NGO    10000
#define NEDGES 800000
#define DIM    512
#define HID2D  256
#define GOIDD  4096
#define MPAD_GO 10112   // 79*128
#define MPAD_N  50048   // 391*128

// ---------------- helpers ----------------
__device__ __forceinline__ uint32_t smem_u32(const void* p) {
    uint32_t a;
    asm("{ .reg .u64 t; cvta.to.shared.u64 t, %1; cvt.u32.u64 %0, t; }" : "=r"(a) : "l"(p));
    return a;
}
__device__ __forceinline__ void cp16(uint32_t d, const void* s) {
    asm volatile("cp.async.cg.shared.global [%0], [%1], 16;" :: "r"(d), "l"(s) : "memory");
}
#define CP_COMMIT() asm volatile("cp.async.commit_group;" ::: "memory")
#define CP_WAIT(n)  asm volatile("cp.async.wait_group %0;" :: "n"(n) : "memory")

__device__ __forceinline__ void ldsm4(uint32_t* r, uint32_t addr) {
    asm volatile("ldmatrix.sync.aligned.m8n8.x4.shared.b16 {%0,%1,%2,%3}, [%4];"
        : "=r"(r[0]), "=r"(r[1]), "=r"(r[2]), "=r"(r[3]) : "r"(addr));
}
__device__ __forceinline__ void mma16816(float* d, const uint32_t* a, const uint32_t* b) {
    asm volatile(
        "mma.sync.aligned.m16n8k16.row.col.f32.f16.f16.f32 "
        "{%0,%1,%2,%3}, {%4,%5,%6,%7}, {%8,%9}, {%0,%1,%2,%3};"
        : "+f"(d[0]), "+f"(d[1]), "+f"(d[2]), "+f"(d[3])
        : "r"(a[0]), "r"(a[1]), "r"(a[2]), "r"(a[3]), "r"(b[0]), "r"(b[1]));
}
__device__ __forceinline__ uint32_t swz(uint32_t base, uint32_t off) {
    return base + (off ^ ((off >> 3) & 0x70));
}

// ---------------- scratch (device globals) ----------------
__device__ int   g_is64;
__device__ int   g_src[NEDGES];
__device__ int   g_dst[NEDGES];
__device__ int   g_indeg[NNODES];
__device__ int   g_rowptr[NNODES + 1];
__device__ int   g_cursor[NNODES];
__device__ float g_dinv[NNODES];
__device__ __align__(128) int   g_csr_src[NEDGES];
__device__ __align__(128) float g_csr_w[NEDGES];

__device__ __align__(128) float g_hw[(size_t)NNODES * DIM];
__device__ __align__(128) float g_r1[(size_t)NNODES * DIM];
__device__ __align__(128) float g_r2[(size_t)NNODES * HID2D];

// fp16 activations (rows padded to 128 multiples)
__device__ __align__(128) __half g_xgo[(size_t)MPAD_GO * GOIDD];
__device__ __align__(128) __half g_go1[(size_t)MPAD_GO * 1024];
__device__ __align__(128) __half g_xt [(size_t)MPAD_N * DIM];
__device__ __align__(128) __half g_h1 [(size_t)MPAD_N * DIM];

// fp16 transposed weights ([N,K] K-major); _l only used where NPROD=2
__device__ __align__(128) __half g_Wgo1T_h[1024 * 4096];
__device__ __align__(128) __half g_Wgo2T_h[512 * 1024];
__device__ __align__(128) __half g_Wgo2T_l[512 * 1024];
__device__ __align__(128) __half g_W1T_h[1024 * 512];   // [Wc1T ; Wr1T]
__device__ __align__(128) __half g_W2T_h[512 * 512];    // [Wc2T ; Wr2T]
__device__ __align__(128) __half g_W2T_l[512 * 512];

// ---------------- graph preprocessing ----------------
__global__ void k_init_indeg() {
    int i = blockIdx.x * blockDim.x + threadIdx.x;
    if (i < NNODES) g_indeg[i] = 0;
}
__global__ void k_detect_idx_dtype(const int* __restrict__ raw) {
    __shared__ int flag;
    if (threadIdx.x == 0) flag = 1;
    __syncthreads();
    if (raw[2 * threadIdx.x + 1] != 0) flag = 0;
    __syncthreads();
    if (threadIdx.x == 0) g_is64 = flag;
}
__global__ void k_convert_edges(const int* __restrict__ raw) {
    int e = blockIdx.x * blockDim.x + threadIdx.x;
    if (e >= NEDGES) return;
    int s, d;
    if (g_is64) {
        const long long* r64 = (const long long*)raw;
        s = (int)r64[e]; d = (int)r64[NEDGES + e];
    } else {
        s = raw[e]; d = raw[NEDGES + e];
    }
    g_src[e] = s; g_dst[e] = d;
    atomicAdd(&g_indeg[d], 1);
}
__global__ void k_dinv() {
    int i = blockIdx.x * blockDim.x + threadIdx.x;
    if (i < NNODES) g_dinv[i] = rsqrtf(1.0f + (float)g_indeg[i]);
}
__global__ void k_scan() {
    __shared__ int sh[1024];
    __shared__ int carry;
    if (threadIdx.x == 0) carry = 0;
    __syncthreads();
    for (int base = 0; base < NNODES; base += 1024) {
        int i = base + (int)threadIdx.x;
        int v = (i < NNODES) ? g_indeg[i] : 0;
        sh[threadIdx.x] = v;
        __syncthreads();
        for (int off = 1; off < 1024; off <<= 1) {
            int t = (threadIdx.x >= (unsigned)off) ? sh[threadIdx.x - off] : 0;
            __syncthreads();
            sh[threadIdx.x] += t;
            __syncthreads();
        }
        int excl = sh[threadIdx.x] - v + carry;
        if (i < NNODES) { g_rowptr[i] = excl; g_cursor[i] = excl; }
        __syncthreads();
        if (threadIdx.x == 1023) carry += sh[1023];
        __syncthreads();
    }
    if (threadIdx.x == 0) g_rowptr[NNODES] = carry;
}
__global__ void k_fill_csr() {
    int e = blockIdx.x * blockDim.x + threadIdx.x;
    if (e >= NEDGES) return;
    int s = g_src[e], d = g_dst[e];
    int p = atomicAdd(&g_cursor[d], 1);
    g_csr_src[p] = s;
    g_csr_w[p]   = g_dinv[s] * g_dinv[d];
}

// ---------------- conversion kernels ----------------
__global__ void k_cvt_xgo(const float* __restrict__ x) {
    size_t i = (size_t)blockIdx.x * blockDim.x + threadIdx.x;  // half2 unit
    const size_t total = (size_t)MPAD_GO * GOIDD / 2;
    if (i >= total) return;
    size_t row = i / (GOIDD / 2), c2 = i % (GOIDD / 2);
    float2 v = make_float2(0.f, 0.f);
    if (row < NGO) v = ((const float2*)x)[((size_t)(NGENE + row) * GOIDD) / 2 + c2];
    ((__half2*)g_xgo)[i] = __floats2half2_rn(v.x, v.y);
}
__global__ void k_cvt_gene(const float* __restrict__ x) {
    size_t i = (size_t)blockIdx.x * blockDim.x + threadIdx.x;  // half2 unit
    const size_t total = (size_t)NGENE * DIM / 2;
    if (i >= total) return;
    size_t row = i / (DIM / 2), c2 = i % (DIM / 2);
    float2 v = ((const float2*)x)[((size_t)row * GOIDD) / 2 + c2];
    ((__half2*)g_xt)[(size_t)row * (DIM / 2) + c2] = __floats2half2_rn(v.x, v.y);
}
// W[K,N] fp32 -> [N,K] fp16 hi (+ optional lo), 32x32 smem-tiled transpose.
template <bool LO>
__global__ void k_split_w16T(const float* __restrict__ W, __half* __restrict__ dh,
                             __half* __restrict__ dl, int K, int N) {
    __shared__ float tile[32][33];
    const int nb = blockIdx.x * 32, kb = blockIdx.y * 32;
    const int tx = threadIdx.x, ty = threadIdx.y;
#pragma unroll
    for (int r = 0; r < 32; r += 8)
        tile[ty + r][tx] = W[(size_t)(kb + ty + r) * N + nb + tx];
    __syncthreads();
#pragma unroll
    for (int r = 0; r < 32; r += 8) {
        float v = tile[tx][ty + r];              // k = kb+tx, n = nb+ty+r
        __half h = __float2half_rn(v);
        dh[(size_t)(nb + ty + r) * K + kb + tx] = h;
        if (LO) {
            __half l = __float2half_rn(v - __half2float(h));
            dl[(size_t)(nb + ty + r) * K + kb + tx] = l;
        }
    }
}
__global__ void k_zero16(__half* p, int n2) {
    int i = blockIdx.x * blockDim.x + threadIdx.x;
    if (i < n2) ((uint32_t*)p)[i] = 0u;
}

// ---------------- fp16 HMMA GEMM (NPROD = 1 or 2 weight products) ----------------
// C[M,N] = A[M,K](fp16) @ (Bh [+ Bl])^T, weights stored [N,K] K-major.
// CTA tile 128x128, K-chunk 64, 2-stage cp.async pipeline, 2 CTAs/SM.
// DUAL: cols [0,N/2) -> C1 (no bias/relu), cols [N/2,N) -> C2 (+bias).
#define NTILES(NP)    ((NP) + 1)                    // A, Bh [, Bl]   (FIXED: was NP+2)
#define GEMM_SMEM(NP) (2 * NTILES(NP) * 16384)

template <int NPROD, bool DUAL, bool BIAS, bool RELU, bool WH16>
__global__ __launch_bounds__(256, 2)
void k_hgemm(const __half* __restrict__ A,
             const __half* __restrict__ Bh, const __half* __restrict__ Bl,
             const float* __restrict__ bias,
             float* __restrict__ C1, float* __restrict__ C2, __half* __restrict__ Ch,
             int M, int N, int K)
{
    extern __shared__ char smem[];
    const uint32_t sb = smem_u32(smem);
    const int tid  = threadIdx.x;
    const int wid  = tid >> 5;
    const int lane = tid & 31;
    const int wm   = wid >> 1;       // 0..3
    const int wn   = wid & 1;        // 0..1
    const int bm = blockIdx.y * 128, bn = blockIdx.x * 128;

    const uint32_t STAGE = (uint32_t)NTILES(NPROD) * 16384;

    const int lrow  = tid >> 1;          // 0..127
    const int lhalf = (tid & 1) * 64;    // byte offset within 128B row
    const char* srcA  = (const char*)(A  + (size_t)(bm + lrow) * K) + lhalf;
    const char* srcBh = (const char*)(Bh + (size_t)(bn + lrow) * K) + lhalf;
    const char* srcBl = (NPROD == 2) ? (const char*)(Bl + (size_t)(bn + lrow) * K) + lhalf : nullptr;

    const int NC = K / 64;

    auto load_chunk = [&](int s, int c) {
        const uint32_t kb = (uint32_t)c * 128;
        const uint32_t stg = sb + (uint32_t)s * STAGE;
        const uint32_t lbase = (uint32_t)lrow * 128 + (uint32_t)lhalf;
#pragma unroll
        for (int m = 0; m < NTILES(NPROD); m++) {
            const char* src = (m == 0) ? srcA + kb : (m == 1 ? srcBh + kb : srcBl + kb);
            uint32_t dbase = stg + (uint32_t)m * 16384;
#pragma unroll
            for (int i = 0; i < 4; i++) {
                uint32_t off = lbase + i * 16;
                cp16(swz(dbase, off), src + i * 16);
            }
        }
        CP_COMMIT();
    };

    float acc[64];
#pragma unroll
    for (int i = 0; i < 64; i++) acc[i] = 0.f;

    const uint32_t a_row  = (uint32_t)(wm * 32) + (lane & 15);
    const uint32_t a_ksel = (lane >> 4) << 4;
    const uint32_t b_row  = (uint32_t)(wn * 64) + (lane & 7) + ((lane >> 4) << 3);
    const uint32_t b_ksel = (lane & 8) ? 16u : 0u;

    load_chunk(0, 0);

    for (int c = 0; c < NC; c++) {
        if (c + 1 < NC) { load_chunk((c + 1) & 1, c + 1); CP_WAIT(1); }
        else            { CP_WAIT(0); }
        __syncthreads();

        const uint32_t stg = sb + (uint32_t)(c & 1) * STAGE;
        const uint32_t tA  = stg;
        const uint32_t tBh = stg + 16384;
        const uint32_t tBl = stg + 32768;

#pragma unroll
        for (int ks = 0; ks < 4; ks++) {
            const uint32_t kb = (uint32_t)ks * 32;
            uint32_t a[8];
            ldsm4(&a[0], swz(tA, (a_row)      * 128 + kb + a_ksel));
            ldsm4(&a[4], swz(tA, (a_row + 16) * 128 + kb + a_ksel));
#pragma unroll
            for (int p = 0; p < 4; p++) {
                const uint32_t offB = (b_row + p * 16) * 128 + kb + b_ksel;
                uint32_t bh4[4];
                ldsm4(bh4, swz(tBh, offB));
                if (NPROD == 2) {
                    uint32_t bl4[4];
                    ldsm4(bl4, swz(tBl, offB));
#pragma unroll
                    for (int mt = 0; mt < 2; mt++) {
                        float* d0 = &acc[(mt * 8 + 2 * p) * 4];
                        float* d1 = &acc[(mt * 8 + 2 * p + 1) * 4];
                        mma16816(d0, &a[mt * 4], &bh4[0]);
                        mma16816(d0, &a[mt * 4], &bl4[0]);
                        mma16816(d1, &a[mt * 4], &bh4[2]);
                        mma16816(d1, &a[mt * 4], &bl4[2]);
                    }
                } else {
#pragma unroll
                    for (int mt = 0; mt < 2; mt++) {
                        float* d0 = &acc[(mt * 8 + 2 * p) * 4];
                        float* d1 = &acc[(mt * 8 + 2 * p + 1) * 4];
                        mma16816(d0, &a[mt * 4], &bh4[0]);
                        mma16816(d1, &a[mt * 4], &bh4[2]);
                    }
                }
            }
        }
        __syncthreads();
    }

    // ---- epilogue ----
    const int half  = N >> 1;
    const bool sec  = DUAL && (bn >= half);
    float* Cd       = DUAL ? (sec ? C2 : C1) : C1;
    const int cbase = sec ? half : 0;
    const int cstr  = DUAL ? half : N;

#pragma unroll
    for (int mt = 0; mt < 2; mt++) {
#pragma unroll
        for (int nt = 0; nt < 8; nt++) {
            const float* d = &acc[(mt * 8 + nt) * 4];
            const int r0 = bm + wm * 32 + mt * 16 + (lane >> 2);
            const int r1 = r0 + 8;
            const int col = bn + wn * 64 + nt * 8 + 2 * (lane & 3);
            float2 v0 = make_float2(d[0], d[1]);
            float2 v1 = make_float2(d[2], d[3]);
            if (DUAL) {
                if (BIAS && sec) {
                    float b0 = bias[col - cbase], b1 = bias[col - cbase + 1];
                    v0.x += b0; v0.y += b1; v1.x += b0; v1.y += b1;
                }
                const int cc = col - cbase;
                if (r0 < M) *(float2*)(Cd + (size_t)r0 * cstr + cc) = v0;
                if (r1 < M) *(float2*)(Cd + (size_t)r1 * cstr + cc) = v1;
            } else {
                if (BIAS) {
                    float b0 = bias[col], b1 = bias[col + 1];
                    v0.x += b0; v0.y += b1; v1.x += b0; v1.y += b1;
                }
                if (RELU) {
                    v0.x = fmaxf(v0.x, 0.f); v0.y = fmaxf(v0.y, 0.f);
                    v1.x = fmaxf(v1.x, 0.f); v1.y = fmaxf(v1.y, 0.f);
                }
                if (WH16) {
                    if (r0 < M) *(__half2*)(Ch + (size_t)r0 * N + col) = __floats2half2_rn(v0.x, v0.y);
                    if (r1 < M) *(__half2*)(Ch + (size_t)r1 * N + col) = __floats2half2_rn(v1.x, v1.y);
                } else {
                    if (r0 < M) *(float2*)(C1 + (size_t)r0 * N + col) = v0;
                    if (r1 < M) *(float2*)(C1 + (size_t)r1 * N + col) = v1;
                }
            }
        }
    }
}

// ---------------- GCN aggregate + epilogue (CSR gather) ----------------
template <int F, bool H16OUT>
__global__ void k_gather_epi(const float* __restrict__ hw, float* __restrict__ rio,
                             const float* __restrict__ bias, __half* __restrict__ oh)
{
    const int F4 = F / 4;
    int i = blockIdx.x;
    int t = threadIdx.x;
    int beg = g_rowptr[i], end = g_rowptr[i + 1];
    const float4* hw4 = (const float4*)hw;
    float4 acc = make_float4(0.f, 0.f, 0.f, 0.f);
    if (beg < end) {
        int s = g_csr_src[beg];
        float w = g_csr_w[beg];
        for (int e = beg; e < end; e++) {
            int s2 = 0; float w2 = 0.f;
            if (e + 1 < end) { s2 = g_csr_src[e + 1]; w2 = g_csr_w[e + 1]; }
            float4 v = hw4[(size_t)s * F4 + t];
            acc.x += w * v.x; acc.y += w * v.y; acc.z += w * v.z; acc.w += w * v.w;
            s = s2; w = w2;
        }
    }
    float dv = g_dinv[i];
    float sn = dv * dv;
    float4 hv = hw4[(size_t)i * F4 + t];
    float4 bb = ((const float4*)bias)[t];
    float4 r  = ((const float4*)rio)[(size_t)i * F4 + t];
    float4 o;
    o.x = fmaxf(acc.x + sn * hv.x + bb.x, 0.f) + r.x;
    o.y = fmaxf(acc.y + sn * hv.y + bb.y, 0.f) + r.y;
    o.z = fmaxf(acc.z + sn * hv.z + bb.z, 0.f) + r.z;
    o.w = fmaxf(acc.w + sn * hv.w + bb.w, 0.f) + r.w;
    if (H16OUT) {
        __half2* ph = (__half2*)(oh + (size_t)i * F + t * 4);
        ph[0] = __floats2half2_rn(o.x, o.y);
        ph[1] = __floats2half2_rn(o.z, o.w);
    } else {
        ((float4*)rio)[(size_t)i * F4 + t] = o;
    }
}

// ---------------- final fusion ----------------
__global__ void k_fusion(const float* __restrict__ h2, const float* __restrict__ istj,
                         const float* __restrict__ Wf, const float* __restrict__ bf,
                         float* __restrict__ out)
{
    int gwarp = (blockIdx.x * blockDim.x + threadIdx.x) >> 5;
    int lane = threadIdx.x & 31;
    if (gwarp >= NGENE) return;
    const float* h = h2 + (size_t)gwarp * HID2D;
    float a0 = 0.f, a1 = 0.f;
#pragma unroll
    for (int k = lane; k < HID2D; k += 32) {
        float v = h[k];
        a0 += v * Wf[2 * k];
        a1 += v * Wf[2 * k + 1];
    }
#pragma unroll
    for (int off = 16; off > 0; off >>= 1) {
        a0 += __shfl_down_sync(0xffffffffu, a0, off);
        a1 += __shfl_down_sync(0xffffffffu, a1, off);
    }
    if (lane == 0) {
        float t = istj[gwarp];
        out[2 * gwarp + 0] = a0 + t * Wf[2 * HID2D + 0] + bf[0];
        out[2 * gwarp + 1] = a1 + t * Wf[2 * HID2D + 1] + bf[1];
    }
}

// ---------------- host ----------------
template <typename T>
static inline T* sym(const void* s) {
    void* p = nullptr;
    cudaGetSymbolAddress(&p, s);
    return (T*)p;
}

extern "C" void kernel_launch(void* const* d_in, const int* in_sizes, int n_in,
                              void* d_out, int out_size)
{
    const float* x    = (const float*)d_in[0];
    const int*   eraw = (const int*)  d_in[1];
    const float* istj = (const float*)d_in[2];
    const int base = (in_sizes[3] < 1000) ? 4 : 3;
    const float* W_go1 = (const float*)d_in[base + 0];
    const float* b_go1 = (const float*)d_in[base + 1];
    const float* W_go2 = (const float*)d_in[base + 2];
    const float* b_go2 = (const float*)d_in[base + 3];
    const float* W_c1  = (const float*)d_in[base + 4];
    const float* b_c1  = (const float*)d_in[base + 5];
    const float* W_c2  = (const float*)d_in[base + 6];
    const float* b_c2  = (const float*)d_in[base + 7];
    const float* W_r1  = (const float*)d_in[base + 8];
    const float* b_r1  = (const float*)d_in[base + 9];
    const float* W_r2  = (const float*)d_in[base + 10];
    const float* b_r2  = (const float*)d_in[base + 11];
    const float* W_f   = (const float*)d_in[base + 12];
    const float* b_f   = (const float*)d_in[base + 13];
    float* out = (float*)d_out;

    cudaFuncSetAttribute((const void*)k_hgemm<1, false, true,  true,  true >,
                         cudaFuncAttributeMaxDynamicSharedMemorySize, GEMM_SMEM(1));
    cudaFuncSetAttribute((const void*)k_hgemm<2, false, true,  true,  true >,
                         cudaFuncAttributeMaxDynamicSharedMemorySize, GEMM_SMEM(2));
    cudaFuncSetAttribute((const void*)k_hgemm<1, true,  true,  false, false>,
                         cudaFuncAttributeMaxDynamicSharedMemorySize, GEMM_SMEM(1));
    cudaFuncSetAttribute((const void*)k_hgemm<2, true,  true,  false, false>,
                         cudaFuncAttributeMaxDynamicSharedMemorySize, GEMM_SMEM(2));

    float* p_hw = sym<float>(g_hw);
    float* p_r1 = sym<float>(g_r1);
    float* p_r2 = sym<float>(g_r2);
    __half* xgo  = sym<__half>(g_xgo);
    __half* go1  = sym<__half>(g_go1);
    __half* xt   = sym<__half>(g_xt);
    __half* h1   = sym<__half>(g_h1);
    __half* wgo1h = sym<__half>(g_Wgo1T_h);
    __half* wgo2h = sym<__half>(g_Wgo2T_h); __half* wgo2l = sym<__half>(g_Wgo2T_l);
    __half* w1h   = sym<__half>(g_W1T_h);
    __half* w2h   = sym<__half>(g_W2T_h);   __half* w2l   = sym<__half>(g_W2T_l);

    // --- graph preprocessing ---
    k_init_indeg<<<(NNODES + 255) / 256, 256>>>();
    k_detect_idx_dtype<<<1, 1024>>>(eraw);
    k_convert_edges<<<(NEDGES + 255) / 256, 256>>>(eraw);
    k_dinv<<<(NNODES + 255) / 256, 256>>>();
    k_scan<<<1, 1024>>>();
    k_fill_csr<<<(NEDGES + 255) / 256, 256>>>();

    // --- conversions ---
    {
        size_t n2 = (size_t)MPAD_GO * GOIDD / 2;
        k_cvt_xgo<<<(unsigned)((n2 + 255) / 256), 256>>>(x);
    }
    k_cvt_gene<<<(unsigned)(((size_t)NGENE * DIM / 2 + 255) / 256), 256>>>(x);
    {
        dim3 b(32, 8);
        k_split_w16T<false><<<dim3(1024 / 32, 4096 / 32), b>>>(W_go1, wgo1h, nullptr, 4096, 1024);
        k_split_w16T<true ><<<dim3(512 / 32, 1024 / 32),  b>>>(W_go2, wgo2h, wgo2l, 1024, 512);
        k_split_w16T<false><<<dim3(512 / 32, 512 / 32),   b>>>(W_c1, w1h,             nullptr, 512, 512);
        k_split_w16T<false><<<dim3(512 / 32, 512 / 32),   b>>>(W_r1, w1h + 512 * 512, nullptr, 512, 512);
        k_split_w16T<true ><<<dim3(256 / 32, 512 / 32),   b>>>(W_c2, w2h,             w2l,             512, 256);
        k_split_w16T<true ><<<dim3(256 / 32, 512 / 32),   b>>>(W_r2, w2h + 256 * 512, w2l + 256 * 512, 512, 256);
    }
    // zero padded A rows
    k_zero16<<<(112 * 1024 / 2 + 255) / 256, 256>>>(go1 + (size_t)NGO * 1024, 112 * 1024 / 2);
    k_zero16<<<(48 * 512 / 2 + 255) / 256, 256>>>(xt + (size_t)NNODES * DIM, 48 * 512 / 2);
    k_zero16<<<(48 * 512 / 2 + 255) / 256, 256>>>(h1 + (size_t)NNODES * DIM, 48 * 512 / 2);

    // --- goid MLP ---
    {
        dim3 g(1024 / 128, MPAD_GO / 128);
        k_hgemm<1, false, true, true, true><<<g, 256, GEMM_SMEM(1)>>>(
            xgo, wgo1h, nullptr, b_go1, nullptr, nullptr, go1, NGO, 1024, 4096);
    }
    {
        dim3 g(512 / 128, MPAD_GO / 128);
        k_hgemm<2, false, true, true, true><<<g, 256, GEMM_SMEM(2)>>>(
            go1, wgo2h, wgo2l, b_go2, nullptr, nullptr,
            xt + (size_t)NGENE * DIM, NGO, 512, 1024);
    }

    // --- layer 1: dual GEMM (hw | r1), then gather -> h1 fp16 ---
    {
        dim3 g(1024 / 128, MPAD_N / 128);
        k_hgemm<1, true, true, false, false><<<g, 256, GEMM_SMEM(1)>>>(
            xt, w1h, nullptr, b_r1, p_hw, p_r1, nullptr, NNODES, 1024, 512);
    }
    k_gather_epi<DIM, true><<<NNODES, DIM / 4>>>(p_hw, p_r1, b_c1, h1);

    // --- layer 2: dual GEMM (hw | r2), then gather -> h2 fp32 (in r2) ---
    {
        dim3 g(512 / 128, MPAD_N / 128);
        k_hgemm<2, true, true, false, false><<<g, 256, GEMM_SMEM(2)>>>(
            h1, w2h, w2l, b_r2, p_hw, p_r2, nullptr, NNODES, 512, 512);
    }
    k_gather_epi<HID2D, false><<<NNODES, HID2D / 4>>>(p_hw, p_r2, b_c2, nullptr);

    // --- fusion head ---
    k_fusion<<<(NGENE * 32 + 255) / 256, 256>>>(p_r2, istj, W_f, b_f, out);

    (void)n_in; (void)out_size;
}

// round 8
// speedup vs baseline: 4.3663x; 1.0620x over previous
#include <cuda_runtime.h>
#include <cuda_fp16.h>
#include <cstdint>

// ---------------- problem constants ----------------
#define NNODES 50000
#define NGENE  40000
#define NGO    10000
#define NEDGES 800000
#define DIM    512
#define HID2D  256
#define GOIDD  4096
#define MPAD_GO 10112   // 79*128
#define MPAD_N  50048   // 391*128

// ---------------- helpers ----------------
__device__ __forceinline__ uint32_t smem_u32(const void* p) {
    uint32_t a;
    asm("{ .reg .u64 t; cvta.to.shared.u64 t, %1; cvt.u32.u64 %0, t; }" : "=r"(a) : "l"(p));
    return a;
}
__device__ __forceinline__ void cp16(uint32_t d, const void* s) {
    asm volatile("cp.async.cg.shared.global [%0], [%1], 16;" :: "r"(d), "l"(s) : "memory");
}
#define CP_COMMIT() asm volatile("cp.async.commit_group;" ::: "memory")
#define CP_WAIT(n)  asm volatile("cp.async.wait_group %0;" :: "n"(n) : "memory")

__device__ __forceinline__ void ldsm4(uint32_t* r, uint32_t addr) {
    asm volatile("ldmatrix.sync.aligned.m8n8.x4.shared.b16 {%0,%1,%2,%3}, [%4];"
        : "=r"(r[0]), "=r"(r[1]), "=r"(r[2]), "=r"(r[3]) : "r"(addr));
}
__device__ __forceinline__ void mma16816(float* d, const uint32_t* a, const uint32_t* b) {
    asm volatile(
        "mma.sync.aligned.m16n8k16.row.col.f32.f16.f16.f32 "
        "{%0,%1,%2,%3}, {%4,%5,%6,%7}, {%8,%9}, {%0,%1,%2,%3};"
        : "+f"(d[0]), "+f"(d[1]), "+f"(d[2]), "+f"(d[3])
        : "r"(a[0]), "r"(a[1]), "r"(a[2]), "r"(a[3]), "r"(b[0]), "r"(b[1]));
}
__device__ __forceinline__ uint32_t swz(uint32_t base, uint32_t off) {
    return base + (off ^ ((off >> 3) & 0x70));
}

// ---------------- scratch (device globals) ----------------
__device__ int   g_is64;
__device__ int   g_src[NEDGES];
__device__ int   g_dst[NEDGES];
__device__ int   g_indeg[NNODES];
__device__ int   g_rowptr[NNODES + 1];
__device__ int   g_cursor[NNODES];
__device__ float g_dinv[NNODES];
__device__ __align__(128) int   g_csr_src[NEDGES];
__device__ __align__(128) float g_csr_w[NEDGES];

__device__ __align__(128) __half g_hw16[(size_t)NNODES * DIM];  // conv messages (fp16)
__device__ __align__(128) float g_r1[(size_t)NNODES * DIM];
__device__ __align__(128) float g_r2[(size_t)NNODES * HID2D];

// fp16 activations (rows padded to 128 multiples)
__device__ __align__(128) __half g_xgo[(size_t)MPAD_GO * GOIDD];
__device__ __align__(128) __half g_go1[(size_t)MPAD_GO * 1024];
__device__ __align__(128) __half g_xt [(size_t)MPAD_N * DIM];
__device__ __align__(128) __half g_h1 [(size_t)MPAD_N * DIM];

// fp16 transposed weights ([N,K] K-major); _l only used where NPROD=2
__device__ __align__(128) __half g_Wgo1T_h[1024 * 4096];
__device__ __align__(128) __half g_Wgo2T_h[512 * 1024];
__device__ __align__(128) __half g_Wgo2T_l[512 * 1024];
__device__ __align__(128) __half g_W1T_h[1024 * 512];   // [Wc1T ; Wr1T]
__device__ __align__(128) __half g_W2T_h[512 * 512];    // [Wc2T ; Wr2T]
__device__ __align__(128) __half g_W2T_l[512 * 512];

// ---------------- graph preprocessing ----------------
__global__ void k_init_indeg() {
    int i = blockIdx.x * blockDim.x + threadIdx.x;
    if (i < NNODES) g_indeg[i] = 0;
}
__global__ void k_detect_idx_dtype(const int* __restrict__ raw) {
    __shared__ int flag;
    if (threadIdx.x == 0) flag = 1;
    __syncthreads();
    if (raw[2 * threadIdx.x + 1] != 0) flag = 0;
    __syncthreads();
    if (threadIdx.x == 0) g_is64 = flag;
}
__global__ void k_convert_edges(const int* __restrict__ raw) {
    int e = blockIdx.x * blockDim.x + threadIdx.x;
    if (e >= NEDGES) return;
    int s, d;
    if (g_is64) {
        const long long* r64 = (const long long*)raw;
        s = (int)r64[e]; d = (int)r64[NEDGES + e];
    } else {
        s = raw[e]; d = raw[NEDGES + e];
    }
    g_src[e] = s; g_dst[e] = d;
    atomicAdd(&g_indeg[d], 1);
}
__global__ void k_dinv() {
    int i = blockIdx.x * blockDim.x + threadIdx.x;
    if (i < NNODES) g_dinv[i] = rsqrtf(1.0f + (float)g_indeg[i]);
}
__global__ void k_scan() {
    __shared__ int sh[1024];
    __shared__ int carry;
    if (threadIdx.x == 0) carry = 0;
    __syncthreads();
    for (int base = 0; base < NNODES; base += 1024) {
        int i = base + (int)threadIdx.x;
        int v = (i < NNODES) ? g_indeg[i] : 0;
        sh[threadIdx.x] = v;
        __syncthreads();
        for (int off = 1; off < 1024; off <<= 1) {
            int t = (threadIdx.x >= (unsigned)off) ? sh[threadIdx.x - off] : 0;
            __syncthreads();
            sh[threadIdx.x] += t;
            __syncthreads();
        }
        int excl = sh[threadIdx.x] - v + carry;
        if (i < NNODES) { g_rowptr[i] = excl; g_cursor[i] = excl; }
        __syncthreads();
        if (threadIdx.x == 1023) carry += sh[1023];
        __syncthreads();
    }
    if (threadIdx.x == 0) g_rowptr[NNODES] = carry;
}
__global__ void k_fill_csr() {
    int e = blockIdx.x * blockDim.x + threadIdx.x;
    if (e >= NEDGES) return;
    int s = g_src[e], d = g_dst[e];
    int p = atomicAdd(&g_cursor[d], 1);
    g_csr_src[p] = s;
    g_csr_w[p]   = g_dinv[s] * g_dinv[d];
}

// ---------------- conversion kernels ----------------
__global__ void k_cvt_xgo(const float* __restrict__ x) {
    size_t i = (size_t)blockIdx.x * blockDim.x + threadIdx.x;  // half2 unit
    const size_t total = (size_t)MPAD_GO * GOIDD / 2;
    if (i >= total) return;
    size_t row = i / (GOIDD / 2), c2 = i % (GOIDD / 2);
    float2 v = make_float2(0.f, 0.f);
    if (row < NGO) v = ((const float2*)x)[((size_t)(NGENE + row) * GOIDD) / 2 + c2];
    ((__half2*)g_xgo)[i] = __floats2half2_rn(v.x, v.y);
}
__global__ void k_cvt_gene(const float* __restrict__ x) {
    size_t i = (size_t)blockIdx.x * blockDim.x + threadIdx.x;  // half2 unit
    const size_t total = (size_t)NGENE * DIM / 2;
    if (i >= total) return;
    size_t row = i / (DIM / 2), c2 = i % (DIM / 2);
    float2 v = ((const float2*)x)[((size_t)row * GOIDD) / 2 + c2];
    ((__half2*)g_xt)[(size_t)row * (DIM / 2) + c2] = __floats2half2_rn(v.x, v.y);
}
// W[K,N] fp32 -> [N,K] fp16 hi (+ optional lo), 32x32 smem-tiled transpose.
template <bool LO>
__global__ void k_split_w16T(const float* __restrict__ W, __half* __restrict__ dh,
                             __half* __restrict__ dl, int K, int N) {
    __shared__ float tile[32][33];
    const int nb = blockIdx.x * 32, kb = blockIdx.y * 32;
    const int tx = threadIdx.x, ty = threadIdx.y;
#pragma unroll
    for (int r = 0; r < 32; r += 8)
        tile[ty + r][tx] = W[(size_t)(kb + ty + r) * N + nb + tx];
    __syncthreads();
#pragma unroll
    for (int r = 0; r < 32; r += 8) {
        float v = tile[tx][ty + r];              // k = kb+tx, n = nb+ty+r
        __half h = __float2half_rn(v);
        dh[(size_t)(nb + ty + r) * K + kb + tx] = h;
        if (LO) {
            __half l = __float2half_rn(v - __half2float(h));
            dl[(size_t)(nb + ty + r) * K + kb + tx] = l;
        }
    }
}
__global__ void k_zero16(__half* p, int n2) {
    int i = blockIdx.x * blockDim.x + threadIdx.x;
    if (i < n2) ((uint32_t*)p)[i] = 0u;
}

// ---------------- fp16 HMMA GEMM (NPROD = 1 or 2 weight products) ----------------
// C[M,N] = A[M,K](fp16) @ (Bh [+ Bl])^T, weights stored [N,K] K-major.
// CTA tile 128x128; NPROD=1: 3-stage pipeline (2 tiles/stage); NPROD=2: 2-stage
// (3 tiles/stage). Both 96 KB smem, 2 CTAs/SM.
// DUAL: cols [0,N/2) -> Ch fp16 (conv messages, no bias); cols [N/2,N) -> Cr
// fp32 (+bias). Strides N/2.
// non-DUAL: all cols -> Ch fp16 (+bias, +relu), stride N.
#define NTILES(NP)  ((NP) + 1)
#define NSTAGE(NP)  ((NP) == 1 ? 3 : 2)
#define GEMM_SMEM(NP) (NSTAGE(NP) * NTILES(NP) * 16384)

template <int NPROD, bool DUAL, bool BIAS, bool RELU>
__global__ __launch_bounds__(256, 2)
void k_hgemm(const __half* __restrict__ A,
             const __half* __restrict__ Bh, const __half* __restrict__ Bl,
             const float* __restrict__ bias,
             __half* __restrict__ Ch, float* __restrict__ Cr,
             int M, int N, int K)
{
    extern __shared__ char smem[];
    const uint32_t sb = smem_u32(smem);
    const int tid  = threadIdx.x;
    const int wid  = tid >> 5;
    const int lane = tid & 31;
    const int wm   = wid >> 1;       // 0..3
    const int wn   = wid & 1;        // 0..1
    const int bm = blockIdx.y * 128, bn = blockIdx.x * 128;

    const uint32_t STAGE = (uint32_t)NTILES(NPROD) * 16384;
    const int NST = NSTAGE(NPROD);

    const int lrow  = tid >> 1;          // 0..127
    const int lhalf = (tid & 1) * 64;    // byte offset within 128B row
    const char* srcA  = (const char*)(A  + (size_t)(bm + lrow) * K) + lhalf;
    const char* srcBh = (const char*)(Bh + (size_t)(bn + lrow) * K) + lhalf;
    const char* srcBl = (NPROD == 2) ? (const char*)(Bl + (size_t)(bn + lrow) * K) + lhalf : nullptr;

    const int NC = K / 64;

    auto load_chunk = [&](int s, int c) {
        const uint32_t kb = (uint32_t)c * 128;
        const uint32_t stg = sb + (uint32_t)s * STAGE;
        const uint32_t lbase = (uint32_t)lrow * 128 + (uint32_t)lhalf;
#pragma unroll
        for (int m = 0; m < NTILES(NPROD); m++) {
            const char* src = (m == 0) ? srcA + kb : (m == 1 ? srcBh + kb : srcBl + kb);
            uint32_t dbase = stg + (uint32_t)m * 16384;
#pragma unroll
            for (int i = 0; i < 4; i++) {
                uint32_t off = lbase + i * 16;
                cp16(swz(dbase, off), src + i * 16);
            }
        }
        CP_COMMIT();
    };

    float acc[64];
#pragma unroll
    for (int i = 0; i < 64; i++) acc[i] = 0.f;

    const uint32_t a_row  = (uint32_t)(wm * 32) + (lane & 15);
    const uint32_t a_ksel = (lane >> 4) << 4;
    const uint32_t b_row  = (uint32_t)(wn * 64) + (lane & 7) + ((lane >> 4) << 3);
    const uint32_t b_ksel = (lane & 8) ? 16u : 0u;

    // prologue: fill NST-1 stages
    load_chunk(0, 0);
    if (NST == 3 && NC > 1) load_chunk(1, 1);

    for (int c = 0; c < NC; c++) {
        if (NST == 3) {
            if (c + 2 < NC) load_chunk((c + 2) % 3, c + 2);
            // chunks pending beyond c: up to 2
            if (c + 2 < NC)      { CP_WAIT(2); }
            else if (c + 1 < NC) { CP_WAIT(1); }
            else                 { CP_WAIT(0); }
        } else {
            if (c + 1 < NC) { load_chunk((c + 1) & 1, c + 1); CP_WAIT(1); }
            else            { CP_WAIT(0); }
        }
        __syncthreads();

        const uint32_t stg = sb + (uint32_t)(c % NST) * STAGE;
        const uint32_t tA  = stg;
        const uint32_t tBh = stg + 16384;
        const uint32_t tBl = stg + 32768;

#pragma unroll
        for (int ks = 0; ks < 4; ks++) {
            const uint32_t kb = (uint32_t)ks * 32;
            uint32_t a[8];
            ldsm4(&a[0], swz(tA, (a_row)      * 128 + kb + a_ksel));
            ldsm4(&a[4], swz(tA, (a_row + 16) * 128 + kb + a_ksel));
#pragma unroll
            for (int p = 0; p < 4; p++) {
                const uint32_t offB = (b_row + p * 16) * 128 + kb + b_ksel;
                uint32_t bh4[4];
                ldsm4(bh4, swz(tBh, offB));
                if (NPROD == 2) {
                    uint32_t bl4[4];
                    ldsm4(bl4, swz(tBl, offB));
#pragma unroll
                    for (int mt = 0; mt < 2; mt++) {
                        float* d0 = &acc[(mt * 8 + 2 * p) * 4];
                        float* d1 = &acc[(mt * 8 + 2 * p + 1) * 4];
                        mma16816(d0, &a[mt * 4], &bh4[0]);
                        mma16816(d0, &a[mt * 4], &bl4[0]);
                        mma16816(d1, &a[mt * 4], &bh4[2]);
                        mma16816(d1, &a[mt * 4], &bl4[2]);
                    }
                } else {
#pragma unroll
                    for (int mt = 0; mt < 2; mt++) {
                        float* d0 = &acc[(mt * 8 + 2 * p) * 4];
                        float* d1 = &acc[(mt * 8 + 2 * p + 1) * 4];
                        mma16816(d0, &a[mt * 4], &bh4[0]);
                        mma16816(d1, &a[mt * 4], &bh4[2]);
                    }
                }
            }
        }
        __syncthreads();
    }

    // ---- epilogue ----
    const int half  = N >> 1;
    const bool sec  = DUAL && (bn >= half);
    const int cbase = sec ? half : 0;
    const int cstr  = DUAL ? half : N;

#pragma unroll
    for (int mt = 0; mt < 2; mt++) {
#pragma unroll
        for (int nt = 0; nt < 8; nt++) {
            const float* d = &acc[(mt * 8 + nt) * 4];
            const int r0 = bm + wm * 32 + mt * 16 + (lane >> 2);
            const int r1 = r0 + 8;
            const int col = bn + wn * 64 + nt * 8 + 2 * (lane & 3);
            float2 v0 = make_float2(d[0], d[1]);
            float2 v1 = make_float2(d[2], d[3]);
            if (DUAL) {
                const int cc = col - cbase;
                if (sec) {
                    if (BIAS) {
                        float b0 = bias[cc], b1 = bias[cc + 1];
                        v0.x += b0; v0.y += b1; v1.x += b0; v1.y += b1;
                    }
                    if (r0 < M) *(float2*)(Cr + (size_t)r0 * cstr + cc) = v0;
                    if (r1 < M) *(float2*)(Cr + (size_t)r1 * cstr + cc) = v1;
                } else {
                    if (r0 < M) *(__half2*)(Ch + (size_t)r0 * cstr + cc) = __floats2half2_rn(v0.x, v0.y);
                    if (r1 < M) *(__half2*)(Ch + (size_t)r1 * cstr + cc) = __floats2half2_rn(v1.x, v1.y);
                }
            } else {
                if (BIAS) {
                    float b0 = bias[col], b1 = bias[col + 1];
                    v0.x += b0; v0.y += b1; v1.x += b0; v1.y += b1;
                }
                if (RELU) {
                    v0.x = fmaxf(v0.x, 0.f); v0.y = fmaxf(v0.y, 0.f);
                    v1.x = fmaxf(v1.x, 0.f); v1.y = fmaxf(v1.y, 0.f);
                }
                if (r0 < M) *(__half2*)(Ch + (size_t)r0 * N + col) = __floats2half2_rn(v0.x, v0.y);
                if (r1 < M) *(__half2*)(Ch + (size_t)r1 * N + col) = __floats2half2_rn(v1.x, v1.y);
            }
        }
    }
}

// ---------------- GCN aggregate + epilogue (CSR gather, fp16 messages) --------
// o[i] = relu( sum_e w_e*hw[src_e] + dinv[i]^2*hw[i] + bias ) + r[i]
// hw rows are fp16 (F halves). Each thread handles 4 features (8 bytes/row).
template <int F, bool H16OUT>
__global__ void k_gather_epi(const __half* __restrict__ hw, float* __restrict__ rio,
                             const float* __restrict__ bias, __half* __restrict__ oh)
{
    int i = blockIdx.x;
    int t = threadIdx.x;        // blockDim == F/4
    int beg = g_rowptr[i], end = g_rowptr[i + 1];
    float4 acc = make_float4(0.f, 0.f, 0.f, 0.f);
    if (beg < end) {
        int s = g_csr_src[beg];
        float w = g_csr_w[beg];
        for (int e = beg; e < end; e++) {
            int s2 = 0; float w2 = 0.f;
            if (e + 1 < end) { s2 = g_csr_src[e + 1]; w2 = g_csr_w[e + 1]; }
            uint2 raw = *(const uint2*)(hw + (size_t)s * F + 4 * t);
            float2 f0 = __half22float2(*(const __half2*)&raw.x);
            float2 f1 = __half22float2(*(const __half2*)&raw.y);
            acc.x += w * f0.x; acc.y += w * f0.y;
            acc.z += w * f1.x; acc.w += w * f1.y;
            s = s2; w = w2;
        }
    }
    float dv = g_dinv[i];
    float sn = dv * dv;
    uint2 rawS = *(const uint2*)(hw + (size_t)i * F + 4 * t);
    float2 s0 = __half22float2(*(const __half2*)&rawS.x);
    float2 s1 = __half22float2(*(const __half2*)&rawS.y);
    float4 bb = ((const float4*)bias)[t];
    float4 r  = ((const float4*)rio)[(size_t)i * (F / 4) + t];
    float4 o;
    o.x = fmaxf(acc.x + sn * s0.x + bb.x, 0.f) + r.x;
    o.y = fmaxf(acc.y + sn * s0.y + bb.y, 0.f) + r.y;
    o.z = fmaxf(acc.z + sn * s1.x + bb.z, 0.f) + r.z;
    o.w = fmaxf(acc.w + sn * s1.y + bb.w, 0.f) + r.w;
    if (H16OUT) {
        __half2* ph = (__half2*)(oh + (size_t)i * F + t * 4);
        ph[0] = __floats2half2_rn(o.x, o.y);
        ph[1] = __floats2half2_rn(o.z, o.w);
    } else {
        ((float4*)rio)[(size_t)i * (F / 4) + t] = o;
    }
}

// ---------------- final fusion ----------------
__global__ void k_fusion(const float* __restrict__ h2, const float* __restrict__ istj,
                         const float* __restrict__ Wf, const float* __restrict__ bf,
                         float* __restrict__ out)
{
    int gwarp = (blockIdx.x * blockDim.x + threadIdx.x) >> 5;
    int lane = threadIdx.x & 31;
    if (gwarp >= NGENE) return;
    const float* h = h2 + (size_t)gwarp * HID2D;
    float a0 = 0.f, a1 = 0.f;
#pragma unroll
    for (int k = lane; k < HID2D; k += 32) {
        float v = h[k];
        a0 += v * Wf[2 * k];
        a1 += v * Wf[2 * k + 1];
    }
#pragma unroll
    for (int off = 16; off > 0; off >>= 1) {
        a0 += __shfl_down_sync(0xffffffffu, a0, off);
        a1 += __shfl_down_sync(0xffffffffu, a1, off);
    }
    if (lane == 0) {
        float t = istj[gwarp];
        out[2 * gwarp + 0] = a0 + t * Wf[2 * HID2D + 0] + bf[0];
        out[2 * gwarp + 1] = a1 + t * Wf[2 * HID2D + 1] + bf[1];
    }
}

// ---------------- host ----------------
template <typename T>
static inline T* sym(const void* s) {
    void* p = nullptr;
    cudaGetSymbolAddress(&p, s);
    return (T*)p;
}

extern "C" void kernel_launch(void* const* d_in, const int* in_sizes, int n_in,
                              void* d_out, int out_size)
{
    const float* x    = (const float*)d_in[0];
    const int*   eraw = (const int*)  d_in[1];
    const float* istj = (const float*)d_in[2];
    const int base = (in_sizes[3] < 1000) ? 4 : 3;
    const float* W_go1 = (const float*)d_in[base + 0];
    const float* b_go1 = (const float*)d_in[base + 1];
    const float* W_go2 = (const float*)d_in[base + 2];
    const float* b_go2 = (const float*)d_in[base + 3];
    const float* W_c1  = (const float*)d_in[base + 4];
    const float* b_c1  = (const float*)d_in[base + 5];
    const float* W_c2  = (const float*)d_in[base + 6];
    const float* b_c2  = (const float*)d_in[base + 7];
    const float* W_r1  = (const float*)d_in[base + 8];
    const float* b_r1  = (const float*)d_in[base + 9];
    const float* W_r2  = (const float*)d_in[base + 10];
    const float* b_r2  = (const float*)d_in[base + 11];
    const float* W_f   = (const float*)d_in[base + 12];
    const float* b_f   = (const float*)d_in[base + 13];
    float* out = (float*)d_out;

    cudaFuncSetAttribute((const void*)k_hgemm<1, false, true,  true >,
                         cudaFuncAttributeMaxDynamicSharedMemorySize, GEMM_SMEM(1));
    cudaFuncSetAttribute((const void*)k_hgemm<2, false, true,  true >,
                         cudaFuncAttributeMaxDynamicSharedMemorySize, GEMM_SMEM(2));
    cudaFuncSetAttribute((const void*)k_hgemm<1, true,  true,  false>,
                         cudaFuncAttributeMaxDynamicSharedMemorySize, GEMM_SMEM(1));
    cudaFuncSetAttribute((const void*)k_hgemm<2, true,  true,  false>,
                         cudaFuncAttributeMaxDynamicSharedMemorySize, GEMM_SMEM(2));

    __half* hw16 = sym<__half>(g_hw16);
    float* p_r1 = sym<float>(g_r1);
    float* p_r2 = sym<float>(g_r2);
    __half* xgo  = sym<__half>(g_xgo);
    __half* go1  = sym<__half>(g_go1);
    __half* xt   = sym<__half>(g_xt);
    __half* h1   = sym<__half>(g_h1);
    __half* wgo1h = sym<__half>(g_Wgo1T_h);
    __half* wgo2h = sym<__half>(g_Wgo2T_h); __half* wgo2l = sym<__half>(g_Wgo2T_l);
    __half* w1h   = sym<__half>(g_W1T_h);
    __half* w2h   = sym<__half>(g_W2T_h);   __half* w2l   = sym<__half>(g_W2T_l);

    // --- graph preprocessing ---
    k_init_indeg<<<(NNODES + 255) / 256, 256>>>();
    k_detect_idx_dtype<<<1, 1024>>>(eraw);
    k_convert_edges<<<(NEDGES + 255) / 256, 256>>>(eraw);
    k_dinv<<<(NNODES + 255) / 256, 256>>>();
    k_scan<<<1, 1024>>>();
    k_fill_csr<<<(NEDGES + 255) / 256, 256>>>();

    // --- conversions ---
    {
        size_t n2 = (size_t)MPAD_GO * GOIDD / 2;
        k_cvt_xgo<<<(unsigned)((n2 + 255) / 256), 256>>>(x);
    }
    k_cvt_gene<<<(unsigned)(((size_t)NGENE * DIM / 2 + 255) / 256), 256>>>(x);
    {
        dim3 b(32, 8);
        k_split_w16T<false><<<dim3(1024 / 32, 4096 / 32), b>>>(W_go1, wgo1h, nullptr, 4096, 1024);
        k_split_w16T<true ><<<dim3(512 / 32, 1024 / 32),  b>>>(W_go2, wgo2h, wgo2l, 1024, 512);
        k_split_w16T<false><<<dim3(512 / 32, 512 / 32),   b>>>(W_c1, w1h,             nullptr, 512, 512);
        k_split_w16T<false><<<dim3(512 / 32, 512 / 32),   b>>>(W_r1, w1h + 512 * 512, nullptr, 512, 512);
        k_split_w16T<true ><<<dim3(256 / 32, 512 / 32),   b>>>(W_c2, w2h,             w2l,             512, 256);
        k_split_w16T<true ><<<dim3(256 / 32, 512 / 32),   b>>>(W_r2, w2h + 256 * 512, w2l + 256 * 512, 512, 256);
    }
    // zero padded A rows
    k_zero16<<<(112 * 1024 / 2 + 255) / 256, 256>>>(go1 + (size_t)NGO * 1024, 112 * 1024 / 2);
    k_zero16<<<(48 * 512 / 2 + 255) / 256, 256>>>(xt + (size_t)NNODES * DIM, 48 * 512 / 2);
    k_zero16<<<(48 * 512 / 2 + 255) / 256, 256>>>(h1 + (size_t)NNODES * DIM, 48 * 512 / 2);

    // --- goid MLP ---
    {
        dim3 g(1024 / 128, MPAD_GO / 128);
        k_hgemm<1, false, true, true><<<g, 256, GEMM_SMEM(1)>>>(
            xgo, wgo1h, nullptr, b_go1, go1, nullptr, NGO, 1024, 4096);
    }
    {
        dim3 g(512 / 128, MPAD_GO / 128);
        k_hgemm<2, false, true, true><<<g, 256, GEMM_SMEM(2)>>>(
            go1, wgo2h, wgo2l, b_go2, xt + (size_t)NGENE * DIM, nullptr, NGO, 512, 1024);
    }

    // --- layer 1: dual GEMM (hw fp16 | r1 fp32), gather -> h1 fp16 ---
    {
        dim3 g(1024 / 128, MPAD_N / 128);
        k_hgemm<1, true, true, false><<<g, 256, GEMM_SMEM(1)>>>(
            xt, w1h, nullptr, b_r1, hw16, p_r1, NNODES, 1024, 512);
    }
    k_gather_epi<DIM, true><<<NNODES, DIM / 4>>>(hw16, p_r1, b_c1, h1);

    // --- layer 2: dual GEMM (hw fp16 | r2 fp32), gather -> h2 fp32 (in r2) ---
    {
        dim3 g(512 / 128, MPAD_N / 128);
        k_hgemm<2, true, true, false><<<g, 256, GEMM_SMEM(2)>>>(
            h1, w2h, w2l, b_r2, hw16, p_r2, NNODES, 512, 512);
    }
    k_gather_epi<HID2D, false><<<NNODES, HID2D / 4>>>(hw16, p_r2, b_c2, nullptr);

    // --- fusion head ---
    k_fusion<<<(NGENE * 32 + 255) / 256, 256>>>(p_r2, istj, W_f, b_f, out);

    (void)n_in; (void)out_size;
}

// round 9
// speedup vs baseline: 5.1256x; 1.1739x over previous
#include <cuda_runtime.h>
#include <cuda_fp16.h>
#include <cstdint>

// ---------------- problem constants ----------------
#define NNODES 50000
#define NGENE  40000
#define NGO    10000
#define NEDGES 800000
#define DIM    512
#define HID2D  256
#define GOIDD  4096
#define MPAD_GO 10112   // 79*128
#define MPAD_N  50048   // 391*128
#define NSCANB 196      // ceil(50000/256)

// ---------------- helpers ----------------
__device__ __forceinline__ uint32_t smem_u32(const void* p) {
    uint32_t a;
    asm("{ .reg .u64 t; cvta.to.shared.u64 t, %1; cvt.u32.u64 %0, t; }" : "=r"(a) : "l"(p));
    return a;
}
__device__ __forceinline__ void cp16(uint32_t d, const void* s) {
    asm volatile("cp.async.cg.shared.global [%0], [%1], 16;" :: "r"(d), "l"(s) : "memory");
}
#define CP_COMMIT() asm volatile("cp.async.commit_group;" ::: "memory")
#define CP_WAIT(n)  asm volatile("cp.async.wait_group %0;" :: "n"(n) : "memory")

__device__ __forceinline__ void ldsm4(uint32_t* r, uint32_t addr) {
    asm volatile("ldmatrix.sync.aligned.m8n8.x4.shared.b16 {%0,%1,%2,%3}, [%4];"
        : "=r"(r[0]), "=r"(r[1]), "=r"(r[2]), "=r"(r[3]) : "r"(addr));
}
__device__ __forceinline__ void mma16816(float* d, const uint32_t* a, const uint32_t* b) {
    asm volatile(
        "mma.sync.aligned.m16n8k16.row.col.f32.f16.f16.f32 "
        "{%0,%1,%2,%3}, {%4,%5,%6,%7}, {%8,%9}, {%0,%1,%2,%3};"
        : "+f"(d[0]), "+f"(d[1]), "+f"(d[2]), "+f"(d[3])
        : "r"(a[0]), "r"(a[1]), "r"(a[2]), "r"(a[3]), "r"(b[0]), "r"(b[1]));
}
__device__ __forceinline__ uint32_t swz(uint32_t base, uint32_t off) {
    return base + (off ^ ((off >> 3) & 0x70));
}

// ---------------- scratch (device globals) ----------------
__device__ int   g_is64;
__device__ int   g_src[NEDGES];
__device__ int   g_dst[NEDGES];
__device__ int   g_indeg[NNODES];
__device__ int   g_rowptr[NNODES + 1];
__device__ int   g_cursor[NNODES];
__device__ int   g_bsum[256];
__device__ float g_dinv[NNODES];
__device__ __align__(128) int   g_csr_src[NEDGES];
__device__ __align__(128) float g_csr_w[NEDGES];

__device__ __align__(128) __half g_hw16[(size_t)NNODES * DIM];  // conv messages (fp16)
__device__ __align__(128) float g_r1[(size_t)NNODES * DIM];
__device__ __align__(128) float g_r2[(size_t)NNODES * HID2D];

// fp16 activations (rows padded to 128 multiples)
__device__ __align__(128) __half g_xgo[(size_t)MPAD_GO * GOIDD];
__device__ __align__(128) __half g_go1[(size_t)MPAD_GO * 1024];
__device__ __align__(128) __half g_xt [(size_t)MPAD_N * DIM];
__device__ __align__(128) __half g_h1 [(size_t)MPAD_N * DIM];

// fp16 transposed weights ([N,K] K-major), single product everywhere
__device__ __align__(128) __half g_Wgo1T[1024 * 4096];
__device__ __align__(128) __half g_Wgo2T[512 * 1024];
__device__ __align__(128) __half g_W1T[1024 * 512];   // [Wc1T ; Wr1T]
__device__ __align__(128) __half g_W2T[512 * 512];    // [Wc2T ; Wr2T]

// ---------------- graph preprocessing ----------------
__global__ void k_init_indeg() {
    int i = blockIdx.x * blockDim.x + threadIdx.x;
    if (i < NNODES) g_indeg[i] = 0;
}
__global__ void k_detect_idx_dtype(const int* __restrict__ raw) {
    __shared__ int flag;
    if (threadIdx.x == 0) flag = 1;
    __syncthreads();
    if (raw[2 * threadIdx.x + 1] != 0) flag = 0;
    __syncthreads();
    if (threadIdx.x == 0) g_is64 = flag;
}
__global__ void k_convert_edges(const int* __restrict__ raw) {
    int e = blockIdx.x * blockDim.x + threadIdx.x;
    if (e >= NEDGES) return;
    int s, d;
    if (g_is64) {
        const long long* r64 = (const long long*)raw;
        s = (int)r64[e]; d = (int)r64[NEDGES + e];
    } else {
        s = raw[e]; d = raw[NEDGES + e];
    }
    g_src[e] = s; g_dst[e] = d;
    atomicAdd(&g_indeg[d], 1);
}
__global__ void k_dinv() {
    int i = blockIdx.x * blockDim.x + threadIdx.x;
    if (i < NNODES) g_dinv[i] = rsqrtf(1.0f + (float)g_indeg[i]);
}
// 3-phase parallel exclusive scan of indeg -> rowptr (+cursor)
__global__ void k_scan1() {   // grid NSCANB, block 256: local exclusive scans
    __shared__ int sh[256];
    const int b = blockIdx.x, t = threadIdx.x;
    const int i = b * 256 + t;
    int v = (i < NNODES) ? g_indeg[i] : 0;
    sh[t] = v;
    __syncthreads();
#pragma unroll
    for (int off = 1; off < 256; off <<= 1) {
        int x = (t >= off) ? sh[t - off] : 0;
        __syncthreads();
        sh[t] += x;
        __syncthreads();
    }
    if (i < NNODES) g_rowptr[i] = sh[t] - v;   // local exclusive
    if (t == 255) g_bsum[b] = sh[255];
}
__global__ void k_scan2() {   // 1 block, 256 threads: scan block sums
    __shared__ int sh[256];
    const int t = threadIdx.x;
    int v = (t < NSCANB) ? g_bsum[t] : 0;
    sh[t] = v;
    __syncthreads();
#pragma unroll
    for (int off = 1; off < 256; off <<= 1) {
        int x = (t >= off) ? sh[t - off] : 0;
        __syncthreads();
        sh[t] += x;
        __syncthreads();
    }
    if (t < NSCANB) g_bsum[t] = sh[t] - v;     // exclusive block offsets
    if (t == 255) g_rowptr[NNODES] = sh[255];
}
__global__ void k_scan3() {   // grid NSCANB, block 256: add offsets
    const int b = blockIdx.x, t = threadIdx.x;
    const int i = b * 256 + t;
    if (i < NNODES) {
        int r = g_rowptr[i] + g_bsum[b];
        g_rowptr[i] = r;
        g_cursor[i] = r;
    }
}
__global__ void k_fill_csr() {
    int e = blockIdx.x * blockDim.x + threadIdx.x;
    if (e >= NEDGES) return;
    int s = g_src[e], d = g_dst[e];
    int p = atomicAdd(&g_cursor[d], 1);
    g_csr_src[p] = s;
    g_csr_w[p]   = g_dinv[s] * g_dinv[d];
}

// ---------------- conversion kernels ----------------
__global__ void k_cvt_xgo(const float* __restrict__ x) {
    size_t i = (size_t)blockIdx.x * blockDim.x + threadIdx.x;  // half2 unit
    const size_t total = (size_t)MPAD_GO * GOIDD / 2;
    if (i >= total) return;
    size_t row = i / (GOIDD / 2), c2 = i % (GOIDD / 2);
    float2 v = make_float2(0.f, 0.f);
    if (row < NGO) v = ((const float2*)x)[((size_t)(NGENE + row) * GOIDD) / 2 + c2];
    ((__half2*)g_xgo)[i] = __floats2half2_rn(v.x, v.y);
}
__global__ void k_cvt_gene(const float* __restrict__ x) {
    size_t i = (size_t)blockIdx.x * blockDim.x + threadIdx.x;  // half2 unit
    const size_t total = (size_t)NGENE * DIM / 2;
    if (i >= total) return;
    size_t row = i / (DIM / 2), c2 = i % (DIM / 2);
    float2 v = ((const float2*)x)[((size_t)row * GOIDD) / 2 + c2];
    ((__half2*)g_xt)[(size_t)row * (DIM / 2) + c2] = __floats2half2_rn(v.x, v.y);
}
// W[K,N] fp32 -> [N,K] fp16, 32x32 smem-tiled transpose (coalesced).
__global__ void k_cvt_wT(const float* __restrict__ W, __half* __restrict__ dh,
                         int K, int N) {
    __shared__ float tile[32][33];
    const int nb = blockIdx.x * 32, kb = blockIdx.y * 32;
    const int tx = threadIdx.x, ty = threadIdx.y;
#pragma unroll
    for (int r = 0; r < 32; r += 8)
        tile[ty + r][tx] = W[(size_t)(kb + ty + r) * N + nb + tx];
    __syncthreads();
#pragma unroll
    for (int r = 0; r < 32; r += 8) {
        float v = tile[tx][ty + r];              // k = kb+tx, n = nb+ty+r
        dh[(size_t)(nb + ty + r) * K + kb + tx] = __float2half_rn(v);
    }
}
__global__ void k_zero16(__half* p, int n2) {
    int i = blockIdx.x * blockDim.x + threadIdx.x;
    if (i < n2) ((uint32_t*)p)[i] = 0u;
}

// ---------------- fp16 HMMA GEMM (single weight product) ----------------
// C[M,N] = A[M,K](fp16) @ B^T (fp16 weights, stored [N,K] K-major).
// CTA tile 128x128, 3-stage cp.async pipeline (2 tiles/stage, 96 KB), 2 CTAs/SM.
// DUAL: cols [0,N/2) -> Ch fp16 (conv messages, no bias); cols [N/2,N) -> Cr
// fp32 (+bias). Strides N/2.
// non-DUAL: all cols -> Ch fp16 (+bias, +relu), stride N.
#define GEMM_SMEM (3 * 2 * 16384)   // 96 KB

template <bool DUAL, bool BIAS, bool RELU>
__global__ __launch_bounds__(256, 2)
void k_hgemm(const __half* __restrict__ A, const __half* __restrict__ B,
             const float* __restrict__ bias,
             __half* __restrict__ Ch, float* __restrict__ Cr,
             int M, int N, int K)
{
    extern __shared__ char smem[];
    const uint32_t sb = smem_u32(smem);
    const int tid  = threadIdx.x;
    const int wid  = tid >> 5;
    const int lane = tid & 31;
    const int wm   = wid >> 1;       // 0..3
    const int wn   = wid & 1;        // 0..1
    const int bm = blockIdx.y * 128, bn = blockIdx.x * 128;

    const uint32_t STAGE = 2 * 16384;

    const int lrow  = tid >> 1;          // 0..127
    const int lhalf = (tid & 1) * 64;    // byte offset within 128B row
    const char* srcA = (const char*)(A + (size_t)(bm + lrow) * K) + lhalf;
    const char* srcB = (const char*)(B + (size_t)(bn + lrow) * K) + lhalf;

    const int NC = K / 64;

    auto load_chunk = [&](int s, int c) {
        const uint32_t kb = (uint32_t)c * 128;
        const uint32_t stg = sb + (uint32_t)s * STAGE;
        const uint32_t lbase = (uint32_t)lrow * 128 + (uint32_t)lhalf;
#pragma unroll
        for (int i = 0; i < 4; i++) {
            uint32_t off = lbase + i * 16;
            cp16(swz(stg, off),         srcA + kb + i * 16);
            cp16(swz(stg + 16384, off), srcB + kb + i * 16);
        }
        CP_COMMIT();
    };

    float acc[64];
#pragma unroll
    for (int i = 0; i < 64; i++) acc[i] = 0.f;

    const uint32_t a_row  = (uint32_t)(wm * 32) + (lane & 15);
    const uint32_t a_ksel = (lane >> 4) << 4;
    const uint32_t b_row  = (uint32_t)(wn * 64) + (lane & 7) + ((lane >> 4) << 3);
    const uint32_t b_ksel = (lane & 8) ? 16u : 0u;

    load_chunk(0, 0);
    if (NC > 1) load_chunk(1, 1);

    for (int c = 0; c < NC; c++) {
        if (c + 2 < NC) load_chunk((c + 2) % 3, c + 2);
        if (c + 2 < NC)      { CP_WAIT(2); }
        else if (c + 1 < NC) { CP_WAIT(1); }
        else                 { CP_WAIT(0); }
        __syncthreads();

        const uint32_t stg = sb + (uint32_t)(c % 3) * STAGE;
        const uint32_t tA = stg;
        const uint32_t tB = stg + 16384;

#pragma unroll
        for (int ks = 0; ks < 4; ks++) {
            const uint32_t kb = (uint32_t)ks * 32;
            uint32_t a[8];
            ldsm4(&a[0], swz(tA, (a_row)      * 128 + kb + a_ksel));
            ldsm4(&a[4], swz(tA, (a_row + 16) * 128 + kb + a_ksel));
#pragma unroll
            for (int p = 0; p < 4; p++) {
                uint32_t b4[4];
                ldsm4(b4, swz(tB, (b_row + p * 16) * 128 + kb + b_ksel));
#pragma unroll
                for (int mt = 0; mt < 2; mt++) {
                    mma16816(&acc[(mt * 8 + 2 * p) * 4],     &a[mt * 4], &b4[0]);
                    mma16816(&acc[(mt * 8 + 2 * p + 1) * 4], &a[mt * 4], &b4[2]);
                }
            }
        }
        __syncthreads();
    }

    // ---- epilogue ----
    const int half  = N >> 1;
    const bool sec  = DUAL && (bn >= half);
    const int cbase = sec ? half : 0;
    const int cstr  = DUAL ? half : N;

#pragma unroll
    for (int mt = 0; mt < 2; mt++) {
#pragma unroll
        for (int nt = 0; nt < 8; nt++) {
            const float* d = &acc[(mt * 8 + nt) * 4];
            const int r0 = bm + wm * 32 + mt * 16 + (lane >> 2);
            const int r1 = r0 + 8;
            const int col = bn + wn * 64 + nt * 8 + 2 * (lane & 3);
            float2 v0 = make_float2(d[0], d[1]);
            float2 v1 = make_float2(d[2], d[3]);
            if (DUAL) {
                const int cc = col - cbase;
                if (sec) {
                    if (BIAS) {
                        float b0 = bias[cc], b1 = bias[cc + 1];
                        v0.x += b0; v0.y += b1; v1.x += b0; v1.y += b1;
                    }
                    if (r0 < M) *(float2*)(Cr + (size_t)r0 * cstr + cc) = v0;
                    if (r1 < M) *(float2*)(Cr + (size_t)r1 * cstr + cc) = v1;
                } else {
                    if (r0 < M) *(__half2*)(Ch + (size_t)r0 * cstr + cc) = __floats2half2_rn(v0.x, v0.y);
                    if (r1 < M) *(__half2*)(Ch + (size_t)r1 * cstr + cc) = __floats2half2_rn(v1.x, v1.y);
                }
            } else {
                if (BIAS) {
                    float b0 = bias[col], b1 = bias[col + 1];
                    v0.x += b0; v0.y += b1; v1.x += b0; v1.y += b1;
                }
                if (RELU) {
                    v0.x = fmaxf(v0.x, 0.f); v0.y = fmaxf(v0.y, 0.f);
                    v1.x = fmaxf(v1.x, 0.f); v1.y = fmaxf(v1.y, 0.f);
                }
                if (r0 < M) *(__half2*)(Ch + (size_t)r0 * N + col) = __floats2half2_rn(v0.x, v0.y);
                if (r1 < M) *(__half2*)(Ch + (size_t)r1 * N + col) = __floats2half2_rn(v1.x, v1.y);
            }
        }
    }
}

// ---------------- GCN aggregate + epilogue (CSR gather, fp16 messages) --------
template <int F, bool H16OUT>
__global__ void k_gather_epi(const __half* __restrict__ hw, float* __restrict__ rio,
                             const float* __restrict__ bias, __half* __restrict__ oh)
{
    int i = blockIdx.x;
    int t = threadIdx.x;        // blockDim == F/4
    int beg = g_rowptr[i], end = g_rowptr[i + 1];
    float4 acc = make_float4(0.f, 0.f, 0.f, 0.f);
    if (beg < end) {
        int s = g_csr_src[beg];
        float w = g_csr_w[beg];
        for (int e = beg; e < end; e++) {
            int s2 = 0; float w2 = 0.f;
            if (e + 1 < end) { s2 = g_csr_src[e + 1]; w2 = g_csr_w[e + 1]; }
            uint2 raw = *(const uint2*)(hw + (size_t)s * F + 4 * t);
            float2 f0 = __half22float2(*(const __half2*)&raw.x);
            float2 f1 = __half22float2(*(const __half2*)&raw.y);
            acc.x += w * f0.x; acc.y += w * f0.y;
            acc.z += w * f1.x; acc.w += w * f1.y;
            s = s2; w = w2;
        }
    }
    float dv = g_dinv[i];
    float sn = dv * dv;
    uint2 rawS = *(const uint2*)(hw + (size_t)i * F + 4 * t);
    float2 s0 = __half22float2(*(const __half2*)&rawS.x);
    float2 s1 = __half22float2(*(const __half2*)&rawS.y);
    float4 bb = ((const float4*)bias)[t];
    float4 r  = ((const float4*)rio)[(size_t)i * (F / 4) + t];
    float4 o;
    o.x = fmaxf(acc.x + sn * s0.x + bb.x, 0.f) + r.x;
    o.y = fmaxf(acc.y + sn * s0.y + bb.y, 0.f) + r.y;
    o.z = fmaxf(acc.z + sn * s1.x + bb.z, 0.f) + r.z;
    o.w = fmaxf(acc.w + sn * s1.y + bb.w, 0.f) + r.w;
    if (H16OUT) {
        __half2* ph = (__half2*)(oh + (size_t)i * F + t * 4);
        ph[0] = __floats2half2_rn(o.x, o.y);
        ph[1] = __floats2half2_rn(o.z, o.w);
    } else {
        ((float4*)rio)[(size_t)i * (F / 4) + t] = o;
    }
}

// ---------------- final fusion ----------------
__global__ void k_fusion(const float* __restrict__ h2, const float* __restrict__ istj,
                         const float* __restrict__ Wf, const float* __restrict__ bf,
                         float* __restrict__ out)
{
    int gwarp = (blockIdx.x * blockDim.x + threadIdx.x) >> 5;
    int lane = threadIdx.x & 31;
    if (gwarp >= NGENE) return;
    const float* h = h2 + (size_t)gwarp * HID2D;
    float a0 = 0.f, a1 = 0.f;
#pragma unroll
    for (int k = lane; k < HID2D; k += 32) {
        float v = h[k];
        a0 += v * Wf[2 * k];
        a1 += v * Wf[2 * k + 1];
    }
#pragma unroll
    for (int off = 16; off > 0; off >>= 1) {
        a0 += __shfl_down_sync(0xffffffffu, a0, off);
        a1 += __shfl_down_sync(0xffffffffu, a1, off);
    }
    if (lane == 0) {
        float t = istj[gwarp];
        out[2 * gwarp + 0] = a0 + t * Wf[2 * HID2D + 0] + bf[0];
        out[2 * gwarp + 1] = a1 + t * Wf[2 * HID2D + 1] + bf[1];
    }
}

// ---------------- host ----------------
template <typename T>
static inline T* sym(const void* s) {
    void* p = nullptr;
    cudaGetSymbolAddress(&p, s);
    return (T*)p;
}

extern "C" void kernel_launch(void* const* d_in, const int* in_sizes, int n_in,
                              void* d_out, int out_size)
{
    const float* x    = (const float*)d_in[0];
    const int*   eraw = (const int*)  d_in[1];
    const float* istj = (const float*)d_in[2];
    const int base = (in_sizes[3] < 1000) ? 4 : 3;
    const float* W_go1 = (const float*)d_in[base + 0];
    const float* b_go1 = (const float*)d_in[base + 1];
    const float* W_go2 = (const float*)d_in[base + 2];
    const float* b_go2 = (const float*)d_in[base + 3];
    const float* W_c1  = (const float*)d_in[base + 4];
    const float* b_c1  = (const float*)d_in[base + 5];
    const float* W_c2  = (const float*)d_in[base + 6];
    const float* b_c2  = (const float*)d_in[base + 7];
    const float* W_r1  = (const float*)d_in[base + 8];
    const float* b_r1  = (const float*)d_in[base + 9];
    const float* W_r2  = (const float*)d_in[base + 10];
    const float* b_r2  = (const float*)d_in[base + 11];
    const float* W_f   = (const float*)d_in[base + 12];
    const float* b_f   = (const float*)d_in[base + 13];
    float* out = (float*)d_out;

    cudaFuncSetAttribute((const void*)k_hgemm<false, true, true >,
                         cudaFuncAttributeMaxDynamicSharedMemorySize, GEMM_SMEM);
    cudaFuncSetAttribute((const void*)k_hgemm<true,  true, false>,
                         cudaFuncAttributeMaxDynamicSharedMemorySize, GEMM_SMEM);

    __half* hw16 = sym<__half>(g_hw16);
    float* p_r1 = sym<float>(g_r1);
    float* p_r2 = sym<float>(g_r2);
    __half* xgo  = sym<__half>(g_xgo);
    __half* go1  = sym<__half>(g_go1);
    __half* xt   = sym<__half>(g_xt);
    __half* h1   = sym<__half>(g_h1);
    __half* wgo1 = sym<__half>(g_Wgo1T);
    __half* wgo2 = sym<__half>(g_Wgo2T);
    __half* w1   = sym<__half>(g_W1T);
    __half* w2   = sym<__half>(g_W2T);

    // --- graph preprocessing ---
    k_init_indeg<<<(NNODES + 255) / 256, 256>>>();
    k_detect_idx_dtype<<<1, 1024>>>(eraw);
    k_convert_edges<<<(NEDGES + 255) / 256, 256>>>(eraw);
    k_dinv<<<(NNODES + 255) / 256, 256>>>();
    k_scan1<<<NSCANB, 256>>>();
    k_scan2<<<1, 256>>>();
    k_scan3<<<NSCANB, 256>>>();
    k_fill_csr<<<(NEDGES + 255) / 256, 256>>>();

    // --- conversions ---
    {
        size_t n2 = (size_t)MPAD_GO * GOIDD / 2;
        k_cvt_xgo<<<(unsigned)((n2 + 255) / 256), 256>>>(x);
    }
    k_cvt_gene<<<(unsigned)(((size_t)NGENE * DIM / 2 + 255) / 256), 256>>>(x);
    {
        dim3 b(32, 8);
        k_cvt_wT<<<dim3(1024 / 32, 4096 / 32), b>>>(W_go1, wgo1, 4096, 1024);
        k_cvt_wT<<<dim3(512 / 32, 1024 / 32),  b>>>(W_go2, wgo2, 1024, 512);
        k_cvt_wT<<<dim3(512 / 32, 512 / 32),   b>>>(W_c1, w1,             512, 512);
        k_cvt_wT<<<dim3(512 / 32, 512 / 32),   b>>>(W_r1, w1 + 512 * 512, 512, 512);
        k_cvt_wT<<<dim3(256 / 32, 512 / 32),   b>>>(W_c2, w2,             512, 256);
        k_cvt_wT<<<dim3(256 / 32, 512 / 32),   b>>>(W_r2, w2 + 256 * 512, 512, 256);
    }
    // zero padded A rows
    k_zero16<<<(112 * 1024 / 2 + 255) / 256, 256>>>(go1 + (size_t)NGO * 1024, 112 * 1024 / 2);
    k_zero16<<<(48 * 512 / 2 + 255) / 256, 256>>>(xt + (size_t)NNODES * DIM, 48 * 512 / 2);
    k_zero16<<<(48 * 512 / 2 + 255) / 256, 256>>>(h1 + (size_t)NNODES * DIM, 48 * 512 / 2);

    // --- goid MLP ---
    {
        dim3 g(1024 / 128, MPAD_GO / 128);
        k_hgemm<false, true, true><<<g, 256, GEMM_SMEM>>>(
            xgo, wgo1, b_go1, go1, nullptr, NGO, 1024, 4096);
    }
    {
        dim3 g(512 / 128, MPAD_GO / 128);
        k_hgemm<false, true, true><<<g, 256, GEMM_SMEM>>>(
            go1, wgo2, b_go2, xt + (size_t)NGENE * DIM, nullptr, NGO, 512, 1024);
    }

    // --- layer 1: dual GEMM (hw fp16 | r1 fp32), gather -> h1 fp16 ---
    {
        dim3 g(1024 / 128, MPAD_N / 128);
        k_hgemm<true, true, false><<<g, 256, GEMM_SMEM>>>(
            xt, w1, b_r1, hw16, p_r1, NNODES, 1024, 512);
    }
    k_gather_epi<DIM, true><<<NNODES, DIM / 4>>>(hw16, p_r1, b_c1, h1);

    // --- layer 2: dual GEMM (hw fp16 | r2 fp32), gather -> h2 fp32 (in r2) ---
    {
        dim3 g(512 / 128, MPAD_N / 128);
        k_hgemm<true, true, false><<<g, 256, GEMM_SMEM>>>(
            h1, w2, b_r2, hw16, p_r2, NNODES, 512, 512);
    }
    k_gather_epi<HID2D, false><<<NNODES, HID2D / 4>>>(hw16, p_r2, b_c2, nullptr);

    // --- fusion head ---
    k_fusion<<<(NGENE * 32 + 255) / 256, 256>>>(p_r2, istj, W_f, b_f, out);

    (void)n_in; (void)out_size;
}

// round 10
// speedup vs baseline: 5.5999x; 1.0925x over previous
#include <cuda_runtime.h>
#include <cuda_fp16.h>
#include <cstdint>

// ---------------- problem constants ----------------
#define NNODES 50000
#define NGENE  40000
#define NGO    10000
#define NEDGES 800000
#define DIM    512
#define HID2D  256
#define GOIDD  4096
#define MPAD_GO 10112   // 79*128
#define MPAD_N  50048   // 391*128
#define NROWS_BOT 39936 // 312*128 (gene-only rows of layer1)
#define NROWS_TOP 10112 // 79*128  (rows 39936..50047, includes goid rows)
#define NSCANB 196      // ceil(50000/256)

// ---------------- helpers ----------------
__device__ __forceinline__ uint32_t smem_u32(const void* p) {
    uint32_t a;
    asm("{ .reg .u64 t; cvta.to.shared.u64 t, %1; cvt.u32.u64 %0, t; }" : "=r"(a) : "l"(p));
    return a;
}
__device__ __forceinline__ void cp16(uint32_t d, const void* s) {
    asm volatile("cp.async.cg.shared.global [%0], [%1], 16;" :: "r"(d), "l"(s) : "memory");
}
#define CP_COMMIT() asm volatile("cp.async.commit_group;" ::: "memory")
#define CP_WAIT(n)  asm volatile("cp.async.wait_group %0;" :: "n"(n) : "memory")

__device__ __forceinline__ void ldsm4(uint32_t* r, uint32_t addr) {
    asm volatile("ldmatrix.sync.aligned.m8n8.x4.shared.b16 {%0,%1,%2,%3}, [%4];"
        : "=r"(r[0]), "=r"(r[1]), "=r"(r[2]), "=r"(r[3]) : "r"(addr));
}
__device__ __forceinline__ void mma16816(float* d, const uint32_t* a, const uint32_t* b) {
    asm volatile(
        "mma.sync.aligned.m16n8k16.row.col.f32.f16.f16.f32 "
        "{%0,%1,%2,%3}, {%4,%5,%6,%7}, {%8,%9}, {%0,%1,%2,%3};"
        : "+f"(d[0]), "+f"(d[1]), "+f"(d[2]), "+f"(d[3])
        : "r"(a[0]), "r"(a[1]), "r"(a[2]), "r"(a[3]), "r"(b[0]), "r"(b[1]));
}
__device__ __forceinline__ uint32_t swz(uint32_t base, uint32_t off) {
    return base + (off ^ ((off >> 3) & 0x70));
}

// ---------------- scratch (device globals) ----------------
__device__ int   g_is64;
__device__ int   g_src[NEDGES];
__device__ int   g_dst[NEDGES];
__device__ int   g_indeg[NNODES];
__device__ int   g_rowptr[NNODES + 1];
__device__ int   g_cursor[NNODES];
__device__ int   g_bsum[256];
__device__ float g_dinv[NNODES];
__device__ __align__(128) int   g_csr_src[NEDGES];
__device__ __align__(128) float g_csr_w[NEDGES];

__device__ __align__(128) __half g_hw16[(size_t)NNODES * DIM];  // conv messages (fp16)
__device__ __align__(128) float g_r1[(size_t)NNODES * DIM];
__device__ __align__(128) float g_r2[(size_t)NNODES * HID2D];

// fp16 activations (rows padded to 128 multiples)
__device__ __align__(128) __half g_xgo[(size_t)MPAD_GO * GOIDD];
__device__ __align__(128) __half g_go1[(size_t)MPAD_GO * 1024];
__device__ __align__(128) __half g_xt [(size_t)MPAD_N * DIM];
__device__ __align__(128) __half g_h1 [(size_t)MPAD_N * DIM];

// fp16 transposed weights ([N,K] K-major)
__device__ __align__(128) __half g_Wgo1T[1024 * 4096];
__device__ __align__(128) __half g_Wgo2T[512 * 1024];
__device__ __align__(128) __half g_W1T[1024 * 512];   // [Wc1T ; Wr1T]
__device__ __align__(128) __half g_W2T[512 * 512];    // [Wc2T ; Wr2T]

// ---------------- graph preprocessing ----------------
__global__ void k_init_indeg() {
    int i = blockIdx.x * blockDim.x + threadIdx.x;
    if (i < NNODES) g_indeg[i] = 0;
}
__global__ void k_detect_idx_dtype(const int* __restrict__ raw) {
    __shared__ int flag;
    if (threadIdx.x == 0) flag = 1;
    __syncthreads();
    if (raw[2 * threadIdx.x + 1] != 0) flag = 0;
    __syncthreads();
    if (threadIdx.x == 0) g_is64 = flag;
}
__global__ void k_convert_edges(const int* __restrict__ raw) {
    int e = blockIdx.x * blockDim.x + threadIdx.x;
    if (e >= NEDGES) return;
    int s, d;
    if (g_is64) {
        const long long* r64 = (const long long*)raw;
        s = (int)r64[e]; d = (int)r64[NEDGES + e];
    } else {
        s = raw[e]; d = raw[NEDGES + e];
    }
    g_src[e] = s; g_dst[e] = d;
    atomicAdd(&g_indeg[d], 1);
}
__global__ void k_dinv() {
    int i = blockIdx.x * blockDim.x + threadIdx.x;
    if (i < NNODES) g_dinv[i] = rsqrtf(1.0f + (float)g_indeg[i]);
}
// 3-phase parallel exclusive scan of indeg -> rowptr (+cursor)
__global__ void k_scan1() {
    __shared__ int sh[256];
    const int b = blockIdx.x, t = threadIdx.x;
    const int i = b * 256 + t;
    int v = (i < NNODES) ? g_indeg[i] : 0;
    sh[t] = v;
    __syncthreads();
#pragma unroll
    for (int off = 1; off < 256; off <<= 1) {
        int x = (t >= off) ? sh[t - off] : 0;
        __syncthreads();
        sh[t] += x;
        __syncthreads();
    }
    if (i < NNODES) g_rowptr[i] = sh[t] - v;
    if (t == 255) g_bsum[b] = sh[255];
}
__global__ void k_scan2() {
    __shared__ int sh[256];
    const int t = threadIdx.x;
    int v = (t < NSCANB) ? g_bsum[t] : 0;
    sh[t] = v;
    __syncthreads();
#pragma unroll
    for (int off = 1; off < 256; off <<= 1) {
        int x = (t >= off) ? sh[t - off] : 0;
        __syncthreads();
        sh[t] += x;
        __syncthreads();
    }
    if (t < NSCANB) g_bsum[t] = sh[t] - v;
    if (t == 255) g_rowptr[NNODES] = sh[255];
}
__global__ void k_scan3() {
    const int b = blockIdx.x, t = threadIdx.x;
    const int i = b * 256 + t;
    if (i < NNODES) {
        int r = g_rowptr[i] + g_bsum[b];
        g_rowptr[i] = r;
        g_cursor[i] = r;
    }
}
__global__ void k_fill_csr() {
    int e = blockIdx.x * blockDim.x + threadIdx.x;
    if (e >= NEDGES) return;
    int s = g_src[e], d = g_dst[e];
    int p = atomicAdd(&g_cursor[d], 1);
    g_csr_src[p] = s;
    g_csr_w[p]   = g_dinv[s] * g_dinv[d];
}

// ---------------- conversion kernels ----------------
__global__ void k_cvt_xgo(const float* __restrict__ x) {
    size_t i = (size_t)blockIdx.x * blockDim.x + threadIdx.x;  // half2 unit
    const size_t total = (size_t)MPAD_GO * GOIDD / 2;
    if (i >= total) return;
    size_t row = i / (GOIDD / 2), c2 = i % (GOIDD / 2);
    float2 v = make_float2(0.f, 0.f);
    if (row < NGO) v = ((const float2*)x)[((size_t)(NGENE + row) * GOIDD) / 2 + c2];
    ((__half2*)g_xgo)[i] = __floats2half2_rn(v.x, v.y);
}
__global__ void k_cvt_gene(const float* __restrict__ x) {
    size_t i = (size_t)blockIdx.x * blockDim.x + threadIdx.x;  // half2 unit
    const size_t total = (size_t)NGENE * DIM / 2;
    if (i >= total) return;
    size_t row = i / (DIM / 2), c2 = i % (DIM / 2);
    float2 v = ((const float2*)x)[((size_t)row * GOIDD) / 2 + c2];
    ((__half2*)g_xt)[(size_t)row * (DIM / 2) + c2] = __floats2half2_rn(v.x, v.y);
}
__global__ void k_cvt_wT(const float* __restrict__ W, __half* __restrict__ dh,
                         int K, int N) {
    __shared__ float tile[32][33];
    const int nb = blockIdx.x * 32, kb = blockIdx.y * 32;
    const int tx = threadIdx.x, ty = threadIdx.y;
#pragma unroll
    for (int r = 0; r < 32; r += 8)
        tile[ty + r][tx] = W[(size_t)(kb + ty + r) * N + nb + tx];
    __syncthreads();
#pragma unroll
    for (int r = 0; r < 32; r += 8) {
        float v = tile[tx][ty + r];
        dh[(size_t)(nb + ty + r) * K + kb + tx] = __float2half_rn(v);
    }
}
__global__ void k_zero16(__half* p, int n2) {
    int i = blockIdx.x * blockDim.x + threadIdx.x;
    if (i < n2) ((uint32_t*)p)[i] = 0u;
}

// ---------------- fp16 HMMA GEMM (single weight product) ----------------
// C[M,N] = A[M,K](fp16) @ B^T (fp16 weights, stored [N,K] K-major).
// CTA tile 128x128, 3-stage cp.async pipeline, 2 CTAs/SM.
// DUAL: cols [0,N/2) -> Ch fp16 (no bias); cols [N/2,N) -> Cr fp32 (+bias).
#define GEMM_SMEM (3 * 2 * 16384)   // 96 KB

template <bool DUAL, bool BIAS, bool RELU>
__global__ __launch_bounds__(256, 2)
void k_hgemm(const __half* __restrict__ A, const __half* __restrict__ B,
             const float* __restrict__ bias,
             __half* __restrict__ Ch, float* __restrict__ Cr,
             int M, int N, int K)
{
    extern __shared__ char smem[];
    const uint32_t sb = smem_u32(smem);
    const int tid  = threadIdx.x;
    const int wid  = tid >> 5;
    const int lane = tid & 31;
    const int wm   = wid >> 1;
    const int wn   = wid & 1;
    const int bm = blockIdx.y * 128, bn = blockIdx.x * 128;

    const uint32_t STAGE = 2 * 16384;

    const int lrow  = tid >> 1;
    const int lhalf = (tid & 1) * 64;
    const char* srcA = (const char*)(A + (size_t)(bm + lrow) * K) + lhalf;
    const char* srcB = (const char*)(B + (size_t)(bn + lrow) * K) + lhalf;

    const int NC = K / 64;

    auto load_chunk = [&](int s, int c) {
        const uint32_t kb = (uint32_t)c * 128;
        const uint32_t stg = sb + (uint32_t)s * STAGE;
        const uint32_t lbase = (uint32_t)lrow * 128 + (uint32_t)lhalf;
#pragma unroll
        for (int i = 0; i < 4; i++) {
            uint32_t off = lbase + i * 16;
            cp16(swz(stg, off),         srcA + kb + i * 16);
            cp16(swz(stg + 16384, off), srcB + kb + i * 16);
        }
        CP_COMMIT();
    };

    float acc[64];
#pragma unroll
    for (int i = 0; i < 64; i++) acc[i] = 0.f;

    const uint32_t a_row  = (uint32_t)(wm * 32) + (lane & 15);
    const uint32_t a_ksel = (lane >> 4) << 4;
    const uint32_t b_row  = (uint32_t)(wn * 64) + (lane & 7) + ((lane >> 4) << 3);
    const uint32_t b_ksel = (lane & 8) ? 16u : 0u;

    load_chunk(0, 0);
    if (NC > 1) load_chunk(1, 1);

    for (int c = 0; c < NC; c++) {
        if (c + 2 < NC) load_chunk((c + 2) % 3, c + 2);
        if (c + 2 < NC)      { CP_WAIT(2); }
        else if (c + 1 < NC) { CP_WAIT(1); }
        else                 { CP_WAIT(0); }
        __syncthreads();

        const uint32_t stg = sb + (uint32_t)(c % 3) * STAGE;
        const uint32_t tA = stg;
        const uint32_t tB = stg + 16384;

#pragma unroll
        for (int ks = 0; ks < 4; ks++) {
            const uint32_t kb = (uint32_t)ks * 32;
            uint32_t a[8];
            ldsm4(&a[0], swz(tA, (a_row)      * 128 + kb + a_ksel));
            ldsm4(&a[4], swz(tA, (a_row + 16) * 128 + kb + a_ksel));
#pragma unroll
            for (int p = 0; p < 4; p++) {
                uint32_t b4[4];
                ldsm4(b4, swz(tB, (b_row + p * 16) * 128 + kb + b_ksel));
#pragma unroll
                for (int mt = 0; mt < 2; mt++) {
                    mma16816(&acc[(mt * 8 + 2 * p) * 4],     &a[mt * 4], &b4[0]);
                    mma16816(&acc[(mt * 8 + 2 * p + 1) * 4], &a[mt * 4], &b4[2]);
                }
            }
        }
        __syncthreads();
    }

    // ---- epilogue ----
    const int half  = N >> 1;
    const bool sec  = DUAL && (bn >= half);
    const int cbase = sec ? half : 0;
    const int cstr  = DUAL ? half : N;

#pragma unroll
    for (int mt = 0; mt < 2; mt++) {
#pragma unroll
        for (int nt = 0; nt < 8; nt++) {
            const float* d = &acc[(mt * 8 + nt) * 4];
            const int r0 = bm + wm * 32 + mt * 16 + (lane >> 2);
            const int r1 = r0 + 8;
            const int col = bn + wn * 64 + nt * 8 + 2 * (lane & 3);
            float2 v0 = make_float2(d[0], d[1]);
            float2 v1 = make_float2(d[2], d[3]);
            if (DUAL) {
                const int cc = col - cbase;
                if (sec) {
                    if (BIAS) {
                        float b0 = bias[cc], b1 = bias[cc + 1];
                        v0.x += b0; v0.y += b1; v1.x += b0; v1.y += b1;
                    }
                    if (r0 < M) *(float2*)(Cr + (size_t)r0 * cstr + cc) = v0;
                    if (r1 < M) *(float2*)(Cr + (size_t)r1 * cstr + cc) = v1;
                } else {
                    if (r0 < M) *(__half2*)(Ch + (size_t)r0 * cstr + cc) = __floats2half2_rn(v0.x, v0.y);
                    if (r1 < M) *(__half2*)(Ch + (size_t)r1 * cstr + cc) = __floats2half2_rn(v1.x, v1.y);
                }
            } else {
                if (BIAS) {
                    float b0 = bias[col], b1 = bias[col + 1];
                    v0.x += b0; v0.y += b1; v1.x += b0; v1.y += b1;
                }
                if (RELU) {
                    v0.x = fmaxf(v0.x, 0.f); v0.y = fmaxf(v0.y, 0.f);
                    v1.x = fmaxf(v1.x, 0.f); v1.y = fmaxf(v1.y, 0.f);
                }
                if (r0 < M) *(__half2*)(Ch + (size_t)r0 * N + col) = __floats2half2_rn(v0.x, v0.y);
                if (r1 < M) *(__half2*)(Ch + (size_t)r1 * N + col) = __floats2half2_rn(v1.x, v1.y);
            }
        }
    }
}

// ---------------- GCN aggregate + epilogue (CSR gather, fp16 messages) --------
template <int F, bool H16OUT>
__global__ void k_gather_epi(const __half* __restrict__ hw, float* __restrict__ rio,
                             const float* __restrict__ bias, __half* __restrict__ oh)
{
    int i = blockIdx.x;
    int t = threadIdx.x;        // blockDim == F/4
    int beg = g_rowptr[i], end = g_rowptr[i + 1];
    float4 acc = make_float4(0.f, 0.f, 0.f, 0.f);
    if (beg < end) {
        int s = g_csr_src[beg];
        float w = g_csr_w[beg];
        for (int e = beg; e < end; e++) {
            int s2 = 0; float w2 = 0.f;
            if (e + 1 < end) { s2 = g_csr_src[e + 1]; w2 = g_csr_w[e + 1]; }
            uint2 raw = *(const uint2*)(hw + (size_t)s * F + 4 * t);
            float2 f0 = __half22float2(*(const __half2*)&raw.x);
            float2 f1 = __half22float2(*(const __half2*)&raw.y);
            acc.x += w * f0.x; acc.y += w * f0.y;
            acc.z += w * f1.x; acc.w += w * f1.y;
            s = s2; w = w2;
        }
    }
    float dv = g_dinv[i];
    float sn = dv * dv;
    uint2 rawS = *(const uint2*)(hw + (size_t)i * F + 4 * t);
    float2 s0 = __half22float2(*(const __half2*)&rawS.x);
    float2 s1 = __half22float2(*(const __half2*)&rawS.y);
    float4 bb = ((const float4*)bias)[t];
    float4 r  = ((const float4*)rio)[(size_t)i * (F / 4) + t];
    float4 o;
    o.x = fmaxf(acc.x + sn * s0.x + bb.x, 0.f) + r.x;
    o.y = fmaxf(acc.y + sn * s0.y + bb.y, 0.f) + r.y;
    o.z = fmaxf(acc.z + sn * s1.x + bb.z, 0.f) + r.z;
    o.w = fmaxf(acc.w + sn * s1.y + bb.w, 0.f) + r.w;
    if (H16OUT) {
        __half2* ph = (__half2*)(oh + (size_t)i * F + t * 4);
        ph[0] = __floats2half2_rn(o.x, o.y);
        ph[1] = __floats2half2_rn(o.z, o.w);
    } else {
        ((float4*)rio)[(size_t)i * (F / 4) + t] = o;
    }
}

// ---------------- final fusion ----------------
__global__ void k_fusion(const float* __restrict__ h2, const float* __restrict__ istj,
                         const float* __restrict__ Wf, const float* __restrict__ bf,
                         float* __restrict__ out)
{
    int gwarp = (blockIdx.x * blockDim.x + threadIdx.x) >> 5;
    int lane = threadIdx.x & 31;
    if (gwarp >= NGENE) return;
    const float* h = h2 + (size_t)gwarp * HID2D;
    float a0 = 0.f, a1 = 0.f;
#pragma unroll
    for (int k = lane; k < HID2D; k += 32) {
        float v = h[k];
        a0 += v * Wf[2 * k];
        a1 += v * Wf[2 * k + 1];
    }
#pragma unroll
    for (int off = 16; off > 0; off >>= 1) {
        a0 += __shfl_down_sync(0xffffffffu, a0, off);
        a1 += __shfl_down_sync(0xffffffffu, a1, off);
    }
    if (lane == 0) {
        float t = istj[gwarp];
        out[2 * gwarp + 0] = a0 + t * Wf[2 * HID2D + 0] + bf[0];
        out[2 * gwarp + 1] = a1 + t * Wf[2 * HID2D + 1] + bf[1];
    }
}

// ---------------- host ----------------
template <typename T>
static inline T* sym(const void* s) {
    void* p = nullptr;
    cudaGetSymbolAddress(&p, s);
    return (T*)p;
}

extern "C" void kernel_launch(void* const* d_in, const int* in_sizes, int n_in,
                              void* d_out, int out_size)
{
    const float* x    = (const float*)d_in[0];
    const int*   eraw = (const int*)  d_in[1];
    const float* istj = (const float*)d_in[2];
    const int base = (in_sizes[3] < 1000) ? 4 : 3;
    const float* W_go1 = (const float*)d_in[base + 0];
    const float* b_go1 = (const float*)d_in[base + 1];
    const float* W_go2 = (const float*)d_in[base + 2];
    const float* b_go2 = (const float*)d_in[base + 3];
    const float* W_c1  = (const float*)d_in[base + 4];
    const float* b_c1  = (const float*)d_in[base + 5];
    const float* W_c2  = (const float*)d_in[base + 6];
    const float* b_c2  = (const float*)d_in[base + 7];
    const float* W_r1  = (const float*)d_in[base + 8];
    const float* b_r1  = (const float*)d_in[base + 9];
    const float* W_r2  = (const float*)d_in[base + 10];
    const float* b_r2  = (const float*)d_in[base + 11];
    const float* W_f   = (const float*)d_in[base + 12];
    const float* b_f   = (const float*)d_in[base + 13];
    float* out = (float*)d_out;

    // one-time host resources (created on first call = correctness run,
    // before graph capture; no device memory involved)
    static cudaStream_t sA = nullptr, sB = nullptr;
    static cudaEvent_t eFork = nullptr, eGene = nullptr, eTop = nullptr, eJoin = nullptr;
    if (!sA) {
        cudaStreamCreateWithFlags(&sA, cudaStreamNonBlocking);
        cudaStreamCreateWithFlags(&sB, cudaStreamNonBlocking);
        cudaEventCreateWithFlags(&eFork, cudaEventDisableTiming);
        cudaEventCreateWithFlags(&eGene, cudaEventDisableTiming);
        cudaEventCreateWithFlags(&eTop,  cudaEventDisableTiming);
        cudaEventCreateWithFlags(&eJoin, cudaEventDisableTiming);
        cudaFuncSetAttribute((const void*)k_hgemm<false, true, true >,
                             cudaFuncAttributeMaxDynamicSharedMemorySize, GEMM_SMEM);
        cudaFuncSetAttribute((const void*)k_hgemm<true,  true, false>,
                             cudaFuncAttributeMaxDynamicSharedMemorySize, GEMM_SMEM);
    }

    __half* hw16 = sym<__half>(g_hw16);
    float* p_r1 = sym<float>(g_r1);
    float* p_r2 = sym<float>(g_r2);
    __half* xgo  = sym<__half>(g_xgo);
    __half* go1  = sym<__half>(g_go1);
    __half* xt   = sym<__half>(g_xt);
    __half* h1   = sym<__half>(g_h1);
    __half* wgo1 = sym<__half>(g_Wgo1T);
    __half* wgo2 = sym<__half>(g_Wgo2T);
    __half* w1   = sym<__half>(g_W1T);
    __half* w2   = sym<__half>(g_W2T);

    // ---- fork from the (captured) null stream ----
    cudaEventRecord(eFork, 0);
    cudaStreamWaitEvent(sA, eFork, 0);
    cudaStreamWaitEvent(sB, eFork, 0);

    // ======== stream B: goid MLP chain + layer1-top ========
    {
        dim3 b(32, 8);
        k_cvt_wT<<<dim3(1024 / 32, 4096 / 32), b, 0, sB>>>(W_go1, wgo1, 4096, 1024);
        k_cvt_wT<<<dim3(512 / 32, 1024 / 32),  b, 0, sB>>>(W_go2, wgo2, 1024, 512);
    }
    {
        size_t n2 = (size_t)MPAD_GO * GOIDD / 2;
        k_cvt_xgo<<<(unsigned)((n2 + 255) / 256), 256, 0, sB>>>(x);
    }
    k_zero16<<<(112 * 1024 / 2 + 255) / 256, 256, 0, sB>>>(go1 + (size_t)NGO * 1024, 112 * 1024 / 2);
    {
        dim3 g(1024 / 128, MPAD_GO / 128);
        k_hgemm<false, true, true><<<g, 256, GEMM_SMEM, sB>>>(
            xgo, wgo1, b_go1, go1, nullptr, NGO, 1024, 4096);
    }
    {
        dim3 g(512 / 128, MPAD_GO / 128);
        k_hgemm<false, true, true><<<g, 256, GEMM_SMEM, sB>>>(
            go1, wgo2, b_go2, xt + (size_t)NGENE * DIM, nullptr, NGO, 512, 1024);
    }

    // ======== stream A: graph preproc + gene conversion + layer1-bottom ========
    k_init_indeg<<<(NNODES + 255) / 256, 256, 0, sA>>>();
    k_detect_idx_dtype<<<1, 1024, 0, sA>>>(eraw);
    k_convert_edges<<<(NEDGES + 255) / 256, 256, 0, sA>>>(eraw);
    k_dinv<<<(NNODES + 255) / 256, 256, 0, sA>>>();
    k_scan1<<<NSCANB, 256, 0, sA>>>();
    k_scan2<<<1, 256, 0, sA>>>();
    k_scan3<<<NSCANB, 256, 0, sA>>>();
    k_fill_csr<<<(NEDGES + 255) / 256, 256, 0, sA>>>();
    k_cvt_gene<<<(unsigned)(((size_t)NGENE * DIM / 2 + 255) / 256), 256, 0, sA>>>(x);
    {
        dim3 b(32, 8);
        k_cvt_wT<<<dim3(512 / 32, 512 / 32), b, 0, sA>>>(W_c1, w1,             512, 512);
        k_cvt_wT<<<dim3(512 / 32, 512 / 32), b, 0, sA>>>(W_r1, w1 + 512 * 512, 512, 512);
        k_cvt_wT<<<dim3(256 / 32, 512 / 32), b, 0, sA>>>(W_c2, w2,             512, 256);
        k_cvt_wT<<<dim3(256 / 32, 512 / 32), b, 0, sA>>>(W_r2, w2 + 256 * 512, 512, 256);
    }
    k_zero16<<<(48 * 512 / 2 + 255) / 256, 256, 0, sA>>>(xt + (size_t)NNODES * DIM, 48 * 512 / 2);
    k_zero16<<<(48 * 512 / 2 + 255) / 256, 256, 0, sA>>>(h1 + (size_t)NNODES * DIM, 48 * 512 / 2);
    cudaEventRecord(eGene, sA);   // gene rows of xt + W1 + xt pad ready

    // layer1-bottom: rows [0, 39936) — pure gene data
    {
        dim3 g(1024 / 128, NROWS_BOT / 128);
        k_hgemm<true, true, false><<<g, 256, GEMM_SMEM, sA>>>(
            xt, w1, b_r1, hw16, p_r1, NROWS_BOT, 1024, 512);
    }

    // layer1-top on stream B: rows [39936, 50048) — needs goid2 + eGene
    cudaStreamWaitEvent(sB, eGene, 0);
    {
        dim3 g(1024 / 128, NROWS_TOP / 128);
        k_hgemm<true, true, false><<<g, 256, GEMM_SMEM, sB>>>(
            xt   + (size_t)NROWS_BOT * DIM,
            w1, b_r1,
            hw16 + (size_t)NROWS_BOT * DIM,
            p_r1 + (size_t)NROWS_BOT * DIM,
            NNODES - NROWS_BOT, 1024, 512);
    }
    cudaEventRecord(eTop, sB);

    // ======== stream A continues: gathers + layer2 + fusion ========
    cudaStreamWaitEvent(sA, eTop, 0);
    k_gather_epi<DIM, true><<<NNODES, DIM / 4, 0, sA>>>(hw16, p_r1, b_c1, h1);
    {
        dim3 g(512 / 128, MPAD_N / 128);
        k_hgemm<true, true, false><<<g, 256, GEMM_SMEM, sA>>>(
            h1, w2, b_r2, hw16, p_r2, NNODES, 512, 512);
    }
    k_gather_epi<HID2D, false><<<NNODES, HID2D / 4, 0, sA>>>(hw16, p_r2, b_c2, nullptr);
    k_fusion<<<(NGENE * 32 + 255) / 256, 256, 0, sA>>>(p_r2, istj, W_f, b_f, out);

    // ---- join back to the null stream ----
    cudaEventRecord(eJoin, sA);
    cudaStreamWaitEvent(0, eJoin, 0);

    (void)n_in; (void)out_size;
}

// round 11
// speedup vs baseline: 5.6768x; 1.0137x over previous
#include <cuda_runtime.h>
#include <cuda_fp16.h>
#include <cstdint>

// ---------------- problem constants ----------------
#define NNODES 50000
#define NGENE  40000
#define NGO    10000
#define NEDGES 800000
#define DIM    512
#define HID2D  256
#define GOIDD  4096
#define MPAD_GO 10112   // 79*128
#define MPAD_N  50048   // 391*128
#define NROWS_BOT 39936 // 312*128 (gene-only rows of layer1)
#define NROWS_TOP 10112 // 79*128
#define NSCANB 196      // ceil(50000/256)

// ---------------- helpers ----------------
__device__ __forceinline__ uint32_t smem_u32(const void* p) {
    uint32_t a;
    asm("{ .reg .u64 t; cvta.to.shared.u64 t, %1; cvt.u32.u64 %0, t; }" : "=r"(a) : "l"(p));
    return a;
}
__device__ __forceinline__ void cp16(uint32_t d, const void* s) {
    asm volatile("cp.async.cg.shared.global [%0], [%1], 16;" :: "r"(d), "l"(s) : "memory");
}
#define CP_COMMIT() asm volatile("cp.async.commit_group;" ::: "memory")
#define CP_WAIT(n)  asm volatile("cp.async.wait_group %0;" :: "n"(n) : "memory")

__device__ __forceinline__ void ldsm4(uint32_t* r, uint32_t addr) {
    asm volatile("ldmatrix.sync.aligned.m8n8.x4.shared.b16 {%0,%1,%2,%3}, [%4];"
        : "=r"(r[0]), "=r"(r[1]), "=r"(r[2]), "=r"(r[3]) : "r"(addr));
}
__device__ __forceinline__ void mma16816(float* d, const uint32_t* a, const uint32_t* b) {
    asm volatile(
        "mma.sync.aligned.m16n8k16.row.col.f32.f16.f16.f32 "
        "{%0,%1,%2,%3}, {%4,%5,%6,%7}, {%8,%9}, {%0,%1,%2,%3};"
        : "+f"(d[0]), "+f"(d[1]), "+f"(d[2]), "+f"(d[3])
        : "r"(a[0]), "r"(a[1]), "r"(a[2]), "r"(a[3]), "r"(b[0]), "r"(b[1]));
}
__device__ __forceinline__ uint32_t swz(uint32_t base, uint32_t off) {
    return base + (off ^ ((off >> 3) & 0x70));
}
// accumulate 8 fp16 features (one uint4) scaled by w
__device__ __forceinline__ void acc8(float* a, uint4 r, float w) {
    float2 f;
    f = __half22float2(*(const __half2*)&r.x); a[0] += w * f.x; a[1] += w * f.y;
    f = __half22float2(*(const __half2*)&r.y); a[2] += w * f.x; a[3] += w * f.y;
    f = __half22float2(*(const __half2*)&r.z); a[4] += w * f.x; a[5] += w * f.y;
    f = __half22float2(*(const __half2*)&r.w); a[6] += w * f.x; a[7] += w * f.y;
}
__device__ __forceinline__ void unpack8(float* o, uint4 r) {
    float2 f;
    f = __half22float2(*(const __half2*)&r.x); o[0] = f.x; o[1] = f.y;
    f = __half22float2(*(const __half2*)&r.y); o[2] = f.x; o[3] = f.y;
    f = __half22float2(*(const __half2*)&r.z); o[4] = f.x; o[5] = f.y;
    f = __half22float2(*(const __half2*)&r.w); o[6] = f.x; o[7] = f.y;
}

// ---------------- scratch (device globals) ----------------
__device__ int   g_is64;
__device__ int   g_src[NEDGES];
__device__ int   g_dst[NEDGES];
__device__ int   g_indeg[NNODES];
__device__ int   g_rowptr[NNODES + 1];
__device__ int   g_cursor[NNODES];
__device__ int   g_bsum[256];
__device__ float g_dinv[NNODES];
__device__ __align__(128) int   g_csr_src[NEDGES];
__device__ __align__(128) float g_csr_w[NEDGES];

__device__ __align__(128) __half g_hw16[(size_t)NNODES * DIM];  // conv messages (fp16)
__device__ __align__(128) float g_r1[(size_t)NNODES * DIM];
__device__ __align__(128) float g_r2[(size_t)NNODES * HID2D];

// fp16 activations (rows padded to 128 multiples)
__device__ __align__(128) __half g_xgo[(size_t)MPAD_GO * GOIDD];
__device__ __align__(128) __half g_go1[(size_t)MPAD_GO * 1024];
__device__ __align__(128) __half g_xt [(size_t)MPAD_N * DIM];
__device__ __align__(128) __half g_h1 [(size_t)MPAD_N * DIM];

// fp16 transposed weights ([N,K] K-major)
__device__ __align__(128) __half g_Wgo1T[1024 * 4096];
__device__ __align__(128) __half g_Wgo2T[512 * 1024];
__device__ __align__(128) __half g_W1T[1024 * 512];   // [Wc1T ; Wr1T]
__device__ __align__(128) __half g_W2T[512 * 512];    // [Wc2T ; Wr2T]

// ---------------- graph preprocessing ----------------
__global__ void k_init_indeg() {
    int i = blockIdx.x * blockDim.x + threadIdx.x;
    if (i < NNODES) g_indeg[i] = 0;
}
__global__ void k_detect_idx_dtype(const int* __restrict__ raw) {
    __shared__ int flag;
    if (threadIdx.x == 0) flag = 1;
    __syncthreads();
    if (raw[2 * threadIdx.x + 1] != 0) flag = 0;
    __syncthreads();
    if (threadIdx.x == 0) g_is64 = flag;
}
__global__ void k_convert_edges(const int* __restrict__ raw) {
    int e = blockIdx.x * blockDim.x + threadIdx.x;
    if (e >= NEDGES) return;
    int s, d;
    if (g_is64) {
        const long long* r64 = (const long long*)raw;
        s = (int)r64[e]; d = (int)r64[NEDGES + e];
    } else {
        s = raw[e]; d = raw[NEDGES + e];
    }
    g_src[e] = s; g_dst[e] = d;
    atomicAdd(&g_indeg[d], 1);
}
__global__ void k_dinv() {
    int i = blockIdx.x * blockDim.x + threadIdx.x;
    if (i < NNODES) g_dinv[i] = rsqrtf(1.0f + (float)g_indeg[i]);
}
__global__ void k_scan1() {
    __shared__ int sh[256];
    const int b = blockIdx.x, t = threadIdx.x;
    const int i = b * 256 + t;
    int v = (i < NNODES) ? g_indeg[i] : 0;
    sh[t] = v;
    __syncthreads();
#pragma unroll
    for (int off = 1; off < 256; off <<= 1) {
        int x = (t >= off) ? sh[t - off] : 0;
        __syncthreads();
        sh[t] += x;
        __syncthreads();
    }
    if (i < NNODES) g_rowptr[i] = sh[t] - v;
    if (t == 255) g_bsum[b] = sh[255];
}
__global__ void k_scan2() {
    __shared__ int sh[256];
    const int t = threadIdx.x;
    int v = (t < NSCANB) ? g_bsum[t] : 0;
    sh[t] = v;
    __syncthreads();
#pragma unroll
    for (int off = 1; off < 256; off <<= 1) {
        int x = (t >= off) ? sh[t - off] : 0;
        __syncthreads();
        sh[t] += x;
        __syncthreads();
    }
    if (t < NSCANB) g_bsum[t] = sh[t] - v;
    if (t == 255) g_rowptr[NNODES] = sh[255];
}
__global__ void k_scan3() {
    const int b = blockIdx.x, t = threadIdx.x;
    const int i = b * 256 + t;
    if (i < NNODES) {
        int r = g_rowptr[i] + g_bsum[b];
        g_rowptr[i] = r;
        g_cursor[i] = r;
    }
}
__global__ void k_fill_csr() {
    int e = blockIdx.x * blockDim.x + threadIdx.x;
    if (e >= NEDGES) return;
    int s = g_src[e], d = g_dst[e];
    int p = atomicAdd(&g_cursor[d], 1);
    g_csr_src[p] = s;
    g_csr_w[p]   = g_dinv[s] * g_dinv[d];
}

// ---------------- conversion kernels ----------------
__global__ void k_cvt_xgo(const float* __restrict__ x) {
    size_t i = (size_t)blockIdx.x * blockDim.x + threadIdx.x;  // half2 unit
    const size_t total = (size_t)MPAD_GO * GOIDD / 2;
    if (i >= total) return;
    size_t row = i / (GOIDD / 2), c2 = i % (GOIDD / 2);
    float2 v = make_float2(0.f, 0.f);
    if (row < NGO) v = ((const float2*)x)[((size_t)(NGENE + row) * GOIDD) / 2 + c2];
    ((__half2*)g_xgo)[i] = __floats2half2_rn(v.x, v.y);
}
__global__ void k_cvt_gene(const float* __restrict__ x) {
    size_t i = (size_t)blockIdx.x * blockDim.x + threadIdx.x;  // half2 unit
    const size_t total = (size_t)NGENE * DIM / 2;
    if (i >= total) return;
    size_t row = i / (DIM / 2), c2 = i % (DIM / 2);
    float2 v = ((const float2*)x)[((size_t)row * GOIDD) / 2 + c2];
    ((__half2*)g_xt)[(size_t)row * (DIM / 2) + c2] = __floats2half2_rn(v.x, v.y);
}
__global__ void k_cvt_wT(const float* __restrict__ W, __half* __restrict__ dh,
                         int K, int N) {
    __shared__ float tile[32][33];
    const int nb = blockIdx.x * 32, kb = blockIdx.y * 32;
    const int tx = threadIdx.x, ty = threadIdx.y;
#pragma unroll
    for (int r = 0; r < 32; r += 8)
        tile[ty + r][tx] = W[(size_t)(kb + ty + r) * N + nb + tx];
    __syncthreads();
#pragma unroll
    for (int r = 0; r < 32; r += 8) {
        float v = tile[tx][ty + r];
        dh[(size_t)(nb + ty + r) * K + kb + tx] = __float2half_rn(v);
    }
}
__global__ void k_zero16(__half* p, int n2) {
    int i = blockIdx.x * blockDim.x + threadIdx.x;
    if (i < n2) ((uint32_t*)p)[i] = 0u;
}

// ---------------- fp16 HMMA GEMM (single weight product) ----------------
#define GEMM_SMEM (3 * 2 * 16384)   // 96 KB

template <bool DUAL, bool BIAS, bool RELU>
__global__ __launch_bounds__(256, 2)
void k_hgemm(const __half* __restrict__ A, const __half* __restrict__ B,
             const float* __restrict__ bias,
             __half* __restrict__ Ch, float* __restrict__ Cr,
             int M, int N, int K)
{
    extern __shared__ char smem[];
    const uint32_t sb = smem_u32(smem);
    const int tid  = threadIdx.x;
    const int wid  = tid >> 5;
    const int lane = tid & 31;
    const int wm   = wid >> 1;
    const int wn   = wid & 1;
    const int bm = blockIdx.y * 128, bn = blockIdx.x * 128;

    const uint32_t STAGE = 2 * 16384;

    const int lrow  = tid >> 1;
    const int lhalf = (tid & 1) * 64;
    const char* srcA = (const char*)(A + (size_t)(bm + lrow) * K) + lhalf;
    const char* srcB = (const char*)(B + (size_t)(bn + lrow) * K) + lhalf;

    const int NC = K / 64;

    auto load_chunk = [&](int s, int c) {
        const uint32_t kb = (uint32_t)c * 128;
        const uint32_t stg = sb + (uint32_t)s * STAGE;
        const uint32_t lbase = (uint32_t)lrow * 128 + (uint32_t)lhalf;
#pragma unroll
        for (int i = 0; i < 4; i++) {
            uint32_t off = lbase + i * 16;
            cp16(swz(stg, off),         srcA + kb + i * 16);
            cp16(swz(stg + 16384, off), srcB + kb + i * 16);
        }
        CP_COMMIT();
    };

    float acc[64];
#pragma unroll
    for (int i = 0; i < 64; i++) acc[i] = 0.f;

    const uint32_t a_row  = (uint32_t)(wm * 32) + (lane & 15);
    const uint32_t a_ksel = (lane >> 4) << 4;
    const uint32_t b_row  = (uint32_t)(wn * 64) + (lane & 7) + ((lane >> 4) << 3);
    const uint32_t b_ksel = (lane & 8) ? 16u : 0u;

    load_chunk(0, 0);
    if (NC > 1) load_chunk(1, 1);

    for (int c = 0; c < NC; c++) {
        if (c + 2 < NC) load_chunk((c + 2) % 3, c + 2);
        if (c + 2 < NC)      { CP_WAIT(2); }
        else if (c + 1 < NC) { CP_WAIT(1); }
        else                 { CP_WAIT(0); }
        __syncthreads();

        const uint32_t stg = sb + (uint32_t)(c % 3) * STAGE;
        const uint32_t tA = stg;
        const uint32_t tB = stg + 16384;

#pragma unroll
        for (int ks = 0; ks < 4; ks++) {
            const uint32_t kb = (uint32_t)ks * 32;
            uint32_t a[8];
            ldsm4(&a[0], swz(tA, (a_row)      * 128 + kb + a_ksel));
            ldsm4(&a[4], swz(tA, (a_row + 16) * 128 + kb + a_ksel));
#pragma unroll
            for (int p = 0; p < 4; p++) {
                uint32_t b4[4];
                ldsm4(b4, swz(tB, (b_row + p * 16) * 128 + kb + b_ksel));
#pragma unroll
                for (int mt = 0; mt < 2; mt++) {
                    mma16816(&acc[(mt * 8 + 2 * p) * 4],     &a[mt * 4], &b4[0]);
                    mma16816(&acc[(mt * 8 + 2 * p + 1) * 4], &a[mt * 4], &b4[2]);
                }
            }
        }
        __syncthreads();
    }

    // ---- epilogue ----
    const int half  = N >> 1;
    const bool sec  = DUAL && (bn >= half);
    const int cbase = sec ? half : 0;
    const int cstr  = DUAL ? half : N;

#pragma unroll
    for (int mt = 0; mt < 2; mt++) {
#pragma unroll
        for (int nt = 0; nt < 8; nt++) {
            const float* d = &acc[(mt * 8 + nt) * 4];
            const int r0 = bm + wm * 32 + mt * 16 + (lane >> 2);
            const int r1 = r0 + 8;
            const int col = bn + wn * 64 + nt * 8 + 2 * (lane & 3);
            float2 v0 = make_float2(d[0], d[1]);
            float2 v1 = make_float2(d[2], d[3]);
            if (DUAL) {
                const int cc = col - cbase;
                if (sec) {
                    if (BIAS) {
                        float b0 = bias[cc], b1 = bias[cc + 1];
                        v0.x += b0; v0.y += b1; v1.x += b0; v1.y += b1;
                    }
                    if (r0 < M) *(float2*)(Cr + (size_t)r0 * cstr + cc) = v0;
                    if (r1 < M) *(float2*)(Cr + (size_t)r1 * cstr + cc) = v1;
                } else {
                    if (r0 < M) *(__half2*)(Ch + (size_t)r0 * cstr + cc) = __floats2half2_rn(v0.x, v0.y);
                    if (r1 < M) *(__half2*)(Ch + (size_t)r1 * cstr + cc) = __floats2half2_rn(v1.x, v1.y);
                }
            } else {
                if (BIAS) {
                    float b0 = bias[col], b1 = bias[col + 1];
                    v0.x += b0; v0.y += b1; v1.x += b0; v1.y += b1;
                }
                if (RELU) {
                    v0.x = fmaxf(v0.x, 0.f); v0.y = fmaxf(v0.y, 0.f);
                    v1.x = fmaxf(v1.x, 0.f); v1.y = fmaxf(v1.y, 0.f);
                }
                if (r0 < M) *(__half2*)(Ch + (size_t)r0 * N + col) = __floats2half2_rn(v0.x, v0.y);
                if (r1 < M) *(__half2*)(Ch + (size_t)r1 * N + col) = __floats2half2_rn(v1.x, v1.y);
            }
        }
    }
}

// ---------------- GCN aggregate + epilogue (CSR gather, fp16 messages) --------
// o[i] = relu( sum_e w_e*hw[src_e] + dinv[i]^2*hw[i] + bias ) + r[i]
// blockDim = F/8; each thread handles 8 features (16B). Edge loop unrolled x2.
// H16OUT: write fp16 to oh.
// FUSE (F==256, blockDim 32 = one warp): don't store; compute
// out[i] = [o, istj[i]] @ Wf + bf directly (warp shfl reduce).
template <int F, bool H16OUT, bool FUSE>
__global__ void k_gather_epi(const __half* __restrict__ hw, const float* __restrict__ rin,
                             const float* __restrict__ bias, __half* __restrict__ oh,
                             float* __restrict__ rout,
                             const float* __restrict__ istj, const float* __restrict__ Wf,
                             const float* __restrict__ bf, float* __restrict__ out)
{
    const int F8 = F / 8;
    const int i = blockIdx.x;
    const int t = threadIdx.x;       // blockDim == F8
    const int beg = g_rowptr[i], end = g_rowptr[i + 1];
    const uint4* hw8 = (const uint4*)hw;

    float acc[8];
#pragma unroll
    for (int j = 0; j < 8; j++) acc[j] = 0.f;

    int e = beg;
    for (; e + 1 < end; e += 2) {
        int   s0 = g_csr_src[e],     s1 = g_csr_src[e + 1];
        float w0 = g_csr_w[e],       w1 = g_csr_w[e + 1];
        uint4 ra = hw8[(size_t)s0 * F8 + t];
        uint4 rb = hw8[(size_t)s1 * F8 + t];
        acc8(acc, ra, w0);
        acc8(acc, rb, w1);
    }
    if (e < end) {
        int s0 = g_csr_src[e];
        float w0 = g_csr_w[e];
        acc8(acc, hw8[(size_t)s0 * F8 + t], w0);
    }

    const float dv = g_dinv[i];
    const float sn = dv * dv;
    float sv[8];
    unpack8(sv, hw8[(size_t)i * F8 + t]);
    float bb[8], rr[8];
    *(float4*)&bb[0] = ((const float4*)bias)[2 * t];
    *(float4*)&bb[4] = ((const float4*)bias)[2 * t + 1];
    *(float4*)&rr[0] = ((const float4*)(rin + (size_t)i * F))[2 * t];
    *(float4*)&rr[4] = ((const float4*)(rin + (size_t)i * F))[2 * t + 1];

    float o[8];
#pragma unroll
    for (int j = 0; j < 8; j++)
        o[j] = fmaxf(acc[j] + sn * sv[j] + bb[j], 0.f) + rr[j];

    if (H16OUT) {
        uint4 pk;
        *(__half2*)&pk.x = __floats2half2_rn(o[0], o[1]);
        *(__half2*)&pk.y = __floats2half2_rn(o[2], o[3]);
        *(__half2*)&pk.z = __floats2half2_rn(o[4], o[5]);
        *(__half2*)&pk.w = __floats2half2_rn(o[6], o[7]);
        ((uint4*)(oh + (size_t)i * F))[t] = pk;
    } else if (FUSE) {
        // blockDim == 32 (one warp). out[i] = o . Wf[:,0/1] + istj*Wf[F] + bf
        float a0 = 0.f, a1 = 0.f;
#pragma unroll
        for (int j = 0; j < 8; j++) {
            int k = 8 * t + j;
            a0 += o[j] * Wf[2 * k];
            a1 += o[j] * Wf[2 * k + 1];
        }
#pragma unroll
        for (int off = 16; off > 0; off >>= 1) {
            a0 += __shfl_down_sync(0xffffffffu, a0, off);
            a1 += __shfl_down_sync(0xffffffffu, a1, off);
        }
        if (t == 0) {
            float tv = istj[i];
            out[2 * i + 0] = a0 + tv * Wf[2 * F + 0] + bf[0];
            out[2 * i + 1] = a1 + tv * Wf[2 * F + 1] + bf[1];
        }
    } else {
        ((float4*)(rout + (size_t)i * F))[2 * t]     = *(float4*)&o[0];
        ((float4*)(rout + (size_t)i * F))[2 * t + 1] = *(float4*)&o[4];
    }
}

// ---------------- host ----------------
template <typename T>
static inline T* sym(const void* s) {
    void* p = nullptr;
    cudaGetSymbolAddress(&p, s);
    return (T*)p;
}

extern "C" void kernel_launch(void* const* d_in, const int* in_sizes, int n_in,
                              void* d_out, int out_size)
{
    const float* x    = (const float*)d_in[0];
    const int*   eraw = (const int*)  d_in[1];
    const float* istj = (const float*)d_in[2];
    const int base = (in_sizes[3] < 1000) ? 4 : 3;
    const float* W_go1 = (const float*)d_in[base + 0];
    const float* b_go1 = (const float*)d_in[base + 1];
    const float* W_go2 = (const float*)d_in[base + 2];
    const float* b_go2 = (const float*)d_in[base + 3];
    const float* W_c1  = (const float*)d_in[base + 4];
    const float* b_c1  = (const float*)d_in[base + 5];
    const float* W_c2  = (const float*)d_in[base + 6];
    const float* b_c2  = (const float*)d_in[base + 7];
    const float* W_r1  = (const float*)d_in[base + 8];
    const float* b_r1  = (const float*)d_in[base + 9];
    const float* W_r2  = (const float*)d_in[base + 10];
    const float* b_r2  = (const float*)d_in[base + 11];
    const float* W_f   = (const float*)d_in[base + 12];
    const float* b_f   = (const float*)d_in[base + 13];
    float* out = (float*)d_out;

    static cudaStream_t sA = nullptr, sB = nullptr;
    static cudaEvent_t eFork = nullptr, eGene = nullptr, eTop = nullptr, eJoin = nullptr;
    if (!sA) {
        cudaStreamCreateWithFlags(&sA, cudaStreamNonBlocking);
        cudaStreamCreateWithFlags(&sB, cudaStreamNonBlocking);
        cudaEventCreateWithFlags(&eFork, cudaEventDisableTiming);
        cudaEventCreateWithFlags(&eGene, cudaEventDisableTiming);
        cudaEventCreateWithFlags(&eTop,  cudaEventDisableTiming);
        cudaEventCreateWithFlags(&eJoin, cudaEventDisableTiming);
        cudaFuncSetAttribute((const void*)k_hgemm<false, true, true >,
                             cudaFuncAttributeMaxDynamicSharedMemorySize, GEMM_SMEM);
        cudaFuncSetAttribute((const void*)k_hgemm<true,  true, false>,
                             cudaFuncAttributeMaxDynamicSharedMemorySize, GEMM_SMEM);
    }

    __half* hw16 = sym<__half>(g_hw16);
    float* p_r1 = sym<float>(g_r1);
    float* p_r2 = sym<float>(g_r2);
    __half* xgo  = sym<__half>(g_xgo);
    __half* go1  = sym<__half>(g_go1);
    __half* xt   = sym<__half>(g_xt);
    __half* h1   = sym<__half>(g_h1);
    __half* wgo1 = sym<__half>(g_Wgo1T);
    __half* wgo2 = sym<__half>(g_Wgo2T);
    __half* w1   = sym<__half>(g_W1T);
    __half* w2   = sym<__half>(g_W2T);

    // ---- fork from the (captured) null stream ----
    cudaEventRecord(eFork, 0);
    cudaStreamWaitEvent(sA, eFork, 0);
    cudaStreamWaitEvent(sB, eFork, 0);

    // ======== stream B: goid MLP chain + layer1-top ========
    {
        dim3 b(32, 8);
        k_cvt_wT<<<dim3(1024 / 32, 4096 / 32), b, 0, sB>>>(W_go1, wgo1, 4096, 1024);
        k_cvt_wT<<<dim3(512 / 32, 1024 / 32),  b, 0, sB>>>(W_go2, wgo2, 1024, 512);
    }
    {
        size_t n2 = (size_t)MPAD_GO * GOIDD / 2;
        k_cvt_xgo<<<(unsigned)((n2 + 255) / 256), 256, 0, sB>>>(x);
    }
    k_zero16<<<(112 * 1024 / 2 + 255) / 256, 256, 0, sB>>>(go1 + (size_t)NGO * 1024, 112 * 1024 / 2);
    {
        dim3 g(1024 / 128, MPAD_GO / 128);
        k_hgemm<false, true, true><<<g, 256, GEMM_SMEM, sB>>>(
            xgo, wgo1, b_go1, go1, nullptr, NGO, 1024, 4096);
    }
    {
        dim3 g(512 / 128, MPAD_GO / 128);
        k_hgemm<false, true, true><<<g, 256, GEMM_SMEM, sB>>>(
            go1, wgo2, b_go2, xt + (size_t)NGENE * DIM, nullptr, NGO, 512, 1024);
    }

    // ======== stream A: graph preproc + gene conversion + layer1-bottom ========
    k_init_indeg<<<(NNODES + 255) / 256, 256, 0, sA>>>();
    k_detect_idx_dtype<<<1, 1024, 0, sA>>>(eraw);
    k_convert_edges<<<(NEDGES + 255) / 256, 256, 0, sA>>>(eraw);
    k_dinv<<<(NNODES + 255) / 256, 256, 0, sA>>>();
    k_scan1<<<NSCANB, 256, 0, sA>>>();
    k_scan2<<<1, 256, 0, sA>>>();
    k_scan3<<<NSCANB, 256, 0, sA>>>();
    k_fill_csr<<<(NEDGES + 255) / 256, 256, 0, sA>>>();
    k_cvt_gene<<<(unsigned)(((size_t)NGENE * DIM / 2 + 255) / 256), 256, 0, sA>>>(x);
    {
        dim3 b(32, 8);
        k_cvt_wT<<<dim3(512 / 32, 512 / 32), b, 0, sA>>>(W_c1, w1,             512, 512);
        k_cvt_wT<<<dim3(512 / 32, 512 / 32), b, 0, sA>>>(W_r1, w1 + 512 * 512, 512, 512);
        k_cvt_wT<<<dim3(256 / 32, 512 / 32), b, 0, sA>>>(W_c2, w2,             512, 256);
        k_cvt_wT<<<dim3(256 / 32, 512 / 32), b, 0, sA>>>(W_r2, w2 + 256 * 512, 512, 256);
    }
    k_zero16<<<(48 * 512 / 2 + 255) / 256, 256, 0, sA>>>(xt + (size_t)NNODES * DIM, 48 * 512 / 2);
    k_zero16<<<(48 * 512 / 2 + 255) / 256, 256, 0, sA>>>(h1 + (size_t)NNODES * DIM, 48 * 512 / 2);
    cudaEventRecord(eGene, sA);

    // layer1-bottom: rows [0, 39936) — pure gene data
    {
        dim3 g(1024 / 128, NROWS_BOT / 128);
        k_hgemm<true, true, false><<<g, 256, GEMM_SMEM, sA>>>(
            xt, w1, b_r1, hw16, p_r1, NROWS_BOT, 1024, 512);
    }

    // layer1-top on stream B: rows [39936, 50048)
    cudaStreamWaitEvent(sB, eGene, 0);
    {
        dim3 g(1024 / 128, NROWS_TOP / 128);
        k_hgemm<true, true, false><<<g, 256, GEMM_SMEM, sB>>>(
            xt   + (size_t)NROWS_BOT * DIM,
            w1, b_r1,
            hw16 + (size_t)NROWS_BOT * DIM,
            p_r1 + (size_t)NROWS_BOT * DIM,
            NNODES - NROWS_BOT, 1024, 512);
    }
    cudaEventRecord(eTop, sB);

    // ======== stream A continues: gathers + layer2 + fused fusion ========
    cudaStreamWaitEvent(sA, eTop, 0);
    k_gather_epi<DIM, true, false><<<NNODES, DIM / 8, 0, sA>>>(
        hw16, p_r1, b_c1, h1, nullptr, nullptr, nullptr, nullptr, nullptr);
    {
        dim3 g(512 / 128, MPAD_N / 128);
        k_hgemm<true, true, false><<<g, 256, GEMM_SMEM, sA>>>(
            h1, w2, b_r2, hw16, p_r2, NNODES, 512, 512);
    }
    // gather2 fused with fusion head, gene nodes only
    k_gather_epi<HID2D, false, true><<<NGENE, HID2D / 8, 0, sA>>>(
        hw16, p_r2, b_c2, nullptr, nullptr, istj, W_f, b_f, out);

    // ---- join back to the null stream ----
    cudaEventRecord(eJoin, sA);
    cudaStreamWaitEvent(0, eJoin, 0);

    (void)n_in; (void)out_size;
}